// round 1
// baseline (speedup 1.0000x reference)
#include <cuda_runtime.h>

// Problem constants (fixed shapes from the reference)
#define NB_B 8
#define NB_L 160
#define NB_H 512
#define NB_C 8
#define NB_S 64
#define NB_R 8
#define NB_BL (NB_B*NB_L)   // 1280

// ---------------- scratch (device globals: no runtime allocation) -------------
__device__ float g_vv [NB_BL*NB_H];
__device__ float g_tmp[NB_BL*NB_H];
__device__ float g_x0 [NB_BL*NB_H];
__device__ float g_x1 [NB_BL*NB_H];
__device__ float g_y0 [NB_B*NB_C*NB_S*NB_R*NB_L];  // layout [b][c][s][r][l]
__device__ float g_y1 [NB_B*NB_C*NB_S*NB_R*NB_L];
__device__ float g_sc [NB_B*NB_L*NB_L];
__device__ float g_scr[NB_B*NB_L*NB_H];

// ------------------------------------------------------------------------------
// C[m,n] = sum_k A[m,k]*W[n,k] + bias[n].  M=1280, N=512, K=512.
// Tiles: 64x64, BK=16, 256 threads, 4x4 per thread.
__global__ void __launch_bounds__(256) gemm_nt_kernel(
    const float* __restrict__ A, const float* __restrict__ W,
    const float* __restrict__ bias, float* __restrict__ C)
{
    __shared__ float As[16][68];
    __shared__ float Ws[16][68];
    const int tid = threadIdx.x;
    const int m0 = blockIdx.x * 64;
    const int n0 = blockIdx.y * 64;
    const int lr = tid >> 2;            // 0..63
    const int lc = (tid & 3) << 2;      // 0,4,8,12
    const float* Ap = A + (m0 + lr) * 512 + lc;
    const float* Wp = W + (n0 + lr) * 512 + lc;
    const int tm = (tid & 15) << 2;
    const int tn = (tid >> 4) << 2;
    float acc[4][4] = {};
    for (int k0 = 0; k0 < 512; k0 += 16) {
        float4 av = *(const float4*)(Ap + k0);
        float4 wv = *(const float4*)(Wp + k0);
        __syncthreads();
        As[lc+0][lr]=av.x; As[lc+1][lr]=av.y; As[lc+2][lr]=av.z; As[lc+3][lr]=av.w;
        Ws[lc+0][lr]=wv.x; Ws[lc+1][lr]=wv.y; Ws[lc+2][lr]=wv.z; Ws[lc+3][lr]=wv.w;
        __syncthreads();
        #pragma unroll
        for (int kk = 0; kk < 16; kk++) {
            float a[4], w[4];
            *(float4*)a = *(const float4*)&As[kk][tm];
            *(float4*)w = *(const float4*)&Ws[kk][tn];
            #pragma unroll
            for (int i = 0; i < 4; i++)
                #pragma unroll
                for (int j = 0; j < 4; j++)
                    acc[i][j] = fmaf(a[i], w[j], acc[i][j]);
        }
    }
    #pragma unroll
    for (int i = 0; i < 4; i++) {
        float4 o;
        o.x = acc[i][0] + bias[n0+tn+0];
        o.y = acc[i][1] + bias[n0+tn+1];
        o.z = acc[i][2] + bias[n0+tn+2];
        o.w = acc[i][3] + bias[n0+tn+3];
        *(float4*)&C[(m0+tm+i)*512 + n0 + tn] = o;
    }
}

// ------------------------------------------------------------------------------
// Merge projection + transpose:
//   y[b,l,c,t] = sum_s X[b,l, c*64+s] * WM[c, t, s] + BM[c,t],  t = r*64 + st
// stored as Y[b][c][st][r][l]  (contiguous l for the scores kernel).
// grid (l-tiles=5, r=8, bc=64), 256 threads, tile 64(st) x 32(l), K=64.
__global__ void __launch_bounds__(256) merge_kernel(
    const float* __restrict__ X, const float* __restrict__ WM,
    const float* __restrict__ BM, float* __restrict__ Y)
{
    __shared__ float xs[64][36];   // [k][l]
    __shared__ float ws[64][68];   // [k][st]
    const int tid = threadIdx.x;
    const int l0 = blockIdx.x * 32;
    const int r  = blockIdx.y;
    const int bc = blockIdx.z;
    const int b = bc >> 3, c = bc & 7;
    #pragma unroll
    for (int j = 0; j < 2; j++) {
        int i = tid + j*256;
        int ll = i >> 4, k4 = (i & 15) << 2;
        float4 v = *(const float4*)(X + (b*160 + l0 + ll)*512 + c*64 + k4);
        xs[k4+0][ll]=v.x; xs[k4+1][ll]=v.y; xs[k4+2][ll]=v.z; xs[k4+3][ll]=v.w;
    }
    #pragma unroll
    for (int j = 0; j < 4; j++) {
        int i = tid + j*256;
        int st = i >> 4, k4 = (i & 15) << 2;
        float4 v = *(const float4*)(WM + (c*512 + r*64 + st)*64 + k4);
        ws[k4+0][st]=v.x; ws[k4+1][st]=v.y; ws[k4+2][st]=v.z; ws[k4+3][st]=v.w;
    }
    __syncthreads();
    const int lB = (tid & 7) << 2;   // 4 l's
    const int sB = (tid >> 3) << 1;  // 2 st's
    float acc[2][4] = {};
    #pragma unroll 8
    for (int k = 0; k < 64; k++) {
        float a[4];
        *(float4*)a = *(const float4*)&xs[k][lB];
        float2 wv = *(const float2*)&ws[k][sB];
        #pragma unroll
        for (int j = 0; j < 4; j++) {
            acc[0][j] = fmaf(wv.x, a[j], acc[0][j]);
            acc[1][j] = fmaf(wv.y, a[j], acc[1][j]);
        }
    }
    #pragma unroll
    for (int i = 0; i < 2; i++) {
        int st = sB + i;
        float bb = BM[c*512 + r*64 + st];
        float4 o = { acc[i][0]+bb, acc[i][1]+bb, acc[i][2]+bb, acc[i][3]+bb };
        *(float4*)&Y[((bc*64 + st)*8 + r)*160 + l0 + lB] = o;
    }
}

// ------------------------------------------------------------------------------
// Fused scores: z = sum_r y1*y0, signed sqrt = z*rsqrt(|z|), chunk L2 norm
// via den = sum_s |z|, score = sum_c num_c/max(sqrt(den_c),1e-12) + b_bo.
__device__ __forceinline__ void zpost(float z, float wb, float& num, float& den)
{
    float az = fabsf(z);
    den += az;
    float rv = rsqrtf(fmaxf(az, 1e-35f));
    num = fmaf(wb, z * rv, num);
}

__global__ void __launch_bounds__(256) scores_kernel(
    const float* __restrict__ Y1, const float* __restrict__ Y0,
    const float* __restrict__ wbo, const float* __restrict__ bbo,
    float* __restrict__ SC)
{
    __shared__ float s1[16*8*32];   // [s(16)][r(8)][q(32)]
    __shared__ float s0[16*8*32];   // [s(16)][r(8)][k(32)]
    const int tid = threadIdx.x;
    const int qt = blockIdx.x, kt = blockIdx.y, b = blockIdx.z;
    const int kB = (tid & 15) << 1;
    const int qB = (tid >> 4) << 1;
    float acc[2][2] = {};
    for (int c = 0; c < 8; c++) {
        float num[2][2] = {}, den[2][2] = {};
        for (int sq = 0; sq < 4; sq++) {
            const int base = ((b*8 + c)*512 + sq*128)*160;
            __syncthreads();
            #pragma unroll
            for (int j = 0; j < 4; j++) {
                int i = tid + j*256;
                int sr = i >> 3, c4 = (i & 7) << 2;
                *(float4*)&s1[sr*32 + c4] = *(const float4*)(Y1 + base + sr*160 + qt*32 + c4);
                *(float4*)&s0[sr*32 + c4] = *(const float4*)(Y0 + base + sr*160 + kt*32 + c4);
            }
            __syncthreads();
            #pragma unroll 2
            for (int s = 0; s < 16; s++) {
                float z00=0.f, z01=0.f, z10=0.f, z11=0.f;
                #pragma unroll
                for (int rr = 0; rr < 8; rr++) {
                    float2 u = *(const float2*)&s1[(s*8+rr)*32 + qB];
                    float2 v = *(const float2*)&s0[(s*8+rr)*32 + kB];
                    z00 = fmaf(u.x, v.x, z00);
                    z01 = fmaf(u.x, v.y, z01);
                    z10 = fmaf(u.y, v.x, z10);
                    z11 = fmaf(u.y, v.y, z11);
                }
                float wb = wbo[c*64 + sq*16 + s];
                zpost(z00, wb, num[0][0], den[0][0]);
                zpost(z01, wb, num[0][1], den[0][1]);
                zpost(z10, wb, num[1][0], den[1][0]);
                zpost(z11, wb, num[1][1], den[1][1]);
            }
        }
        #pragma unroll
        for (int i = 0; i < 2; i++)
            #pragma unroll
            for (int j = 0; j < 2; j++)
                acc[i][j] += num[i][j] * rsqrtf(fmaxf(den[i][j], 1e-24f));
    }
    float bb = bbo[0];
    int q = qt*32 + qB, k = kt*32 + kB;
    #pragma unroll
    for (int i = 0; i < 2; i++) {
        float2 o = { acc[i][0] + bb, acc[i][1] + bb };
        *(float2*)&SC[(b*160 + q + i)*160 + k] = o;
    }
}

// ------------------------------------------------------------------------------
// Row softmax over the last axis (160), in place.
__global__ void __launch_bounds__(192) softmax_kernel(float* __restrict__ sc)
{
    const int row = blockIdx.x;
    float* p = sc + row*160;
    const int t = threadIdx.x;
    __shared__ float red[6], red2[6];
    float v = (t < 160) ? p[t] : -3.0e38f;
    #pragma unroll
    for (int o = 16; o; o >>= 1) v = fmaxf(v, __shfl_xor_sync(0xffffffffu, v, o));
    if ((t & 31) == 0) red[t >> 5] = v;
    __syncthreads();
    float m = red[0];
    #pragma unroll
    for (int i = 1; i < 6; i++) m = fmaxf(m, red[i]);
    float e = (t < 160) ? expf(p[t] - m) : 0.f;
    float sv = e;
    #pragma unroll
    for (int o = 16; o; o >>= 1) sv += __shfl_xor_sync(0xffffffffu, sv, o);
    if ((t & 31) == 0) red2[t >> 5] = sv;
    __syncthreads();
    float ssum = 0.f;
    #pragma unroll
    for (int i = 0; i < 6; i++) ssum += red2[i];
    if (t < 160) p[t] = e / ssum;
}

// ------------------------------------------------------------------------------
// atted = att @ vv per batch (M=160,K=160,N=512), fused with the torch-faithful
// transpose(1,2).view(B,-1,H) scramble: scr[b][f/512][f%512], f = h*160 + q.
__global__ void __launch_bounds__(256) attv_kernel(
    const float* __restrict__ att, const float* __restrict__ vv,
    float* __restrict__ scr)
{
    __shared__ float As[16][36];   // [k][m]
    __shared__ float Ws[16][68];   // [k][n]
    const int tid = threadIdx.x;
    const int m0 = blockIdx.x * 32;
    const int n0 = blockIdx.y * 64;
    const int b  = blockIdx.z;
    const float* attb = att + b*160*160;
    const float* vvb  = vv  + b*160*512;
    const int amr = tid >> 3;
    const int akc = (tid & 7) << 1;
    const int wkr = tid >> 4;
    const int wnc = (tid & 15) << 2;
    const int tm = (tid & 15) << 1;
    const int tn = (tid >> 4) << 2;
    float acc[2][4] = {};
    for (int k0 = 0; k0 < 160; k0 += 16) {
        float2 av = *(const float2*)(attb + (m0 + amr)*160 + k0 + akc);
        float4 wv = *(const float4*)(vvb + (k0 + wkr)*512 + n0 + wnc);
        __syncthreads();
        As[akc+0][amr] = av.x; As[akc+1][amr] = av.y;
        *(float4*)&Ws[wkr][wnc] = wv;
        __syncthreads();
        #pragma unroll
        for (int kk = 0; kk < 16; kk++) {
            float a0 = As[kk][tm], a1 = As[kk][tm+1];
            float w[4];
            *(float4*)w = *(const float4*)&Ws[kk][tn];
            #pragma unroll
            for (int j = 0; j < 4; j++) {
                acc[0][j] = fmaf(a0, w[j], acc[0][j]);
                acc[1][j] = fmaf(a1, w[j], acc[1][j]);
            }
        }
    }
    #pragma unroll
    for (int i = 0; i < 2; i++)
        #pragma unroll
        for (int j = 0; j < 4; j++) {
            int q = m0 + tm + i;
            int h = n0 + tn + j;
            scr[b*81920 + h*160 + q] = acc[i][j];
        }
}

// ------------------------------------------------------------------------------
extern "C" void kernel_launch(void* const* d_in, const int* in_sizes, int n_in,
                              void* d_out, int out_size)
{
    (void)in_sizes; (void)n_in; (void)out_size;
    const float* v    = (const float*)d_in[0];
    const float* kin  = (const float*)d_in[1];
    const float* qin  = (const float*)d_in[2];
    const float* w_v  = (const float*)d_in[3];  const float* b_v = (const float*)d_in[4];
    const float* w_k  = (const float*)d_in[5];  const float* b_k = (const float*)d_in[6];
    const float* w_q  = (const float*)d_in[7];  const float* b_q = (const float*)d_in[8];
    const float* w0   = (const float*)d_in[9];  const float* b0  = (const float*)d_in[10];
    const float* w1   = (const float*)d_in[11]; const float* b1  = (const float*)d_in[12];
    const float* wm0  = (const float*)d_in[13]; const float* bm0 = (const float*)d_in[14];
    const float* wm1  = (const float*)d_in[15]; const float* bm1 = (const float*)d_in[16];
    const float* w_bo = (const float*)d_in[17]; const float* b_bo= (const float*)d_in[18];
    const float* w_m  = (const float*)d_in[19]; const float* b_m = (const float*)d_in[20];
    float* out = (float*)d_out;

    float *vv, *tmp, *x0, *x1, *y0, *y1, *sc, *scr;
    cudaGetSymbolAddress((void**)&vv,  g_vv);
    cudaGetSymbolAddress((void**)&tmp, g_tmp);
    cudaGetSymbolAddress((void**)&x0,  g_x0);
    cudaGetSymbolAddress((void**)&x1,  g_x1);
    cudaGetSymbolAddress((void**)&y0,  g_y0);
    cudaGetSymbolAddress((void**)&y1,  g_y1);
    cudaGetSymbolAddress((void**)&sc,  g_sc);
    cudaGetSymbolAddress((void**)&scr, g_scr);

    dim3 gg(20, 8);
    gemm_nt_kernel<<<gg, 256>>>(v,   w_v, b_v, vv);   // vv
    gemm_nt_kernel<<<gg, 256>>>(kin, w_k, b_k, tmp);  // kk
    gemm_nt_kernel<<<gg, 256>>>(tmp, w0,  b0,  x0);   // x0 = kk @ w0^T
    gemm_nt_kernel<<<gg, 256>>>(qin, w_q, b_q, tmp);  // qq
    gemm_nt_kernel<<<gg, 256>>>(tmp, w1,  b1,  x1);   // x1 = qq @ w1^T

    merge_kernel<<<dim3(5, 8, 64), 256>>>(x0, wm0, bm0, y0);
    merge_kernel<<<dim3(5, 8, 64), 256>>>(x1, wm1, bm1, y1);

    scores_kernel<<<dim3(5, 5, 8), 256>>>(y1, y0, w_bo, b_bo, sc);
    softmax_kernel<<<1280, 192>>>(sc);
    attv_kernel<<<dim3(5, 8, 8), 256>>>(sc, vv, scr);
    gemm_nt_kernel<<<gg, 256>>>(scr, w_m, b_m, out);
}

// round 3
// speedup vs baseline: 1.2899x; 1.2899x over previous
#include <cuda_runtime.h>
#include <cuda_bf16.h>
#include <cstdint>

// Problem constants (fixed shapes from the reference)
#define NB_B 8
#define NB_L 160
#define NB_H 512
#define NB_C 8
#define NB_S 64
#define NB_R 8
#define NB_BL (NB_B*NB_L)   // 1280

// ---------------- scratch (device globals: no runtime allocation) -------------
__device__ float g_vv [NB_BL*NB_H];
__device__ float g_kk [NB_BL*NB_H];
__device__ float g_qq [NB_BL*NB_H];
__device__ float g_x0 [NB_BL*NB_H];
__device__ float g_x1 [NB_BL*NB_H];
__device__ float g_y0 [NB_B*NB_C*NB_S*NB_R*NB_L];  // layout [b][c][s][r][l]
__device__ float g_y1 [NB_B*NB_C*NB_S*NB_R*NB_L];
__device__ float g_sc [NB_B*NB_L*NB_L];
__device__ float g_scr[NB_B*NB_L*NB_H];

// ======================= mma.sync helpers (sm_80+ path) =======================
__device__ __forceinline__ uint32_t smem_u32(const void* p) {
    uint32_t a;
    asm("{ .reg .u64 t; cvta.to.shared.u64 t, %1; cvt.u32.u64 %0, t; }"
        : "=r"(a) : "l"(p));
    return a;
}
__device__ __forceinline__ void mma16816(float* d, const uint32_t* a, const uint32_t* b) {
    asm volatile(
        "mma.sync.aligned.m16n8k16.row.col.f32.bf16.bf16.f32 "
        "{%0,%1,%2,%3}, {%4,%5,%6,%7}, {%8,%9}, {%0,%1,%2,%3};"
        : "+f"(d[0]), "+f"(d[1]), "+f"(d[2]), "+f"(d[3])
        : "r"(a[0]), "r"(a[1]), "r"(a[2]), "r"(a[3]), "r"(b[0]), "r"(b[1]));
}
__device__ __forceinline__ void ldsm_x4(uint32_t* r, uint32_t addr) {
    asm volatile("ldmatrix.sync.aligned.m8n8.x4.shared.b16 {%0,%1,%2,%3}, [%4];"
        : "=r"(r[0]), "=r"(r[1]), "=r"(r[2]), "=r"(r[3]) : "r"(addr));
}

// ================= bf16-split tensor-core GEMM: C = A @ W^T + bias ===========
// M=1280, N=512, K=512 per instance; up to 3 instances via blockIdx.z.
// 3-term bf16 split (Ah·Wh + Ah·Wl + Al·Wh) accumulated in fp32 by mma.sync.
// CTA tile 128x64, BK=64, 8 warps (warp tile 32x32).
struct GemmBatch {
    const float* A[3]; const float* W[3]; const float* bias[3]; float* C[3];
};

// SMEM half-element offsets (row stride 72 halves = 144B -> ldmatrix
// chunk bank-group = (9*row + col16) mod 8 : conflict-free)
#define LDA_S 72
#define OFF_AH 0
#define OFF_AL (128*LDA_S)
#define OFF_WH (256*LDA_S)
#define OFF_WL (320*LDA_S)
#define HM_SMEM_BYTES (384*LDA_S*2)   // 55296

__global__ void __launch_bounds__(256) hmma_gemm_kernel(GemmBatch gb)
{
    extern __shared__ __nv_bfloat16 sm[];
    const int tid  = threadIdx.x;
    const int wid  = tid >> 5, lane = tid & 31;
    const int z = blockIdx.z;
    const float* A    = gb.A[z];
    const float* W    = gb.W[z];
    const float* bias = gb.bias[z];
    float*       C    = gb.C[z];
    const int m0 = blockIdx.x * 128;
    const int n0 = blockIdx.y * 64;
    const int wm = wid & 3, wn = wid >> 2;      // warp tile: (wm*32, wn*32)
    const uint32_t sb = smem_u32(sm);

    float acc[2][4][4] = {};

    // per-thread ldmatrix base addresses (byte offsets into smem)
    // A: row = wm*32 + mi*16 + (lane&15), colhalf = (lane>>4)*8 + k16*16
    const int a_row = wm * 32 + (lane & 15);
    const uint32_t a_addr0 = sb + (uint32_t)((OFF_AH + a_row * LDA_S + (lane >> 4) * 8) * 2);
    // B: row = wn*32 + j2*16 + (lane>>4)*8 + (lane&7), colhalf = ((lane>>3)&1)*8 + k16*16
    const int b_row = wn * 32 + ((lane >> 4) & 1) * 8 + (lane & 7);
    const uint32_t b_addr0 = sb + (uint32_t)((OFF_WH + b_row * LDA_S + ((lane >> 3) & 1) * 8) * 2);
    const uint32_t ALO_B = (uint32_t)((OFF_AL - OFF_AH) * 2);
    const uint32_t WLO_B = (uint32_t)((OFF_WL - OFF_WH) * 2);

    for (int kc = 0; kc < 8; kc++) {
        const int kbase = kc * 64;
        __syncthreads();
        // ---- stage A chunk: 128 rows x 64 k (fp32 -> bf16 hi/lo) ----
        #pragma unroll
        for (int it = 0; it < 8; it++) {
            int u = tid + it * 256;
            int row = u >> 4, kg = (u & 15) << 2;
            float4 v = *(const float4*)(A + (m0 + row) * 512 + kbase + kg);
            __nv_bfloat162 h01 = __floats2bfloat162_rn(v.x, v.y);
            __nv_bfloat162 h23 = __floats2bfloat162_rn(v.z, v.w);
            float2 f01 = __bfloat1622float2(h01);
            float2 f23 = __bfloat1622float2(h23);
            __nv_bfloat162 l01 = __floats2bfloat162_rn(v.x - f01.x, v.y - f01.y);
            __nv_bfloat162 l23 = __floats2bfloat162_rn(v.z - f23.x, v.w - f23.y);
            int o = row * LDA_S + kg;
            *(uint2*)&sm[OFF_AH + o] = make_uint2(*(uint32_t*)&h01, *(uint32_t*)&h23);
            *(uint2*)&sm[OFF_AL + o] = make_uint2(*(uint32_t*)&l01, *(uint32_t*)&l23);
        }
        // ---- stage W chunk: 64 rows (n) x 64 k ----
        #pragma unroll
        for (int it = 0; it < 4; it++) {
            int u = tid + it * 256;
            int row = u >> 4, kg = (u & 15) << 2;
            float4 v = *(const float4*)(W + (n0 + row) * 512 + kbase + kg);
            __nv_bfloat162 h01 = __floats2bfloat162_rn(v.x, v.y);
            __nv_bfloat162 h23 = __floats2bfloat162_rn(v.z, v.w);
            float2 f01 = __bfloat1622float2(h01);
            float2 f23 = __bfloat1622float2(h23);
            __nv_bfloat162 l01 = __floats2bfloat162_rn(v.x - f01.x, v.y - f01.y);
            __nv_bfloat162 l23 = __floats2bfloat162_rn(v.z - f23.x, v.w - f23.y);
            int o = row * LDA_S + kg;
            *(uint2*)&sm[OFF_WH + o] = make_uint2(*(uint32_t*)&h01, *(uint32_t*)&h23);
            *(uint2*)&sm[OFF_WL + o] = make_uint2(*(uint32_t*)&l01, *(uint32_t*)&l23);
        }
        __syncthreads();

        #pragma unroll
        for (int k16 = 0; k16 < 4; k16++) {
            const uint32_t kb = (uint32_t)(k16 * 32);  // 16 halves
            uint32_t ah[2][4], al[2][4];
            ldsm_x4(ah[0], a_addr0 + kb);
            ldsm_x4(ah[1], a_addr0 + (uint32_t)(16 * LDA_S * 2) + kb);
            ldsm_x4(al[0], a_addr0 + ALO_B + kb);
            ldsm_x4(al[1], a_addr0 + ALO_B + (uint32_t)(16 * LDA_S * 2) + kb);
            uint32_t bh[2][4], bl[2][4];   // each x4 = 2 n-tiles (regs 0,1 / 2,3)
            ldsm_x4(bh[0], b_addr0 + kb);
            ldsm_x4(bh[1], b_addr0 + (uint32_t)(16 * LDA_S * 2) + kb);
            ldsm_x4(bl[0], b_addr0 + WLO_B + kb);
            ldsm_x4(bl[1], b_addr0 + WLO_B + (uint32_t)(16 * LDA_S * 2) + kb);
            #pragma unroll
            for (int mi = 0; mi < 2; mi++) {
                #pragma unroll
                for (int nj = 0; nj < 4; nj++) {
                    const uint32_t* bph = &bh[nj >> 1][(nj & 1) * 2];
                    const uint32_t* bpl = &bl[nj >> 1][(nj & 1) * 2];
                    mma16816(acc[mi][nj], ah[mi], bph);
                    mma16816(acc[mi][nj], ah[mi], bpl);
                    mma16816(acc[mi][nj], al[mi], bph);
                }
            }
        }
    }

    // ---- epilogue: acc[mi][nj] layout: c[m][n], m = wm*32+mi*16+(lane/4)+(reg>=2)*8,
    //      n = wn*32+nj*8+(lane%4)*2+(reg&1)
    const int mrow = m0 + wm * 32 + (lane >> 2);
    const int ncol = n0 + wn * 32 + (lane & 3) * 2;
    #pragma unroll
    for (int mi = 0; mi < 2; mi++) {
        #pragma unroll
        for (int nj = 0; nj < 4; nj++) {
            int n = ncol + nj * 8;
            float b0 = bias[n], b1 = bias[n + 1];
            int m_a = mrow + mi * 16;
            *(float2*)&C[m_a * 512 + n]       = make_float2(acc[mi][nj][0] + b0, acc[mi][nj][1] + b1);
            *(float2*)&C[(m_a + 8) * 512 + n] = make_float2(acc[mi][nj][2] + b0, acc[mi][nj][3] + b1);
        }
    }
}

// ------------------------------------------------------------------------------
// Merge projection + transpose (unchanged from R1):
//   y[b,l,c,t] = sum_s X[b,l, c*64+s] * WM[c, t, s] + BM[c,t],  t = r*64 + st
// stored as Y[b][c][st][r][l].
__global__ void __launch_bounds__(256) merge_kernel(
    const float* __restrict__ X, const float* __restrict__ WM,
    const float* __restrict__ BM, float* __restrict__ Y)
{
    __shared__ float xs[64][36];
    __shared__ float ws[64][68];
    const int tid = threadIdx.x;
    const int l0 = blockIdx.x * 32;
    const int r  = blockIdx.y;
    const int bc = blockIdx.z;
    const int b = bc >> 3, c = bc & 7;
    #pragma unroll
    for (int j = 0; j < 2; j++) {
        int i = tid + j*256;
        int ll = i >> 4, k4 = (i & 15) << 2;
        float4 v = *(const float4*)(X + (b*160 + l0 + ll)*512 + c*64 + k4);
        xs[k4+0][ll]=v.x; xs[k4+1][ll]=v.y; xs[k4+2][ll]=v.z; xs[k4+3][ll]=v.w;
    }
    #pragma unroll
    for (int j = 0; j < 4; j++) {
        int i = tid + j*256;
        int st = i >> 4, k4 = (i & 15) << 2;
        float4 v = *(const float4*)(WM + (c*512 + r*64 + st)*64 + k4);
        ws[k4+0][st]=v.x; ws[k4+1][st]=v.y; ws[k4+2][st]=v.z; ws[k4+3][st]=v.w;
    }
    __syncthreads();
    const int lB = (tid & 7) << 2;
    const int sB = (tid >> 3) << 1;
    float acc[2][4] = {};
    #pragma unroll 8
    for (int k = 0; k < 64; k++) {
        float a[4];
        *(float4*)a = *(const float4*)&xs[k][lB];
        float2 wv = *(const float2*)&ws[k][sB];
        #pragma unroll
        for (int j = 0; j < 4; j++) {
            acc[0][j] = fmaf(wv.x, a[j], acc[0][j]);
            acc[1][j] = fmaf(wv.y, a[j], acc[1][j]);
        }
    }
    #pragma unroll
    for (int i = 0; i < 2; i++) {
        int st = sB + i;
        float bb = BM[c*512 + r*64 + st];
        float4 o = { acc[i][0]+bb, acc[i][1]+bb, acc[i][2]+bb, acc[i][3]+bb };
        *(float4*)&Y[((bc*64 + st)*8 + r)*160 + l0 + lB] = o;
    }
}

// ------------------------------------------------------------------------------
// Fused scores (unchanged from R1).
__device__ __forceinline__ void zpost(float z, float wb, float& num, float& den)
{
    float az = fabsf(z);
    den += az;
    float rv = rsqrtf(fmaxf(az, 1e-35f));
    num = fmaf(wb, z * rv, num);
}

__global__ void __launch_bounds__(256) scores_kernel(
    const float* __restrict__ Y1, const float* __restrict__ Y0,
    const float* __restrict__ wbo, const float* __restrict__ bbo,
    float* __restrict__ SC)
{
    __shared__ float s1[16*8*32];
    __shared__ float s0[16*8*32];
    const int tid = threadIdx.x;
    const int qt = blockIdx.x, kt = blockIdx.y, b = blockIdx.z;
    const int kB = (tid & 15) << 1;
    const int qB = (tid >> 4) << 1;
    float acc[2][2] = {};
    for (int c = 0; c < 8; c++) {
        float num[2][2] = {}, den[2][2] = {};
        for (int sq = 0; sq < 4; sq++) {
            const int base = ((b*8 + c)*512 + sq*128)*160;
            __syncthreads();
            #pragma unroll
            for (int j = 0; j < 4; j++) {
                int i = tid + j*256;
                int sr = i >> 3, c4 = (i & 7) << 2;
                *(float4*)&s1[sr*32 + c4] = *(const float4*)(Y1 + base + sr*160 + qt*32 + c4);
                *(float4*)&s0[sr*32 + c4] = *(const float4*)(Y0 + base + sr*160 + kt*32 + c4);
            }
            __syncthreads();
            #pragma unroll 2
            for (int s = 0; s < 16; s++) {
                float z00=0.f, z01=0.f, z10=0.f, z11=0.f;
                #pragma unroll
                for (int rr = 0; rr < 8; rr++) {
                    float2 u = *(const float2*)&s1[(s*8+rr)*32 + qB];
                    float2 v = *(const float2*)&s0[(s*8+rr)*32 + kB];
                    z00 = fmaf(u.x, v.x, z00);
                    z01 = fmaf(u.x, v.y, z01);
                    z10 = fmaf(u.y, v.x, z10);
                    z11 = fmaf(u.y, v.y, z11);
                }
                float wb = wbo[c*64 + sq*16 + s];
                zpost(z00, wb, num[0][0], den[0][0]);
                zpost(z01, wb, num[0][1], den[0][1]);
                zpost(z10, wb, num[1][0], den[1][0]);
                zpost(z11, wb, num[1][1], den[1][1]);
            }
        }
        #pragma unroll
        for (int i = 0; i < 2; i++)
            #pragma unroll
            for (int j = 0; j < 2; j++)
                acc[i][j] += num[i][j] * rsqrtf(fmaxf(den[i][j], 1e-24f));
    }
    float bb = bbo[0];
    int q = qt*32 + qB, k = kt*32 + kB;
    #pragma unroll
    for (int i = 0; i < 2; i++) {
        float2 o = { acc[i][0] + bb, acc[i][1] + bb };
        *(float2*)&SC[(b*160 + q + i)*160 + k] = o;
    }
}

// ------------------------------------------------------------------------------
__global__ void __launch_bounds__(192) softmax_kernel(float* __restrict__ sc)
{
    const int row = blockIdx.x;
    float* p = sc + row*160;
    const int t = threadIdx.x;
    __shared__ float red[6], red2[6];
    float v = (t < 160) ? p[t] : -3.0e38f;
    #pragma unroll
    for (int o = 16; o; o >>= 1) v = fmaxf(v, __shfl_xor_sync(0xffffffffu, v, o));
    if ((t & 31) == 0) red[t >> 5] = v;
    __syncthreads();
    float m = red[0];
    #pragma unroll
    for (int i = 1; i < 6; i++) m = fmaxf(m, red[i]);
    float e = (t < 160) ? expf(p[t] - m) : 0.f;
    float sv = e;
    #pragma unroll
    for (int o = 16; o; o >>= 1) sv += __shfl_xor_sync(0xffffffffu, sv, o);
    if ((t & 31) == 0) red2[t >> 5] = sv;
    __syncthreads();
    float ssum = 0.f;
    #pragma unroll
    for (int i = 0; i < 6; i++) ssum += red2[i];
    if (t < 160) p[t] = e / ssum;
}

// ------------------------------------------------------------------------------
// atted = att @ vv per batch, fused with transpose-scramble (unchanged).
__global__ void __launch_bounds__(256) attv_kernel(
    const float* __restrict__ att, const float* __restrict__ vv,
    float* __restrict__ scr)
{
    __shared__ float As[16][36];
    __shared__ float Ws[16][68];
    const int tid = threadIdx.x;
    const int m0 = blockIdx.x * 32;
    const int n0 = blockIdx.y * 64;
    const int b  = blockIdx.z;
    const float* attb = att + b*160*160;
    const float* vvb  = vv  + b*160*512;
    const int amr = tid >> 3;
    const int akc = (tid & 7) << 1;
    const int wkr = tid >> 4;
    const int wnc = (tid & 15) << 2;
    const int tm = (tid & 15) << 1;
    const int tn = (tid >> 4) << 2;
    float acc[2][4] = {};
    for (int k0 = 0; k0 < 160; k0 += 16) {
        float2 av = *(const float2*)(attb + (m0 + amr)*160 + k0 + akc);
        float4 wv = *(const float4*)(vvb + (k0 + wkr)*512 + n0 + wnc);
        __syncthreads();
        As[akc+0][amr] = av.x; As[akc+1][amr] = av.y;
        *(float4*)&Ws[wkr][wnc] = wv;
        __syncthreads();
        #pragma unroll
        for (int kk = 0; kk < 16; kk++) {
            float a0 = As[kk][tm], a1 = As[kk][tm+1];
            float w[4];
            *(float4*)w = *(const float4*)&Ws[kk][tn];
            #pragma unroll
            for (int j = 0; j < 4; j++) {
                acc[0][j] = fmaf(a0, w[j], acc[0][j]);
                acc[1][j] = fmaf(a1, w[j], acc[1][j]);
            }
        }
    }
    #pragma unroll
    for (int i = 0; i < 2; i++)
        #pragma unroll
        for (int j = 0; j < 4; j++) {
            int q = m0 + tm + i;
            int h = n0 + tn + j;
            scr[b*81920 + h*160 + q] = acc[i][j];
        }
}

// ------------------------------------------------------------------------------
extern "C" void kernel_launch(void* const* d_in, const int* in_sizes, int n_in,
                              void* d_out, int out_size)
{
    (void)in_sizes; (void)n_in; (void)out_size;
    const float* v    = (const float*)d_in[0];
    const float* kin  = (const float*)d_in[1];
    const float* qin  = (const float*)d_in[2];
    const float* w_v  = (const float*)d_in[3];  const float* b_v = (const float*)d_in[4];
    const float* w_k  = (const float*)d_in[5];  const float* b_k = (const float*)d_in[6];
    const float* w_q  = (const float*)d_in[7];  const float* b_q = (const float*)d_in[8];
    const float* w0   = (const float*)d_in[9];  const float* b0  = (const float*)d_in[10];
    const float* w1   = (const float*)d_in[11]; const float* b1  = (const float*)d_in[12];
    const float* wm0  = (const float*)d_in[13]; const float* bm0 = (const float*)d_in[14];
    const float* wm1  = (const float*)d_in[15]; const float* bm1 = (const float*)d_in[16];
    const float* w_bo = (const float*)d_in[17]; const float* b_bo= (const float*)d_in[18];
    const float* w_m  = (const float*)d_in[19]; const float* b_m = (const float*)d_in[20];
    float* out = (float*)d_out;

    float *vv, *kk, *qq, *x0, *x1, *y0, *y1, *sc, *scr;
    cudaGetSymbolAddress((void**)&vv,  g_vv);
    cudaGetSymbolAddress((void**)&kk,  g_kk);
    cudaGetSymbolAddress((void**)&qq,  g_qq);
    cudaGetSymbolAddress((void**)&x0,  g_x0);
    cudaGetSymbolAddress((void**)&x1,  g_x1);
    cudaGetSymbolAddress((void**)&y0,  g_y0);
    cudaGetSymbolAddress((void**)&y1,  g_y1);
    cudaGetSymbolAddress((void**)&sc,  g_sc);
    cudaGetSymbolAddress((void**)&scr, g_scr);

    static int smem_set = 0;
    if (!smem_set) {
        cudaFuncSetAttribute(hmma_gemm_kernel,
                             cudaFuncAttributeMaxDynamicSharedMemorySize, HM_SMEM_BYTES);
        smem_set = 1;
    }

    // Stage 1: vv / kk / qq projections (batched, one launch)
    GemmBatch g1;
    g1.A[0] = v;    g1.W[0] = w_v; g1.bias[0] = b_v; g1.C[0] = vv;
    g1.A[1] = kin;  g1.W[1] = w_k; g1.bias[1] = b_k; g1.C[1] = kk;
    g1.A[2] = qin;  g1.W[2] = w_q; g1.bias[2] = b_q; g1.C[2] = qq;
    hmma_gemm_kernel<<<dim3(10, 8, 3), 256, HM_SMEM_BYTES>>>(g1);

    // Stage 2: x0 = kk @ w0^T, x1 = qq @ w1^T
    GemmBatch g2;
    g2.A[0] = kk; g2.W[0] = w0; g2.bias[0] = b0; g2.C[0] = x0;
    g2.A[1] = qq; g2.W[1] = w1; g2.bias[1] = b1; g2.C[1] = x1;
    g2.A[2] = kk; g2.W[2] = w0; g2.bias[2] = b0; g2.C[2] = x0; // unused (z<2)
    hmma_gemm_kernel<<<dim3(10, 8, 2), 256, HM_SMEM_BYTES>>>(g2);

    merge_kernel<<<dim3(5, 8, 64), 256>>>(x0, wm0, bm0, y0);
    merge_kernel<<<dim3(5, 8, 64), 256>>>(x1, wm1, bm1, y1);

    scores_kernel<<<dim3(5, 5, 8), 256>>>(y1, y0, w_bo, b_bo, sc);
    softmax_kernel<<<1280, 192>>>(sc);
    attv_kernel<<<dim3(5, 8, 8), 256>>>(sc, vv, scr);

    // Stage 3: out = scr @ w_m^T + b_m
    GemmBatch g3;
    g3.A[0] = scr; g3.W[0] = w_m; g3.bias[0] = b_m; g3.C[0] = out;
    g3.A[1] = scr; g3.W[1] = w_m; g3.bias[1] = b_m; g3.C[1] = out; // unused
    g3.A[2] = scr; g3.W[2] = w_m; g3.bias[2] = b_m; g3.C[2] = out; // unused
    hmma_gemm_kernel<<<dim3(10, 8, 1), 256, HM_SMEM_BYTES>>>(g3);
}

// round 4
// speedup vs baseline: 1.3920x; 1.0791x over previous
#include <cuda_runtime.h>
#include <cuda_bf16.h>
#include <cstdint>

// Problem constants (fixed shapes from the reference)
#define NB_B 8
#define NB_L 160
#define NB_H 512
#define NB_C 8
#define NB_S 64
#define NB_R 8
#define NB_BL (NB_B*NB_L)   // 1280

// ---------------- scratch (device globals: no runtime allocation) -------------
__device__ float g_vv [NB_BL*NB_H];
__device__ float g_kk [NB_BL*NB_H];
__device__ float g_qq [NB_BL*NB_H];
__device__ float g_x0 [NB_BL*NB_H];
__device__ float g_x1 [NB_BL*NB_H];
// Y layout: [b][c][s(64)][r(16: 8 hi | 8 lo)][l(160)] bf16
__device__ __nv_bfloat16 g_y0 [NB_B*NB_C*NB_S*16*NB_L];
__device__ __nv_bfloat16 g_y1 [NB_B*NB_C*NB_S*16*NB_L];
__device__ float g_sc [NB_B*NB_L*NB_L];
__device__ float g_scr[NB_B*NB_L*NB_H];

// ======================= mma.sync helpers (sm_80+ path) =======================
__device__ __forceinline__ uint32_t smem_u32(const void* p) {
    uint32_t a;
    asm("{ .reg .u64 t; cvta.to.shared.u64 t, %1; cvt.u32.u64 %0, t; }"
        : "=r"(a) : "l"(p));
    return a;
}
__device__ __forceinline__ void mma16816(float* d, const uint32_t* a, const uint32_t* b) {
    asm volatile(
        "mma.sync.aligned.m16n8k16.row.col.f32.bf16.bf16.f32 "
        "{%0,%1,%2,%3}, {%4,%5,%6,%7}, {%8,%9}, {%0,%1,%2,%3};"
        : "+f"(d[0]), "+f"(d[1]), "+f"(d[2]), "+f"(d[3])
        : "r"(a[0]), "r"(a[1]), "r"(a[2]), "r"(a[3]), "r"(b[0]), "r"(b[1]));
}
__device__ __forceinline__ void ldsm_x4(uint32_t* r, uint32_t addr) {
    asm volatile("ldmatrix.sync.aligned.m8n8.x4.shared.b16 {%0,%1,%2,%3}, [%4];"
        : "=r"(r[0]), "=r"(r[1]), "=r"(r[2]), "=r"(r[3]) : "r"(addr));
}
__device__ __forceinline__ void ldsm_x4t(uint32_t* r, uint32_t addr) {
    asm volatile("ldmatrix.sync.aligned.m8n8.x4.trans.shared.b16 {%0,%1,%2,%3}, [%4];"
        : "=r"(r[0]), "=r"(r[1]), "=r"(r[2]), "=r"(r[3]) : "r"(addr));
}
// m16n8k8 bf16 mma, fresh accumulator (C = 0)
__device__ __forceinline__ void mma1688_z(float* d, uint32_t a0, uint32_t a1, uint32_t b) {
    asm volatile(
        "mma.sync.aligned.m16n8k8.row.col.f32.bf16.bf16.f32 "
        "{%0,%1,%2,%3}, {%4,%5}, {%6}, {%7,%8,%9,%10};"
        : "=f"(d[0]), "=f"(d[1]), "=f"(d[2]), "=f"(d[3])
        : "r"(a0), "r"(a1), "r"(b), "f"(0.f), "f"(0.f), "f"(0.f), "f"(0.f));
}
__device__ __forceinline__ void mma1688_acc(float* d, uint32_t a0, uint32_t a1, uint32_t b) {
    asm volatile(
        "mma.sync.aligned.m16n8k8.row.col.f32.bf16.bf16.f32 "
        "{%0,%1,%2,%3}, {%4,%5}, {%6}, {%0,%1,%2,%3};"
        : "+f"(d[0]), "+f"(d[1]), "+f"(d[2]), "+f"(d[3])
        : "r"(a0), "r"(a1), "r"(b));
}

// ================= bf16-split tensor-core GEMM: C = A @ W^T + bias ===========
struct GemmBatch {
    const float* A[3]; const float* W[3]; const float* bias[3]; float* C[3];
};

#define LDA_S 72
#define OFF_AH 0
#define OFF_AL (128*LDA_S)
#define OFF_WH (256*LDA_S)
#define OFF_WL (320*LDA_S)
#define HM_SMEM_BYTES (384*LDA_S*2)   // 55296

__global__ void __launch_bounds__(256) hmma_gemm_kernel(GemmBatch gb)
{
    extern __shared__ __nv_bfloat16 sm[];
    const int tid  = threadIdx.x;
    const int wid  = tid >> 5, lane = tid & 31;
    const int z = blockIdx.z;
    const float* A    = gb.A[z];
    const float* W    = gb.W[z];
    const float* bias = gb.bias[z];
    float*       C    = gb.C[z];
    const int m0 = blockIdx.x * 128;
    const int n0 = blockIdx.y * 64;
    const int wm = wid & 3, wn = wid >> 2;
    const uint32_t sb = smem_u32(sm);

    float acc[2][4][4] = {};

    const int a_row = wm * 32 + (lane & 15);
    const uint32_t a_addr0 = sb + (uint32_t)((OFF_AH + a_row * LDA_S + (lane >> 4) * 8) * 2);
    const int b_row = wn * 32 + ((lane >> 4) & 1) * 8 + (lane & 7);
    const uint32_t b_addr0 = sb + (uint32_t)((OFF_WH + b_row * LDA_S + ((lane >> 3) & 1) * 8) * 2);
    const uint32_t ALO_B = (uint32_t)((OFF_AL - OFF_AH) * 2);
    const uint32_t WLO_B = (uint32_t)((OFF_WL - OFF_WH) * 2);

    for (int kc = 0; kc < 8; kc++) {
        const int kbase = kc * 64;
        __syncthreads();
        #pragma unroll
        for (int it = 0; it < 8; it++) {
            int u = tid + it * 256;
            int row = u >> 4, kg = (u & 15) << 2;
            float4 v = *(const float4*)(A + (m0 + row) * 512 + kbase + kg);
            __nv_bfloat162 h01 = __floats2bfloat162_rn(v.x, v.y);
            __nv_bfloat162 h23 = __floats2bfloat162_rn(v.z, v.w);
            float2 f01 = __bfloat1622float2(h01);
            float2 f23 = __bfloat1622float2(h23);
            __nv_bfloat162 l01 = __floats2bfloat162_rn(v.x - f01.x, v.y - f01.y);
            __nv_bfloat162 l23 = __floats2bfloat162_rn(v.z - f23.x, v.w - f23.y);
            int o = row * LDA_S + kg;
            *(uint2*)&sm[OFF_AH + o] = make_uint2(*(uint32_t*)&h01, *(uint32_t*)&h23);
            *(uint2*)&sm[OFF_AL + o] = make_uint2(*(uint32_t*)&l01, *(uint32_t*)&l23);
        }
        #pragma unroll
        for (int it = 0; it < 4; it++) {
            int u = tid + it * 256;
            int row = u >> 4, kg = (u & 15) << 2;
            float4 v = *(const float4*)(W + (n0 + row) * 512 + kbase + kg);
            __nv_bfloat162 h01 = __floats2bfloat162_rn(v.x, v.y);
            __nv_bfloat162 h23 = __floats2bfloat162_rn(v.z, v.w);
            float2 f01 = __bfloat1622float2(h01);
            float2 f23 = __bfloat1622float2(h23);
            __nv_bfloat162 l01 = __floats2bfloat162_rn(v.x - f01.x, v.y - f01.y);
            __nv_bfloat162 l23 = __floats2bfloat162_rn(v.z - f23.x, v.w - f23.y);
            int o = row * LDA_S + kg;
            *(uint2*)&sm[OFF_WH + o] = make_uint2(*(uint32_t*)&h01, *(uint32_t*)&h23);
            *(uint2*)&sm[OFF_WL + o] = make_uint2(*(uint32_t*)&l01, *(uint32_t*)&l23);
        }
        __syncthreads();

        #pragma unroll
        for (int k16 = 0; k16 < 4; k16++) {
            const uint32_t kb = (uint32_t)(k16 * 32);
            uint32_t ah[2][4], al[2][4];
            ldsm_x4(ah[0], a_addr0 + kb);
            ldsm_x4(ah[1], a_addr0 + (uint32_t)(16 * LDA_S * 2) + kb);
            ldsm_x4(al[0], a_addr0 + ALO_B + kb);
            ldsm_x4(al[1], a_addr0 + ALO_B + (uint32_t)(16 * LDA_S * 2) + kb);
            uint32_t bh[2][4], bl[2][4];
            ldsm_x4(bh[0], b_addr0 + kb);
            ldsm_x4(bh[1], b_addr0 + (uint32_t)(16 * LDA_S * 2) + kb);
            ldsm_x4(bl[0], b_addr0 + WLO_B + kb);
            ldsm_x4(bl[1], b_addr0 + WLO_B + (uint32_t)(16 * LDA_S * 2) + kb);
            #pragma unroll
            for (int mi = 0; mi < 2; mi++) {
                #pragma unroll
                for (int nj = 0; nj < 4; nj++) {
                    const uint32_t* bph = &bh[nj >> 1][(nj & 1) * 2];
                    const uint32_t* bpl = &bl[nj >> 1][(nj & 1) * 2];
                    mma16816(acc[mi][nj], ah[mi], bph);
                    mma16816(acc[mi][nj], ah[mi], bpl);
                    mma16816(acc[mi][nj], al[mi], bph);
                }
            }
        }
    }

    const int mrow = m0 + wm * 32 + (lane >> 2);
    const int ncol = n0 + wn * 32 + (lane & 3) * 2;
    #pragma unroll
    for (int mi = 0; mi < 2; mi++) {
        #pragma unroll
        for (int nj = 0; nj < 4; nj++) {
            int n = ncol + nj * 8;
            float b0 = bias[n], b1 = bias[n + 1];
            int m_a = mrow + mi * 16;
            *(float2*)&C[m_a * 512 + n]       = make_float2(acc[mi][nj][0] + b0, acc[mi][nj][1] + b1);
            *(float2*)&C[(m_a + 8) * 512 + n] = make_float2(acc[mi][nj][2] + b0, acc[mi][nj][3] + b1);
        }
    }
}

// ------------------------------------------------------------------------------
// Merge projection + transpose. Output: bf16 hi/lo planes
//   Y[((bc*64 + st)*16 + r)*160 + l]       = hi(y)
//   Y[((bc*64 + st)*16 + r + 8)*160 + l]   = lo(y)
__global__ void __launch_bounds__(256) merge_kernel(
    const float* __restrict__ X, const float* __restrict__ WM,
    const float* __restrict__ BM, __nv_bfloat16* __restrict__ Y)
{
    __shared__ float xs[64][36];
    __shared__ float ws[64][68];
    const int tid = threadIdx.x;
    const int l0 = blockIdx.x * 32;
    const int r  = blockIdx.y;
    const int bc = blockIdx.z;
    const int b = bc >> 3, c = bc & 7;
    #pragma unroll
    for (int j = 0; j < 2; j++) {
        int i = tid + j*256;
        int ll = i >> 4, k4 = (i & 15) << 2;
        float4 v = *(const float4*)(X + (b*160 + l0 + ll)*512 + c*64 + k4);
        xs[k4+0][ll]=v.x; xs[k4+1][ll]=v.y; xs[k4+2][ll]=v.z; xs[k4+3][ll]=v.w;
    }
    #pragma unroll
    for (int j = 0; j < 4; j++) {
        int i = tid + j*256;
        int st = i >> 4, k4 = (i & 15) << 2;
        float4 v = *(const float4*)(WM + (c*512 + r*64 + st)*64 + k4);
        ws[k4+0][st]=v.x; ws[k4+1][st]=v.y; ws[k4+2][st]=v.z; ws[k4+3][st]=v.w;
    }
    __syncthreads();
    const int lB = (tid & 7) << 2;
    const int sB = (tid >> 3) << 1;
    float acc[2][4] = {};
    #pragma unroll 8
    for (int k = 0; k < 64; k++) {
        float a[4];
        *(float4*)a = *(const float4*)&xs[k][lB];
        float2 wv = *(const float2*)&ws[k][sB];
        #pragma unroll
        for (int j = 0; j < 4; j++) {
            acc[0][j] = fmaf(wv.x, a[j], acc[0][j]);
            acc[1][j] = fmaf(wv.y, a[j], acc[1][j]);
        }
    }
    #pragma unroll
    for (int i = 0; i < 2; i++) {
        int st = sB + i;
        float bb = BM[c*512 + r*64 + st];
        __nv_bfloat16 hi[4], lo[4];
        #pragma unroll
        for (int j = 0; j < 4; j++) {
            float v = acc[i][j] + bb;
            hi[j] = __float2bfloat16(v);
            lo[j] = __float2bfloat16(v - __bfloat162float(hi[j]));
        }
        size_t base = ((size_t)(bc*64 + st)*16 + r)*160 + l0 + lB;
        *(uint2*)&Y[base]           = *(uint2*)hi;
        *(uint2*)&Y[base + 8*160]   = *(uint2*)lo;
    }
}

// ------------------------------------------------------------------------------
// Tensor-core scores:
//   z[q,k] = sum_r y1·y0 (3-term bf16 split via mma.m16n8k8)
//   num += wb * sign(z)·sqrt(|z|);  den += |z|;  acc += num·rsqrt(den) per c.
// Grid (5 qt, 5 kt, 8 b), 128 threads = 4 warps (2q x 2k), warp tile 16q x 16k.
__global__ void __launch_bounds__(128) scores_tc(
    const __nv_bfloat16* __restrict__ Y1, const __nv_bfloat16* __restrict__ Y0,
    const float* __restrict__ wbo, float* __restrict__ SC)
{
    __shared__ __nv_bfloat16 S1[128*72];   // [st*16 + r16][72] (32 q used)
    __shared__ __nv_bfloat16 S0[128*72];   // [st*16 + r16][72] (32 k used)
    __shared__ float swb[512];
    const int tid = threadIdx.x;
    const int warp = tid >> 5, lane = tid & 31;
    const int qt = blockIdx.x, kt = blockIdx.y, b = blockIdx.z;
    const int qoff = (warp >> 1) * 16, koff = (warp & 1) * 16;
    for (int i = tid; i < 512; i += 128) swb[i] = wbo[i];

    const uint32_t s1b = smem_u32(S1), s0b = smem_u32(S0);
    const int t4 = lane >> 3, rr = lane & 7;
    const int lrow = ((t4 & 2) ? 8 : 0) + rr;     // hi rows 0-7, lo rows 8-15
    const uint32_t aoff = (uint32_t)((lrow * 72 + qoff + (t4 & 1) * 8) * 2);
    const uint32_t boff = (uint32_t)((lrow * 72 + koff + (t4 & 1) * 8) * 2);

    float acc[2][4] = {};
    for (int c = 0; c < 8; c++) {
        float num[2][4] = {}, den[2][4] = {};
        for (int oct = 0; oct < 8; oct++) {
            __syncthreads();
            const int sbase = ((b*8 + c)*64 + oct*8) * 16;
            #pragma unroll
            for (int it = 0; it < 8; it++) {
                int u = tid + it*128;
                int half = u >> 9, v = u & 511;
                int row = v >> 2, ch = v & 3;
                const __nv_bfloat16* src = (half ? Y0 : Y1)
                    + (size_t)(sbase + row) * 160 + (half ? kt : qt) * 32 + ch * 8;
                __nv_bfloat16* dst = (half ? S0 : S1) + row * 72 + ch * 8;
                *(uint4*)dst = *(const uint4*)src;
            }
            __syncthreads();
            #pragma unroll
            for (int st = 0; st < 8; st++) {
                const uint32_t tb = (uint32_t)(st * 2304);   // st*16 rows * 144B
                uint32_t a[4], bv[4];
                ldsm_x4t(a,  s1b + tb + aoff);   // a0,a1 = hi A-frag; a2,a3 = lo
                ldsm_x4t(bv, s0b + tb + boff);   // b0=hi kf0, b1=hi kf1, b2=lo kf0, b3=lo kf1
                float z0[4], z1[4];
                mma1688_z  (z0, a[0], a[1], bv[0]);
                mma1688_acc(z0, a[0], a[1], bv[2]);
                mma1688_acc(z0, a[2], a[3], bv[0]);
                mma1688_z  (z1, a[0], a[1], bv[1]);
                mma1688_acc(z1, a[0], a[1], bv[3]);
                mma1688_acc(z1, a[2], a[3], bv[1]);
                const float wb = swb[c*64 + oct*8 + st];
                #pragma unroll
                for (int e = 0; e < 4; e++) {
                    {
                        float az = fabsf(z0[e]);
                        den[0][e] += az;
                        float s;
                        asm("sqrt.approx.f32 %0, %1;" : "=f"(s) : "f"(az));
                        uint32_t sb2 = (__float_as_uint(s) & 0x7fffffffu)
                                     | (__float_as_uint(z0[e]) & 0x80000000u);
                        num[0][e] = fmaf(wb, __uint_as_float(sb2), num[0][e]);
                    }
                    {
                        float az = fabsf(z1[e]);
                        den[1][e] += az;
                        float s;
                        asm("sqrt.approx.f32 %0, %1;" : "=f"(s) : "f"(az));
                        uint32_t sb2 = (__float_as_uint(s) & 0x7fffffffu)
                                     | (__float_as_uint(z1[e]) & 0x80000000u);
                        num[1][e] = fmaf(wb, __uint_as_float(sb2), num[1][e]);
                    }
                }
            }
        }
        #pragma unroll
        for (int kf = 0; kf < 2; kf++)
            #pragma unroll
            for (int e = 0; e < 4; e++)
                acc[kf][e] += num[kf][e] * rsqrtf(fmaxf(den[kf][e], 1e-24f));
    }
    // epilogue (b_bo dropped: softmax-invariant global constant)
    const int q = qt*32 + qoff + (lane >> 2);
    const int k = kt*32 + koff + (lane & 3)*2;
    float* p0 = SC + (size_t)(b*160 + q)*160 + k;
    *(float2*)(p0)             = make_float2(acc[0][0], acc[0][1]);
    *(float2*)(p0 + 8)         = make_float2(acc[1][0], acc[1][1]);
    *(float2*)(p0 + 8*160)     = make_float2(acc[0][2], acc[0][3]);
    *(float2*)(p0 + 8*160 + 8) = make_float2(acc[1][2], acc[1][3]);
}

// ------------------------------------------------------------------------------
__global__ void __launch_bounds__(192) softmax_kernel(float* __restrict__ sc)
{
    const int row = blockIdx.x;
    float* p = sc + row*160;
    const int t = threadIdx.x;
    __shared__ float red[6], red2[6];
    float v = (t < 160) ? p[t] : -3.0e38f;
    #pragma unroll
    for (int o = 16; o; o >>= 1) v = fmaxf(v, __shfl_xor_sync(0xffffffffu, v, o));
    if ((t & 31) == 0) red[t >> 5] = v;
    __syncthreads();
    float m = red[0];
    #pragma unroll
    for (int i = 1; i < 6; i++) m = fmaxf(m, red[i]);
    float e = (t < 160) ? expf(p[t] - m) : 0.f;
    float sv = e;
    #pragma unroll
    for (int o = 16; o; o >>= 1) sv += __shfl_xor_sync(0xffffffffu, sv, o);
    if ((t & 31) == 0) red2[t >> 5] = sv;
    __syncthreads();
    float ssum = 0.f;
    #pragma unroll
    for (int i = 0; i < 6; i++) ssum += red2[i];
    if (t < 160) p[t] = e / ssum;
}

// ------------------------------------------------------------------------------
__global__ void __launch_bounds__(256) attv_kernel(
    const float* __restrict__ att, const float* __restrict__ vv,
    float* __restrict__ scr)
{
    __shared__ float As[16][36];
    __shared__ float Ws[16][68];
    const int tid = threadIdx.x;
    const int m0 = blockIdx.x * 32;
    const int n0 = blockIdx.y * 64;
    const int b  = blockIdx.z;
    const float* attb = att + b*160*160;
    const float* vvb  = vv  + b*160*512;
    const int amr = tid >> 3;
    const int akc = (tid & 7) << 1;
    const int wkr = tid >> 4;
    const int wnc = (tid & 15) << 2;
    const int tm = (tid & 15) << 1;
    const int tn = (tid >> 4) << 2;
    float acc[2][4] = {};
    for (int k0 = 0; k0 < 160; k0 += 16) {
        float2 av = *(const float2*)(attb + (m0 + amr)*160 + k0 + akc);
        float4 wv = *(const float4*)(vvb + (k0 + wkr)*512 + n0 + wnc);
        __syncthreads();
        As[akc+0][amr] = av.x; As[akc+1][amr] = av.y;
        *(float4*)&Ws[wkr][wnc] = wv;
        __syncthreads();
        #pragma unroll
        for (int kk = 0; kk < 16; kk++) {
            float a0 = As[kk][tm], a1 = As[kk][tm+1];
            float w[4];
            *(float4*)w = *(const float4*)&Ws[kk][tn];
            #pragma unroll
            for (int j = 0; j < 4; j++) {
                acc[0][j] = fmaf(a0, w[j], acc[0][j]);
                acc[1][j] = fmaf(a1, w[j], acc[1][j]);
            }
        }
    }
    #pragma unroll
    for (int i = 0; i < 2; i++)
        #pragma unroll
        for (int j = 0; j < 4; j++) {
            int q = m0 + tm + i;
            int h = n0 + tn + j;
            scr[b*81920 + h*160 + q] = acc[i][j];
        }
}

// ------------------------------------------------------------------------------
extern "C" void kernel_launch(void* const* d_in, const int* in_sizes, int n_in,
                              void* d_out, int out_size)
{
    (void)in_sizes; (void)n_in; (void)out_size;
    const float* v    = (const float*)d_in[0];
    const float* kin  = (const float*)d_in[1];
    const float* qin  = (const float*)d_in[2];
    const float* w_v  = (const float*)d_in[3];  const float* b_v = (const float*)d_in[4];
    const float* w_k  = (const float*)d_in[5];  const float* b_k = (const float*)d_in[6];
    const float* w_q  = (const float*)d_in[7];  const float* b_q = (const float*)d_in[8];
    const float* w0   = (const float*)d_in[9];  const float* b0  = (const float*)d_in[10];
    const float* w1   = (const float*)d_in[11]; const float* b1  = (const float*)d_in[12];
    const float* wm0  = (const float*)d_in[13]; const float* bm0 = (const float*)d_in[14];
    const float* wm1  = (const float*)d_in[15]; const float* bm1 = (const float*)d_in[16];
    const float* w_bo = (const float*)d_in[17];
    const float* w_m  = (const float*)d_in[19]; const float* b_m = (const float*)d_in[20];
    float* out = (float*)d_out;

    float *vv, *kk, *qq, *x0, *x1, *sc, *scr;
    __nv_bfloat16 *y0, *y1;
    cudaGetSymbolAddress((void**)&vv,  g_vv);
    cudaGetSymbolAddress((void**)&kk,  g_kk);
    cudaGetSymbolAddress((void**)&qq,  g_qq);
    cudaGetSymbolAddress((void**)&x0,  g_x0);
    cudaGetSymbolAddress((void**)&x1,  g_x1);
    cudaGetSymbolAddress((void**)&y0,  g_y0);
    cudaGetSymbolAddress((void**)&y1,  g_y1);
    cudaGetSymbolAddress((void**)&sc,  g_sc);
    cudaGetSymbolAddress((void**)&scr, g_scr);

    static int smem_set = 0;
    if (!smem_set) {
        cudaFuncSetAttribute(hmma_gemm_kernel,
                             cudaFuncAttributeMaxDynamicSharedMemorySize, HM_SMEM_BYTES);
        smem_set = 1;
    }

    GemmBatch g1;
    g1.A[0] = v;    g1.W[0] = w_v; g1.bias[0] = b_v; g1.C[0] = vv;
    g1.A[1] = kin;  g1.W[1] = w_k; g1.bias[1] = b_k; g1.C[1] = kk;
    g1.A[2] = qin;  g1.W[2] = w_q; g1.bias[2] = b_q; g1.C[2] = qq;
    hmma_gemm_kernel<<<dim3(10, 8, 3), 256, HM_SMEM_BYTES>>>(g1);

    GemmBatch g2;
    g2.A[0] = kk; g2.W[0] = w0; g2.bias[0] = b0; g2.C[0] = x0;
    g2.A[1] = qq; g2.W[1] = w1; g2.bias[1] = b1; g2.C[1] = x1;
    g2.A[2] = kk; g2.W[2] = w0; g2.bias[2] = b0; g2.C[2] = x0;
    hmma_gemm_kernel<<<dim3(10, 8, 2), 256, HM_SMEM_BYTES>>>(g2);

    merge_kernel<<<dim3(5, 8, 64), 256>>>(x0, wm0, bm0, y0);
    merge_kernel<<<dim3(5, 8, 64), 256>>>(x1, wm1, bm1, y1);

    scores_tc<<<dim3(5, 5, 8), 128>>>(y1, y0, w_bo, sc);
    softmax_kernel<<<1280, 192>>>(sc);
    attv_kernel<<<dim3(5, 8, 8), 256>>>(sc, vv, scr);

    GemmBatch g3;
    g3.A[0] = scr; g3.W[0] = w_m; g3.bias[0] = b_m; g3.C[0] = out;
    g3.A[1] = scr; g3.W[1] = w_m; g3.bias[1] = b_m; g3.C[1] = out;
    g3.A[2] = scr; g3.W[2] = w_m; g3.bias[2] = b_m; g3.C[2] = out;
    hmma_gemm_kernel<<<dim3(10, 8, 1), 256, HM_SMEM_BYTES>>>(g3);
}

// round 5
// speedup vs baseline: 1.6502x; 1.1854x over previous
#include <cuda_runtime.h>
#include <cuda_bf16.h>
#include <cstdint>

// Problem constants (fixed shapes from the reference)
#define NB_B 8
#define NB_L 160
#define NB_H 512
#define NB_C 8
#define NB_S 64
#define NB_R 8
#define NB_BL (NB_B*NB_L)   // 1280

// ---------------- scratch (device globals: no runtime allocation) -------------
__device__ float g_vv [NB_BL*NB_H];
__device__ float g_kk [NB_BL*NB_H];
__device__ float g_qq [NB_BL*NB_H];
__device__ float g_x0 [NB_BL*NB_H];
__device__ float g_x1 [NB_BL*NB_H];
// Y layout: [b][c][s(64)][r(16: 8 hi | 8 lo)][l(160)] bf16
__device__ __nv_bfloat16 g_y0 [NB_B*NB_C*NB_S*16*NB_L];
__device__ __nv_bfloat16 g_y1 [NB_B*NB_C*NB_S*16*NB_L];
__device__ float g_sc [NB_B*NB_L*NB_L];
__device__ float g_scr[NB_B*NB_L*NB_H];

// ======================= mma.sync helpers (sm_80+ path) =======================
__device__ __forceinline__ uint32_t smem_u32(const void* p) {
    uint32_t a;
    asm("{ .reg .u64 t; cvta.to.shared.u64 t, %1; cvt.u32.u64 %0, t; }"
        : "=r"(a) : "l"(p));
    return a;
}
__device__ __forceinline__ void mma16816(float* d, const uint32_t* a, const uint32_t* b) {
    asm volatile(
        "mma.sync.aligned.m16n8k16.row.col.f32.bf16.bf16.f32 "
        "{%0,%1,%2,%3}, {%4,%5,%6,%7}, {%8,%9}, {%0,%1,%2,%3};"
        : "+f"(d[0]), "+f"(d[1]), "+f"(d[2]), "+f"(d[3])
        : "r"(a[0]), "r"(a[1]), "r"(a[2]), "r"(a[3]), "r"(b[0]), "r"(b[1]));
}
__device__ __forceinline__ void ldsm_x4(uint32_t* r, uint32_t addr) {
    asm volatile("ldmatrix.sync.aligned.m8n8.x4.shared.b16 {%0,%1,%2,%3}, [%4];"
        : "=r"(r[0]), "=r"(r[1]), "=r"(r[2]), "=r"(r[3]) : "r"(addr));
}
__device__ __forceinline__ void ldsm_x4t(uint32_t* r, uint32_t addr) {
    asm volatile("ldmatrix.sync.aligned.m8n8.x4.trans.shared.b16 {%0,%1,%2,%3}, [%4];"
        : "=r"(r[0]), "=r"(r[1]), "=r"(r[2]), "=r"(r[3]) : "r"(addr));
}
__device__ __forceinline__ void mma1688_z(float* d, uint32_t a0, uint32_t a1, uint32_t b) {
    asm volatile(
        "mma.sync.aligned.m16n8k8.row.col.f32.bf16.bf16.f32 "
        "{%0,%1,%2,%3}, {%4,%5}, {%6}, {%7,%8,%9,%10};"
        : "=f"(d[0]), "=f"(d[1]), "=f"(d[2]), "=f"(d[3])
        : "r"(a0), "r"(a1), "r"(b), "f"(0.f), "f"(0.f), "f"(0.f), "f"(0.f));
}
__device__ __forceinline__ void mma1688_acc(float* d, uint32_t a0, uint32_t a1, uint32_t b) {
    asm volatile(
        "mma.sync.aligned.m16n8k8.row.col.f32.bf16.bf16.f32 "
        "{%0,%1,%2,%3}, {%4,%5}, {%6}, {%0,%1,%2,%3};"
        : "+f"(d[0]), "+f"(d[1]), "+f"(d[2]), "+f"(d[3])
        : "r"(a0), "r"(a1), "r"(b));
}
// fp32 -> bf16 hi/lo split of a float4, stored to hi/lo SMEM planes
__device__ __forceinline__ void split_store(__nv_bfloat16* smh, __nv_bfloat16* sml,
                                            int off, float4 v) {
    __nv_bfloat162 h01 = __floats2bfloat162_rn(v.x, v.y);
    __nv_bfloat162 h23 = __floats2bfloat162_rn(v.z, v.w);
    float2 f01 = __bfloat1622float2(h01);
    float2 f23 = __bfloat1622float2(h23);
    __nv_bfloat162 l01 = __floats2bfloat162_rn(v.x - f01.x, v.y - f01.y);
    __nv_bfloat162 l23 = __floats2bfloat162_rn(v.z - f23.x, v.w - f23.y);
    *(uint2*)&smh[off] = make_uint2(*(uint32_t*)&h01, *(uint32_t*)&h23);
    *(uint2*)&sml[off] = make_uint2(*(uint32_t*)&l01, *(uint32_t*)&l23);
}

// ================= bf16-split tensor-core GEMM: C = A @ W^T + bias ===========
struct GemmBatch {
    const float* A[3]; const float* W[3]; const float* bias[3]; float* C[3];
};

#define LDA_S 72
#define OFF_AH 0
#define OFF_AL (128*LDA_S)
#define OFF_WH (256*LDA_S)
#define OFF_WL (320*LDA_S)
#define HM_SMEM_BYTES (384*LDA_S*2)   // 55296

__global__ void __launch_bounds__(256) hmma_gemm_kernel(GemmBatch gb)
{
    extern __shared__ __nv_bfloat16 sm[];
    const int tid  = threadIdx.x;
    const int wid  = tid >> 5, lane = tid & 31;
    const int z = blockIdx.z;
    const float* A    = gb.A[z];
    const float* W    = gb.W[z];
    const float* bias = gb.bias[z];
    float*       C    = gb.C[z];
    const int m0 = blockIdx.x * 128;
    const int n0 = blockIdx.y * 64;
    const int wm = wid & 3, wn = wid >> 2;
    const uint32_t sb = smem_u32(sm);

    float acc[2][4][4] = {};

    const int a_row = wm * 32 + (lane & 15);
    const uint32_t a_addr0 = sb + (uint32_t)((OFF_AH + a_row * LDA_S + (lane >> 4) * 8) * 2);
    const int b_row = wn * 32 + ((lane >> 4) & 1) * 8 + (lane & 7);
    const uint32_t b_addr0 = sb + (uint32_t)((OFF_WH + b_row * LDA_S + ((lane >> 3) & 1) * 8) * 2);
    const uint32_t ALO_B = (uint32_t)((OFF_AL - OFF_AH) * 2);
    const uint32_t WLO_B = (uint32_t)((OFF_WL - OFF_WH) * 2);

    for (int kc = 0; kc < 8; kc++) {
        const int kbase = kc * 64;
        __syncthreads();
        #pragma unroll
        for (int it = 0; it < 8; it++) {
            int u = tid + it * 256;
            int row = u >> 4, kg = (u & 15) << 2;
            float4 v = *(const float4*)(A + (m0 + row) * 512 + kbase + kg);
            split_store(sm + OFF_AH, sm + OFF_AL, row * LDA_S + kg, v);
        }
        #pragma unroll
        for (int it = 0; it < 4; it++) {
            int u = tid + it * 256;
            int row = u >> 4, kg = (u & 15) << 2;
            float4 v = *(const float4*)(W + (n0 + row) * 512 + kbase + kg);
            split_store(sm + OFF_WH, sm + OFF_WL, row * LDA_S + kg, v);
        }
        __syncthreads();

        #pragma unroll
        for (int k16 = 0; k16 < 4; k16++) {
            const uint32_t kb = (uint32_t)(k16 * 32);
            uint32_t ah[2][4], al[2][4];
            ldsm_x4(ah[0], a_addr0 + kb);
            ldsm_x4(ah[1], a_addr0 + (uint32_t)(16 * LDA_S * 2) + kb);
            ldsm_x4(al[0], a_addr0 + ALO_B + kb);
            ldsm_x4(al[1], a_addr0 + ALO_B + (uint32_t)(16 * LDA_S * 2) + kb);
            uint32_t bh[2][4], bl[2][4];
            ldsm_x4(bh[0], b_addr0 + kb);
            ldsm_x4(bh[1], b_addr0 + (uint32_t)(16 * LDA_S * 2) + kb);
            ldsm_x4(bl[0], b_addr0 + WLO_B + kb);
            ldsm_x4(bl[1], b_addr0 + WLO_B + (uint32_t)(16 * LDA_S * 2) + kb);
            #pragma unroll
            for (int mi = 0; mi < 2; mi++) {
                #pragma unroll
                for (int nj = 0; nj < 4; nj++) {
                    const uint32_t* bph = &bh[nj >> 1][(nj & 1) * 2];
                    const uint32_t* bpl = &bl[nj >> 1][(nj & 1) * 2];
                    mma16816(acc[mi][nj], ah[mi], bph);
                    mma16816(acc[mi][nj], ah[mi], bpl);
                    mma16816(acc[mi][nj], al[mi], bph);
                }
            }
        }
    }

    const int mrow = m0 + wm * 32 + (lane >> 2);
    const int ncol = n0 + wn * 32 + (lane & 3) * 2;
    #pragma unroll
    for (int mi = 0; mi < 2; mi++) {
        #pragma unroll
        for (int nj = 0; nj < 4; nj++) {
            int n = ncol + nj * 8;
            float b0 = bias[n], b1 = bias[n + 1];
            int m_a = mrow + mi * 16;
            *(float2*)&C[m_a * 512 + n]       = make_float2(acc[mi][nj][0] + b0, acc[mi][nj][1] + b1);
            *(float2*)&C[(m_a + 8) * 512 + n] = make_float2(acc[mi][nj][2] + b0, acc[mi][nj][3] + b1);
        }
    }
}

// ------------------------------------------------------------------------------
// Tensor-core merge projection + transpose, both tensors in one launch.
// For chunk c: Ymat[m, t] = sum_s X[m, c*64+s] * WM[c, t, s] + BM[c, t]
//   m = b*160+l (M=1280), t = r*64+st (N tile 64 => r = blockIdx.y), K=64.
// Output (bf16 hi/lo planes): Y[(( (b*8+c)*64 + st)*16 + r     )*160 + l] = hi
//                             Y[(( (b*8+c)*64 + st)*16 + r + 8 )*160 + l] = lo
struct MergeBatch {
    const float* X[2]; const float* WM[2]; const float* BM[2]; __nv_bfloat16* Y[2];
};

__global__ void __launch_bounds__(256) merge_tc_kernel(MergeBatch mb)
{
    extern __shared__ __nv_bfloat16 sm[];
    const int tid  = threadIdx.x;
    const int wid  = tid >> 5, lane = tid & 31;
    const int zz = blockIdx.z;
    const int tensor = zz >> 3, c = zz & 7;
    const float* X  = mb.X[tensor];
    const float* WM = mb.WM[tensor];
    const float* BM = mb.BM[tensor];
    __nv_bfloat16* Y = mb.Y[tensor];
    const int m0 = blockIdx.x * 128;
    const int r  = blockIdx.y;          // n0 = r*64
    const int n0 = r * 64;
    const int wm = wid & 3, wn = wid >> 2;
    const uint32_t sb = smem_u32(sm);

    // ---- stage X chunk: 128 rows(m) x 64 k ----
    #pragma unroll
    for (int it = 0; it < 8; it++) {
        int u = tid + it * 256;
        int row = u >> 4, kg = (u & 15) << 2;
        float4 v = *(const float4*)(X + (m0 + row) * 512 + c * 64 + kg);
        split_store(sm + OFF_AH, sm + OFF_AL, row * LDA_S + kg, v);
    }
    // ---- stage WM chunk: 64 rows(t) x 64 k ----
    #pragma unroll
    for (int it = 0; it < 4; it++) {
        int u = tid + it * 256;
        int row = u >> 4, kg = (u & 15) << 2;
        float4 v = *(const float4*)(WM + (size_t)(c * 512 + n0 + row) * 64 + kg);
        split_store(sm + OFF_WH, sm + OFF_WL, row * LDA_S + kg, v);
    }
    __syncthreads();

    const int a_row = wm * 32 + (lane & 15);
    const uint32_t a_addr0 = sb + (uint32_t)((OFF_AH + a_row * LDA_S + (lane >> 4) * 8) * 2);
    const int b_row = wn * 32 + ((lane >> 4) & 1) * 8 + (lane & 7);
    const uint32_t b_addr0 = sb + (uint32_t)((OFF_WH + b_row * LDA_S + ((lane >> 3) & 1) * 8) * 2);
    const uint32_t ALO_B = (uint32_t)((OFF_AL - OFF_AH) * 2);
    const uint32_t WLO_B = (uint32_t)((OFF_WL - OFF_WH) * 2);

    float acc[2][4][4] = {};
    #pragma unroll
    for (int k16 = 0; k16 < 4; k16++) {
        const uint32_t kb = (uint32_t)(k16 * 32);
        uint32_t ah[2][4], al[2][4];
        ldsm_x4(ah[0], a_addr0 + kb);
        ldsm_x4(ah[1], a_addr0 + (uint32_t)(16 * LDA_S * 2) + kb);
        ldsm_x4(al[0], a_addr0 + ALO_B + kb);
        ldsm_x4(al[1], a_addr0 + ALO_B + (uint32_t)(16 * LDA_S * 2) + kb);
        uint32_t bh[2][4], bl[2][4];
        ldsm_x4(bh[0], b_addr0 + kb);
        ldsm_x4(bh[1], b_addr0 + (uint32_t)(16 * LDA_S * 2) + kb);
        ldsm_x4(bl[0], b_addr0 + WLO_B + kb);
        ldsm_x4(bl[1], b_addr0 + WLO_B + (uint32_t)(16 * LDA_S * 2) + kb);
        #pragma unroll
        for (int mi = 0; mi < 2; mi++) {
            #pragma unroll
            for (int nj = 0; nj < 4; nj++) {
                const uint32_t* bph = &bh[nj >> 1][(nj & 1) * 2];
                const uint32_t* bpl = &bl[nj >> 1][(nj & 1) * 2];
                mma16816(acc[mi][nj], ah[mi], bph);
                mma16816(acc[mi][nj], ah[mi], bpl);
                mma16816(acc[mi][nj], al[mi], bph);
            }
        }
    }

    // ---- epilogue: pack (hi|lo<<16) into SMEM [t(64)][m(132 stride)] ----
    __syncthreads();
    uint32_t* ps = (uint32_t*)sm;   // 64*132*4 = 33792 B <= 55296
    const int mbase = wm * 32 + (lane >> 2);
    const int tbase = wn * 32 + (lane & 3) * 2;
    #pragma unroll
    for (int mi = 0; mi < 2; mi++) {
        #pragma unroll
        for (int nj = 0; nj < 4; nj++) {
            int tt = tbase + nj * 8;
            float bb0 = BM[c * 512 + n0 + tt];
            float bb1 = BM[c * 512 + n0 + tt + 1];
            #pragma unroll
            for (int e = 0; e < 4; e++) {
                int mm = mbase + mi * 16 + ((e >> 1) ? 8 : 0);
                int tc2 = tt + (e & 1);
                float v = acc[mi][nj][e] + ((e & 1) ? bb1 : bb0);
                __nv_bfloat16 hi = __float2bfloat16(v);
                __nv_bfloat16 lo = __float2bfloat16(v - __bfloat162float(hi));
                ps[tc2 * 132 + mm] = (uint32_t)*(uint16_t*)&hi
                                   | ((uint32_t)*(uint16_t*)&lo << 16);
            }
        }
    }
    __syncthreads();

    // ---- coalesced store: rows = Y[(bc*64+st)*16 + r(hi)/r+8(lo)], cols = l ----
    #pragma unroll
    for (int it = 0; it < 8; it++) {
        int u = tid + it * 256;
        int st = u >> 5, g = u & 31;
        int ml = g * 4;
        uint32_t p0 = ps[st * 132 + ml + 0];
        uint32_t p1 = ps[st * 132 + ml + 1];
        uint32_t p2 = ps[st * 132 + ml + 2];
        uint32_t p3 = ps[st * 132 + ml + 3];
        uint32_t hi01 = (p0 & 0xffffu) | (p1 << 16);
        uint32_t hi23 = (p2 & 0xffffu) | (p3 << 16);
        uint32_t lo01 = (p0 >> 16) | (p1 & 0xffff0000u);
        uint32_t lo23 = (p2 >> 16) | (p3 & 0xffff0000u);
        int m = m0 + ml;
        int b = m / 160, l = m % 160;   // 4-aligned, never crosses b boundary
        size_t base = ((size_t)((b * 8 + c) * 64 + st) * 16 + r) * 160 + l;
        *(uint2*)&Y[base]            = make_uint2(hi01, hi23);
        *(uint2*)&Y[base + 8 * 160]  = make_uint2(lo01, lo23);
    }
}

// ------------------------------------------------------------------------------
// Tensor-core scores (unchanged from R4).
__global__ void __launch_bounds__(128) scores_tc(
    const __nv_bfloat16* __restrict__ Y1, const __nv_bfloat16* __restrict__ Y0,
    const float* __restrict__ wbo, float* __restrict__ SC)
{
    __shared__ __nv_bfloat16 S1[128*72];
    __shared__ __nv_bfloat16 S0[128*72];
    __shared__ float swb[512];
    const int tid = threadIdx.x;
    const int warp = tid >> 5, lane = tid & 31;
    const int qt = blockIdx.x, kt = blockIdx.y, b = blockIdx.z;
    const int qoff = (warp >> 1) * 16, koff = (warp & 1) * 16;
    for (int i = tid; i < 512; i += 128) swb[i] = wbo[i];

    const uint32_t s1b = smem_u32(S1), s0b = smem_u32(S0);
    const int t4 = lane >> 3, rr = lane & 7;
    const int lrow = ((t4 & 2) ? 8 : 0) + rr;
    const uint32_t aoff = (uint32_t)((lrow * 72 + qoff + (t4 & 1) * 8) * 2);
    const uint32_t boff = (uint32_t)((lrow * 72 + koff + (t4 & 1) * 8) * 2);

    float acc[2][4] = {};
    for (int c = 0; c < 8; c++) {
        float num[2][4] = {}, den[2][4] = {};
        for (int oct = 0; oct < 8; oct++) {
            __syncthreads();
            const int sbase = ((b*8 + c)*64 + oct*8) * 16;
            #pragma unroll
            for (int it = 0; it < 8; it++) {
                int u = tid + it*128;
                int half = u >> 9, v = u & 511;
                int row = v >> 2, ch = v & 3;
                const __nv_bfloat16* src = (half ? Y0 : Y1)
                    + (size_t)(sbase + row) * 160 + (half ? kt : qt) * 32 + ch * 8;
                __nv_bfloat16* dst = (half ? S0 : S1) + row * 72 + ch * 8;
                *(uint4*)dst = *(const uint4*)src;
            }
            __syncthreads();
            #pragma unroll
            for (int st = 0; st < 8; st++) {
                const uint32_t tb = (uint32_t)(st * 2304);
                uint32_t a[4], bv[4];
                ldsm_x4t(a,  s1b + tb + aoff);
                ldsm_x4t(bv, s0b + tb + boff);
                float z0[4], z1[4];
                mma1688_z  (z0, a[0], a[1], bv[0]);
                mma1688_acc(z0, a[0], a[1], bv[2]);
                mma1688_acc(z0, a[2], a[3], bv[0]);
                mma1688_z  (z1, a[0], a[1], bv[1]);
                mma1688_acc(z1, a[0], a[1], bv[3]);
                mma1688_acc(z1, a[2], a[3], bv[1]);
                const float wb = swb[c*64 + oct*8 + st];
                #pragma unroll
                for (int e = 0; e < 4; e++) {
                    {
                        float az = fabsf(z0[e]);
                        den[0][e] += az;
                        float s;
                        asm("sqrt.approx.f32 %0, %1;" : "=f"(s) : "f"(az));
                        uint32_t sb2 = (__float_as_uint(s) & 0x7fffffffu)
                                     | (__float_as_uint(z0[e]) & 0x80000000u);
                        num[0][e] = fmaf(wb, __uint_as_float(sb2), num[0][e]);
                    }
                    {
                        float az = fabsf(z1[e]);
                        den[1][e] += az;
                        float s;
                        asm("sqrt.approx.f32 %0, %1;" : "=f"(s) : "f"(az));
                        uint32_t sb2 = (__float_as_uint(s) & 0x7fffffffu)
                                     | (__float_as_uint(z1[e]) & 0x80000000u);
                        num[1][e] = fmaf(wb, __uint_as_float(sb2), num[1][e]);
                    }
                }
            }
        }
        #pragma unroll
        for (int kf = 0; kf < 2; kf++)
            #pragma unroll
            for (int e = 0; e < 4; e++)
                acc[kf][e] += num[kf][e] * rsqrtf(fmaxf(den[kf][e], 1e-24f));
    }
    const int q = qt*32 + qoff + (lane >> 2);
    const int k = kt*32 + koff + (lane & 3)*2;
    float* p0 = SC + (size_t)(b*160 + q)*160 + k;
    *(float2*)(p0)             = make_float2(acc[0][0], acc[0][1]);
    *(float2*)(p0 + 8)         = make_float2(acc[1][0], acc[1][1]);
    *(float2*)(p0 + 8*160)     = make_float2(acc[0][2], acc[0][3]);
    *(float2*)(p0 + 8*160 + 8) = make_float2(acc[1][2], acc[1][3]);
}

// ------------------------------------------------------------------------------
__global__ void __launch_bounds__(192) softmax_kernel(float* __restrict__ sc)
{
    const int row = blockIdx.x;
    float* p = sc + row*160;
    const int t = threadIdx.x;
    __shared__ float red[6], red2[6];
    float v = (t < 160) ? p[t] : -3.0e38f;
    #pragma unroll
    for (int o = 16; o; o >>= 1) v = fmaxf(v, __shfl_xor_sync(0xffffffffu, v, o));
    if ((t & 31) == 0) red[t >> 5] = v;
    __syncthreads();
    float m = red[0];
    #pragma unroll
    for (int i = 1; i < 6; i++) m = fmaxf(m, red[i]);
    float e = (t < 160) ? expf(p[t] - m) : 0.f;
    float sv = e;
    #pragma unroll
    for (int o = 16; o; o >>= 1) sv += __shfl_xor_sync(0xffffffffu, sv, o);
    if ((t & 31) == 0) red2[t >> 5] = sv;
    __syncthreads();
    float ssum = 0.f;
    #pragma unroll
    for (int i = 0; i < 6; i++) ssum += red2[i];
    if (t < 160) p[t] = e / ssum;
}

// ------------------------------------------------------------------------------
__global__ void __launch_bounds__(256) attv_kernel(
    const float* __restrict__ att, const float* __restrict__ vv,
    float* __restrict__ scr)
{
    __shared__ float As[16][36];
    __shared__ float Ws[16][68];
    const int tid = threadIdx.x;
    const int m0 = blockIdx.x * 32;
    const int n0 = blockIdx.y * 64;
    const int b  = blockIdx.z;
    const float* attb = att + b*160*160;
    const float* vvb  = vv  + b*160*512;
    const int amr = tid >> 3;
    const int akc = (tid & 7) << 1;
    const int wkr = tid >> 4;
    const int wnc = (tid & 15) << 2;
    const int tm = (tid & 15) << 1;
    const int tn = (tid >> 4) << 2;
    float acc[2][4] = {};
    for (int k0 = 0; k0 < 160; k0 += 16) {
        float2 av = *(const float2*)(attb + (m0 + amr)*160 + k0 + akc);
        float4 wv = *(const float4*)(vvb + (k0 + wkr)*512 + n0 + wnc);
        __syncthreads();
        As[akc+0][amr] = av.x; As[akc+1][amr] = av.y;
        *(float4*)&Ws[wkr][wnc] = wv;
        __syncthreads();
        #pragma unroll
        for (int kk = 0; kk < 16; kk++) {
            float a0 = As[kk][tm], a1 = As[kk][tm+1];
            float w[4];
            *(float4*)w = *(const float4*)&Ws[kk][tn];
            #pragma unroll
            for (int j = 0; j < 4; j++) {
                acc[0][j] = fmaf(a0, w[j], acc[0][j]);
                acc[1][j] = fmaf(a1, w[j], acc[1][j]);
            }
        }
    }
    #pragma unroll
    for (int i = 0; i < 2; i++)
        #pragma unroll
        for (int j = 0; j < 4; j++) {
            int q = m0 + tm + i;
            int h = n0 + tn + j;
            scr[b*81920 + h*160 + q] = acc[i][j];
        }
}

// ------------------------------------------------------------------------------
extern "C" void kernel_launch(void* const* d_in, const int* in_sizes, int n_in,
                              void* d_out, int out_size)
{
    (void)in_sizes; (void)n_in; (void)out_size;
    const float* v    = (const float*)d_in[0];
    const float* kin  = (const float*)d_in[1];
    const float* qin  = (const float*)d_in[2];
    const float* w_v  = (const float*)d_in[3];  const float* b_v = (const float*)d_in[4];
    const float* w_k  = (const float*)d_in[5];  const float* b_k = (const float*)d_in[6];
    const float* w_q  = (const float*)d_in[7];  const float* b_q = (const float*)d_in[8];
    const float* w0   = (const float*)d_in[9];  const float* b0  = (const float*)d_in[10];
    const float* w1   = (const float*)d_in[11]; const float* b1  = (const float*)d_in[12];
    const float* wm0  = (const float*)d_in[13]; const float* bm0 = (const float*)d_in[14];
    const float* wm1  = (const float*)d_in[15]; const float* bm1 = (const float*)d_in[16];
    const float* w_bo = (const float*)d_in[17];
    const float* w_m  = (const float*)d_in[19]; const float* b_m = (const float*)d_in[20];
    float* out = (float*)d_out;

    float *vv, *kk, *qq, *x0, *x1, *sc, *scr;
    __nv_bfloat16 *y0, *y1;
    cudaGetSymbolAddress((void**)&vv,  g_vv);
    cudaGetSymbolAddress((void**)&kk,  g_kk);
    cudaGetSymbolAddress((void**)&qq,  g_qq);
    cudaGetSymbolAddress((void**)&x0,  g_x0);
    cudaGetSymbolAddress((void**)&x1,  g_x1);
    cudaGetSymbolAddress((void**)&y0,  g_y0);
    cudaGetSymbolAddress((void**)&y1,  g_y1);
    cudaGetSymbolAddress((void**)&sc,  g_sc);
    cudaGetSymbolAddress((void**)&scr, g_scr);

    static int smem_set = 0;
    if (!smem_set) {
        cudaFuncSetAttribute(hmma_gemm_kernel,
                             cudaFuncAttributeMaxDynamicSharedMemorySize, HM_SMEM_BYTES);
        cudaFuncSetAttribute(merge_tc_kernel,
                             cudaFuncAttributeMaxDynamicSharedMemorySize, HM_SMEM_BYTES);
        smem_set = 1;
    }

    GemmBatch g1;
    g1.A[0] = v;    g1.W[0] = w_v; g1.bias[0] = b_v; g1.C[0] = vv;
    g1.A[1] = kin;  g1.W[1] = w_k; g1.bias[1] = b_k; g1.C[1] = kk;
    g1.A[2] = qin;  g1.W[2] = w_q; g1.bias[2] = b_q; g1.C[2] = qq;
    hmma_gemm_kernel<<<dim3(10, 8, 3), 256, HM_SMEM_BYTES>>>(g1);

    GemmBatch g2;
    g2.A[0] = kk; g2.W[0] = w0; g2.bias[0] = b0; g2.C[0] = x0;
    g2.A[1] = qq; g2.W[1] = w1; g2.bias[1] = b1; g2.C[1] = x1;
    g2.A[2] = kk; g2.W[2] = w0; g2.bias[2] = b0; g2.C[2] = x0;
    hmma_gemm_kernel<<<dim3(10, 8, 2), 256, HM_SMEM_BYTES>>>(g2);

    MergeBatch mrg;
    mrg.X[0] = x0; mrg.WM[0] = wm0; mrg.BM[0] = bm0; mrg.Y[0] = y0;
    mrg.X[1] = x1; mrg.WM[1] = wm1; mrg.BM[1] = bm1; mrg.Y[1] = y1;
    merge_tc_kernel<<<dim3(10, 8, 16), 256, HM_SMEM_BYTES>>>(mrg);

    scores_tc<<<dim3(5, 5, 8), 128>>>(y1, y0, w_bo, sc);
    softmax_kernel<<<1280, 192>>>(sc);
    attv_kernel<<<dim3(5, 8, 8), 256>>>(sc, vv, scr);

    GemmBatch g3;
    g3.A[0] = scr; g3.W[0] = w_m; g3.bias[0] = b_m; g3.C[0] = out;
    g3.A[1] = scr; g3.W[1] = w_m; g3.bias[1] = b_m; g3.C[1] = out;
    g3.A[2] = scr; g3.W[2] = w_m; g3.bias[2] = b_m; g3.C[2] = out;
    hmma_gemm_kernel<<<dim3(10, 8, 1), 256, HM_SMEM_BYTES>>>(g3);
}

// round 6
// speedup vs baseline: 1.9025x; 1.1529x over previous
#include <cuda_runtime.h>
#include <cuda_bf16.h>
#include <cstdint>

// Problem constants (fixed shapes from the reference)
#define NB_B 8
#define NB_L 160
#define NB_H 512
#define NB_C 8
#define NB_S 64
#define NB_R 8
#define NB_BL (NB_B*NB_L)   // 1280
#define SC_PLANE (NB_B*NB_L*NB_L)   // 204800

// ---------------- scratch (device globals: no runtime allocation) -------------
__device__ float g_vv [NB_BL*NB_H];
__device__ float g_kk [NB_BL*NB_H];
__device__ float g_qq [NB_BL*NB_H];
__device__ float g_x0 [NB_BL*NB_H];
__device__ float g_x1 [NB_BL*NB_H];
// Y layout: [b][c][s(64)][r(16: 8 hi | 8 lo)][l(160)] bf16
__device__ __nv_bfloat16 g_y0 [NB_B*NB_C*NB_S*16*NB_L];
__device__ __nv_bfloat16 g_y1 [NB_B*NB_C*NB_S*16*NB_L];
__device__ float g_sc [4*SC_PLANE];     // 4 chunk-group partial planes
__device__ float g_scr[NB_BL*NB_H];

// ======================= mma.sync helpers (sm_80+ path) =======================
__device__ __forceinline__ uint32_t smem_u32(const void* p) {
    uint32_t a;
    asm("{ .reg .u64 t; cvta.to.shared.u64 t, %1; cvt.u32.u64 %0, t; }"
        : "=r"(a) : "l"(p));
    return a;
}
__device__ __forceinline__ void mma16816(float* d, const uint32_t* a, const uint32_t* b) {
    asm volatile(
        "mma.sync.aligned.m16n8k16.row.col.f32.bf16.bf16.f32 "
        "{%0,%1,%2,%3}, {%4,%5,%6,%7}, {%8,%9}, {%0,%1,%2,%3};"
        : "+f"(d[0]), "+f"(d[1]), "+f"(d[2]), "+f"(d[3])
        : "r"(a[0]), "r"(a[1]), "r"(a[2]), "r"(a[3]), "r"(b[0]), "r"(b[1]));
}
__device__ __forceinline__ void ldsm_x4(uint32_t* r, uint32_t addr) {
    asm volatile("ldmatrix.sync.aligned.m8n8.x4.shared.b16 {%0,%1,%2,%3}, [%4];"
        : "=r"(r[0]), "=r"(r[1]), "=r"(r[2]), "=r"(r[3]) : "r"(addr));
}
__device__ __forceinline__ void ldsm_x4t(uint32_t* r, uint32_t addr) {
    asm volatile("ldmatrix.sync.aligned.m8n8.x4.trans.shared.b16 {%0,%1,%2,%3}, [%4];"
        : "=r"(r[0]), "=r"(r[1]), "=r"(r[2]), "=r"(r[3]) : "r"(addr));
}
__device__ __forceinline__ void mma1688_z(float* d, uint32_t a0, uint32_t a1, uint32_t b) {
    asm volatile(
        "mma.sync.aligned.m16n8k8.row.col.f32.bf16.bf16.f32 "
        "{%0,%1,%2,%3}, {%4,%5}, {%6}, {%7,%8,%9,%10};"
        : "=f"(d[0]), "=f"(d[1]), "=f"(d[2]), "=f"(d[3])
        : "r"(a0), "r"(a1), "r"(b), "f"(0.f), "f"(0.f), "f"(0.f), "f"(0.f));
}
__device__ __forceinline__ void mma1688_acc(float* d, uint32_t a0, uint32_t a1, uint32_t b) {
    asm volatile(
        "mma.sync.aligned.m16n8k8.row.col.f32.bf16.bf16.f32 "
        "{%0,%1,%2,%3}, {%4,%5}, {%6}, {%0,%1,%2,%3};"
        : "+f"(d[0]), "+f"(d[1]), "+f"(d[2]), "+f"(d[3])
        : "r"(a0), "r"(a1), "r"(b));
}
// fp32 -> bf16 hi/lo split of a float4, stored to hi/lo SMEM planes
__device__ __forceinline__ void split_store(__nv_bfloat16* smh, __nv_bfloat16* sml,
                                            int off, float4 v) {
    __nv_bfloat162 h01 = __floats2bfloat162_rn(v.x, v.y);
    __nv_bfloat162 h23 = __floats2bfloat162_rn(v.z, v.w);
    float2 f01 = __bfloat1622float2(h01);
    float2 f23 = __bfloat1622float2(h23);
    __nv_bfloat162 l01 = __floats2bfloat162_rn(v.x - f01.x, v.y - f01.y);
    __nv_bfloat162 l23 = __floats2bfloat162_rn(v.z - f23.x, v.w - f23.y);
    *(uint2*)&smh[off] = make_uint2(*(uint32_t*)&h01, *(uint32_t*)&h23);
    *(uint2*)&sml[off] = make_uint2(*(uint32_t*)&l01, *(uint32_t*)&l23);
}

// ================= bf16-split tensor-core GEMM: C = A @ W^T + bias ===========
struct GemmBatch {
    const float* A[3]; const float* W[3]; const float* bias[3]; float* C[3];
};

#define LDA_S 72
#define OFF_AH 0
#define OFF_AL (128*LDA_S)
#define OFF_WH (256*LDA_S)
#define OFF_WL (320*LDA_S)
#define HM_SMEM_BYTES (384*LDA_S*2)   // 55296

__global__ void __launch_bounds__(256) hmma_gemm_kernel(GemmBatch gb)
{
    extern __shared__ __nv_bfloat16 sm[];
    const int tid  = threadIdx.x;
    const int wid  = tid >> 5, lane = tid & 31;
    const int z = blockIdx.z;
    const float* A    = gb.A[z];
    const float* W    = gb.W[z];
    const float* bias = gb.bias[z];
    float*       C    = gb.C[z];
    const int m0 = blockIdx.x * 128;
    const int n0 = blockIdx.y * 64;
    const int wm = wid & 3, wn = wid >> 2;
    const uint32_t sb = smem_u32(sm);

    float acc[2][4][4] = {};

    const int a_row = wm * 32 + (lane & 15);
    const uint32_t a_addr0 = sb + (uint32_t)((OFF_AH + a_row * LDA_S + (lane >> 4) * 8) * 2);
    const int b_row = wn * 32 + ((lane >> 4) & 1) * 8 + (lane & 7);
    const uint32_t b_addr0 = sb + (uint32_t)((OFF_WH + b_row * LDA_S + ((lane >> 3) & 1) * 8) * 2);
    const uint32_t ALO_B = (uint32_t)((OFF_AL - OFF_AH) * 2);
    const uint32_t WLO_B = (uint32_t)((OFF_WL - OFF_WH) * 2);

    for (int kc = 0; kc < 8; kc++) {
        const int kbase = kc * 64;
        __syncthreads();
        #pragma unroll
        for (int it = 0; it < 8; it++) {
            int u = tid + it * 256;
            int row = u >> 4, kg = (u & 15) << 2;
            float4 v = *(const float4*)(A + (m0 + row) * 512 + kbase + kg);
            split_store(sm + OFF_AH, sm + OFF_AL, row * LDA_S + kg, v);
        }
        #pragma unroll
        for (int it = 0; it < 4; it++) {
            int u = tid + it * 256;
            int row = u >> 4, kg = (u & 15) << 2;
            float4 v = *(const float4*)(W + (n0 + row) * 512 + kbase + kg);
            split_store(sm + OFF_WH, sm + OFF_WL, row * LDA_S + kg, v);
        }
        __syncthreads();

        #pragma unroll
        for (int k16 = 0; k16 < 4; k16++) {
            const uint32_t kb = (uint32_t)(k16 * 32);
            uint32_t ah[2][4], al[2][4];
            ldsm_x4(ah[0], a_addr0 + kb);
            ldsm_x4(ah[1], a_addr0 + (uint32_t)(16 * LDA_S * 2) + kb);
            ldsm_x4(al[0], a_addr0 + ALO_B + kb);
            ldsm_x4(al[1], a_addr0 + ALO_B + (uint32_t)(16 * LDA_S * 2) + kb);
            uint32_t bh[2][4], bl[2][4];
            ldsm_x4(bh[0], b_addr0 + kb);
            ldsm_x4(bh[1], b_addr0 + (uint32_t)(16 * LDA_S * 2) + kb);
            ldsm_x4(bl[0], b_addr0 + WLO_B + kb);
            ldsm_x4(bl[1], b_addr0 + WLO_B + (uint32_t)(16 * LDA_S * 2) + kb);
            #pragma unroll
            for (int mi = 0; mi < 2; mi++) {
                #pragma unroll
                for (int nj = 0; nj < 4; nj++) {
                    const uint32_t* bph = &bh[nj >> 1][(nj & 1) * 2];
                    const uint32_t* bpl = &bl[nj >> 1][(nj & 1) * 2];
                    mma16816(acc[mi][nj], ah[mi], bph);
                    mma16816(acc[mi][nj], ah[mi], bpl);
                    mma16816(acc[mi][nj], al[mi], bph);
                }
            }
        }
    }

    const int mrow = m0 + wm * 32 + (lane >> 2);
    const int ncol = n0 + wn * 32 + (lane & 3) * 2;
    #pragma unroll
    for (int mi = 0; mi < 2; mi++) {
        #pragma unroll
        for (int nj = 0; nj < 4; nj++) {
            int n = ncol + nj * 8;
            float b0 = bias[n], b1 = bias[n + 1];
            int m_a = mrow + mi * 16;
            *(float2*)&C[m_a * 512 + n]       = make_float2(acc[mi][nj][0] + b0, acc[mi][nj][1] + b1);
            *(float2*)&C[(m_a + 8) * 512 + n] = make_float2(acc[mi][nj][2] + b0, acc[mi][nj][3] + b1);
        }
    }
}

// ------------------------------------------------------------------------------
// Tensor-core merge projection + transpose (unchanged from R5).
struct MergeBatch {
    const float* X[2]; const float* WM[2]; const float* BM[2]; __nv_bfloat16* Y[2];
};

__global__ void __launch_bounds__(256) merge_tc_kernel(MergeBatch mb)
{
    extern __shared__ __nv_bfloat16 sm[];
    const int tid  = threadIdx.x;
    const int wid  = tid >> 5, lane = tid & 31;
    const int zz = blockIdx.z;
    const int tensor = zz >> 3, c = zz & 7;
    const float* X  = mb.X[tensor];
    const float* WM = mb.WM[tensor];
    const float* BM = mb.BM[tensor];
    __nv_bfloat16* Y = mb.Y[tensor];
    const int m0 = blockIdx.x * 128;
    const int r  = blockIdx.y;
    const int n0 = r * 64;
    const int wm = wid & 3, wn = wid >> 2;
    const uint32_t sb = smem_u32(sm);

    #pragma unroll
    for (int it = 0; it < 8; it++) {
        int u = tid + it * 256;
        int row = u >> 4, kg = (u & 15) << 2;
        float4 v = *(const float4*)(X + (m0 + row) * 512 + c * 64 + kg);
        split_store(sm + OFF_AH, sm + OFF_AL, row * LDA_S + kg, v);
    }
    #pragma unroll
    for (int it = 0; it < 4; it++) {
        int u = tid + it * 256;
        int row = u >> 4, kg = (u & 15) << 2;
        float4 v = *(const float4*)(WM + (size_t)(c * 512 + n0 + row) * 64 + kg);
        split_store(sm + OFF_WH, sm + OFF_WL, row * LDA_S + kg, v);
    }
    __syncthreads();

    const int a_row = wm * 32 + (lane & 15);
    const uint32_t a_addr0 = sb + (uint32_t)((OFF_AH + a_row * LDA_S + (lane >> 4) * 8) * 2);
    const int b_row = wn * 32 + ((lane >> 4) & 1) * 8 + (lane & 7);
    const uint32_t b_addr0 = sb + (uint32_t)((OFF_WH + b_row * LDA_S + ((lane >> 3) & 1) * 8) * 2);
    const uint32_t ALO_B = (uint32_t)((OFF_AL - OFF_AH) * 2);
    const uint32_t WLO_B = (uint32_t)((OFF_WL - OFF_WH) * 2);

    float acc[2][4][4] = {};
    #pragma unroll
    for (int k16 = 0; k16 < 4; k16++) {
        const uint32_t kb = (uint32_t)(k16 * 32);
        uint32_t ah[2][4], al[2][4];
        ldsm_x4(ah[0], a_addr0 + kb);
        ldsm_x4(ah[1], a_addr0 + (uint32_t)(16 * LDA_S * 2) + kb);
        ldsm_x4(al[0], a_addr0 + ALO_B + kb);
        ldsm_x4(al[1], a_addr0 + ALO_B + (uint32_t)(16 * LDA_S * 2) + kb);
        uint32_t bh[2][4], bl[2][4];
        ldsm_x4(bh[0], b_addr0 + kb);
        ldsm_x4(bh[1], b_addr0 + (uint32_t)(16 * LDA_S * 2) + kb);
        ldsm_x4(bl[0], b_addr0 + WLO_B + kb);
        ldsm_x4(bl[1], b_addr0 + WLO_B + (uint32_t)(16 * LDA_S * 2) + kb);
        #pragma unroll
        for (int mi = 0; mi < 2; mi++) {
            #pragma unroll
            for (int nj = 0; nj < 4; nj++) {
                const uint32_t* bph = &bh[nj >> 1][(nj & 1) * 2];
                const uint32_t* bpl = &bl[nj >> 1][(nj & 1) * 2];
                mma16816(acc[mi][nj], ah[mi], bph);
                mma16816(acc[mi][nj], ah[mi], bpl);
                mma16816(acc[mi][nj], al[mi], bph);
            }
        }
    }

    __syncthreads();
    uint32_t* ps = (uint32_t*)sm;
    const int mbase = wm * 32 + (lane >> 2);
    const int tbase = wn * 32 + (lane & 3) * 2;
    #pragma unroll
    for (int mi = 0; mi < 2; mi++) {
        #pragma unroll
        for (int nj = 0; nj < 4; nj++) {
            int tt = tbase + nj * 8;
            float bb0 = BM[c * 512 + n0 + tt];
            float bb1 = BM[c * 512 + n0 + tt + 1];
            #pragma unroll
            for (int e = 0; e < 4; e++) {
                int mm = mbase + mi * 16 + ((e >> 1) ? 8 : 0);
                int tc2 = tt + (e & 1);
                float v = acc[mi][nj][e] + ((e & 1) ? bb1 : bb0);
                __nv_bfloat16 hi = __float2bfloat16(v);
                __nv_bfloat16 lo = __float2bfloat16(v - __bfloat162float(hi));
                ps[tc2 * 132 + mm] = (uint32_t)*(uint16_t*)&hi
                                   | ((uint32_t)*(uint16_t*)&lo << 16);
            }
        }
    }
    __syncthreads();

    #pragma unroll
    for (int it = 0; it < 8; it++) {
        int u = tid + it * 256;
        int st = u >> 5, g = u & 31;
        int ml = g * 4;
        uint32_t p0 = ps[st * 132 + ml + 0];
        uint32_t p1 = ps[st * 132 + ml + 1];
        uint32_t p2 = ps[st * 132 + ml + 2];
        uint32_t p3 = ps[st * 132 + ml + 3];
        uint32_t hi01 = (p0 & 0xffffu) | (p1 << 16);
        uint32_t hi23 = (p2 & 0xffffu) | (p3 << 16);
        uint32_t lo01 = (p0 >> 16) | (p1 & 0xffff0000u);
        uint32_t lo23 = (p2 >> 16) | (p3 & 0xffff0000u);
        int m = m0 + ml;
        int b = m / 160, l = m % 160;
        size_t base = ((size_t)((b * 8 + c) * 64 + st) * 16 + r) * 160 + l;
        *(uint2*)&Y[base]            = make_uint2(hi01, hi23);
        *(uint2*)&Y[base + 8 * 160]  = make_uint2(lo01, lo23);
    }
}

// ------------------------------------------------------------------------------
// Tensor-core scores, chunk-split over grid: blockIdx.z = b*4 + cg,
// each CTA handles chunks {2cg, 2cg+1}, writes partial plane SC + cg*SC_PLANE.
__global__ void __launch_bounds__(128) scores_tc(
    const __nv_bfloat16* __restrict__ Y1, const __nv_bfloat16* __restrict__ Y0,
    const float* __restrict__ wbo, float* __restrict__ SC)
{
    __shared__ __nv_bfloat16 S1[128*72];
    __shared__ __nv_bfloat16 S0[128*72];
    __shared__ float swb[128];
    const int tid = threadIdx.x;
    const int warp = tid >> 5, lane = tid & 31;
    const int qt = blockIdx.x, kt = blockIdx.y;
    const int b = blockIdx.z >> 2, cg = blockIdx.z & 3;
    const int c0 = cg * 2;
    const int qoff = (warp >> 1) * 16, koff = (warp & 1) * 16;
    if (tid < 128) swb[tid] = wbo[c0 * 64 + tid];

    const uint32_t s1b = smem_u32(S1), s0b = smem_u32(S0);
    const int t4 = lane >> 3, rr = lane & 7;
    const int lrow = ((t4 & 2) ? 8 : 0) + rr;
    const uint32_t aoff = (uint32_t)((lrow * 72 + qoff + (t4 & 1) * 8) * 2);
    const uint32_t boff = (uint32_t)((lrow * 72 + koff + (t4 & 1) * 8) * 2);

    float acc[2][4] = {};
    for (int ci = 0; ci < 2; ci++) {
        const int c = c0 + ci;
        float num[2][4] = {}, den[2][4] = {};
        for (int oct = 0; oct < 8; oct++) {
            __syncthreads();
            const int sbase = ((b*8 + c)*64 + oct*8) * 16;
            #pragma unroll
            for (int it = 0; it < 8; it++) {
                int u = tid + it*128;
                int half = u >> 9, v = u & 511;
                int row = v >> 2, ch = v & 3;
                const __nv_bfloat16* src = (half ? Y0 : Y1)
                    + (size_t)(sbase + row) * 160 + (half ? kt : qt) * 32 + ch * 8;
                __nv_bfloat16* dst = (half ? S0 : S1) + row * 72 + ch * 8;
                *(uint4*)dst = *(const uint4*)src;
            }
            __syncthreads();
            #pragma unroll
            for (int st = 0; st < 8; st++) {
                const uint32_t tb = (uint32_t)(st * 2304);
                uint32_t a[4], bv[4];
                ldsm_x4t(a,  s1b + tb + aoff);
                ldsm_x4t(bv, s0b + tb + boff);
                float z0[4], z1[4];
                mma1688_z  (z0, a[0], a[1], bv[0]);
                mma1688_acc(z0, a[0], a[1], bv[2]);
                mma1688_acc(z0, a[2], a[3], bv[0]);
                mma1688_z  (z1, a[0], a[1], bv[1]);
                mma1688_acc(z1, a[0], a[1], bv[3]);
                mma1688_acc(z1, a[2], a[3], bv[1]);
                const float wb = swb[ci*64 + oct*8 + st];
                #pragma unroll
                for (int e = 0; e < 4; e++) {
                    {
                        float az = fabsf(z0[e]);
                        den[0][e] += az;
                        float s;
                        asm("sqrt.approx.f32 %0, %1;" : "=f"(s) : "f"(az));
                        uint32_t sb2 = (__float_as_uint(s) & 0x7fffffffu)
                                     | (__float_as_uint(z0[e]) & 0x80000000u);
                        num[0][e] = fmaf(wb, __uint_as_float(sb2), num[0][e]);
                    }
                    {
                        float az = fabsf(z1[e]);
                        den[1][e] += az;
                        float s;
                        asm("sqrt.approx.f32 %0, %1;" : "=f"(s) : "f"(az));
                        uint32_t sb2 = (__float_as_uint(s) & 0x7fffffffu)
                                     | (__float_as_uint(z1[e]) & 0x80000000u);
                        num[1][e] = fmaf(wb, __uint_as_float(sb2), num[1][e]);
                    }
                }
            }
        }
        #pragma unroll
        for (int kf = 0; kf < 2; kf++)
            #pragma unroll
            for (int e = 0; e < 4; e++)
                acc[kf][e] += num[kf][e] * rsqrtf(fmaxf(den[kf][e], 1e-24f));
    }
    const int q = qt*32 + qoff + (lane >> 2);
    const int k = kt*32 + koff + (lane & 3)*2;
    float* p0 = SC + (size_t)cg * SC_PLANE + (size_t)(b*160 + q)*160 + k;
    *(float2*)(p0)             = make_float2(acc[0][0], acc[0][1]);
    *(float2*)(p0 + 8)         = make_float2(acc[1][0], acc[1][1]);
    *(float2*)(p0 + 8*160)     = make_float2(acc[0][2], acc[0][3]);
    *(float2*)(p0 + 8*160 + 8) = make_float2(acc[1][2], acc[1][3]);
}

// ------------------------------------------------------------------------------
// Row softmax summing the 4 partial planes; result written to plane 0.
__global__ void __launch_bounds__(192) softmax_kernel(float* __restrict__ sc)
{
    const int row = blockIdx.x;
    float* p = sc + (size_t)row*160;
    const int t = threadIdx.x;
    __shared__ float red[6], red2[6];
    float x = -3.0e38f;
    if (t < 160) {
        x = p[t] + p[SC_PLANE + t] + p[2*SC_PLANE + t] + p[3*SC_PLANE + t];
    }
    float v = x;
    #pragma unroll
    for (int o = 16; o; o >>= 1) v = fmaxf(v, __shfl_xor_sync(0xffffffffu, v, o));
    if ((t & 31) == 0) red[t >> 5] = v;
    __syncthreads();
    float m = red[0];
    #pragma unroll
    for (int i = 1; i < 6; i++) m = fmaxf(m, red[i]);
    float e = (t < 160) ? expf(x - m) : 0.f;
    float sv = e;
    #pragma unroll
    for (int o = 16; o; o >>= 1) sv += __shfl_xor_sync(0xffffffffu, sv, o);
    if ((t & 31) == 0) red2[t >> 5] = sv;
    __syncthreads();
    float ssum = 0.f;
    #pragma unroll
    for (int i = 0; i < 6; i++) ssum += red2[i];
    if (t < 160) p[t] = e / ssum;
}

// ------------------------------------------------------------------------------
__global__ void __launch_bounds__(256) attv_kernel(
    const float* __restrict__ att, const float* __restrict__ vv,
    float* __restrict__ scr)
{
    __shared__ float As[16][36];
    __shared__ float Ws[16][68];
    const int tid = threadIdx.x;
    const int m0 = blockIdx.x * 32;
    const int n0 = blockIdx.y * 64;
    const int b  = blockIdx.z;
    const float* attb = att + b*160*160;
    const float* vvb  = vv  + b*160*512;
    const int amr = tid >> 3;
    const int akc = (tid & 7) << 1;
    const int wkr = tid >> 4;
    const int wnc = (tid & 15) << 2;
    const int tm = (tid & 15) << 1;
    const int tn = (tid >> 4) << 2;
    float acc[2][4] = {};
    for (int k0 = 0; k0 < 160; k0 += 16) {
        float2 av = *(const float2*)(attb + (m0 + amr)*160 + k0 + akc);
        float4 wv = *(const float4*)(vvb + (k0 + wkr)*512 + n0 + wnc);
        __syncthreads();
        As[akc+0][amr] = av.x; As[akc+1][amr] = av.y;
        *(float4*)&Ws[wkr][wnc] = wv;
        __syncthreads();
        #pragma unroll
        for (int kk = 0; kk < 16; kk++) {
            float a0 = As[kk][tm], a1 = As[kk][tm+1];
            float w[4];
            *(float4*)w = *(const float4*)&Ws[kk][tn];
            #pragma unroll
            for (int j = 0; j < 4; j++) {
                acc[0][j] = fmaf(a0, w[j], acc[0][j]);
                acc[1][j] = fmaf(a1, w[j], acc[1][j]);
            }
        }
    }
    #pragma unroll
    for (int i = 0; i < 2; i++)
        #pragma unroll
        for (int j = 0; j < 4; j++) {
            int q = m0 + tm + i;
            int h = n0 + tn + j;
            scr[b*81920 + h*160 + q] = acc[i][j];
        }
}

// ------------------------------------------------------------------------------
extern "C" void kernel_launch(void* const* d_in, const int* in_sizes, int n_in,
                              void* d_out, int out_size)
{
    (void)in_sizes; (void)n_in; (void)out_size;
    const float* v    = (const float*)d_in[0];
    const float* kin  = (const float*)d_in[1];
    const float* qin  = (const float*)d_in[2];
    const float* w_v  = (const float*)d_in[3];  const float* b_v = (const float*)d_in[4];
    const float* w_k  = (const float*)d_in[5];  const float* b_k = (const float*)d_in[6];
    const float* w_q  = (const float*)d_in[7];  const float* b_q = (const float*)d_in[8];
    const float* w0   = (const float*)d_in[9];  const float* b0  = (const float*)d_in[10];
    const float* w1   = (const float*)d_in[11]; const float* b1  = (const float*)d_in[12];
    const float* wm0  = (const float*)d_in[13]; const float* bm0 = (const float*)d_in[14];
    const float* wm1  = (const float*)d_in[15]; const float* bm1 = (const float*)d_in[16];
    const float* w_bo = (const float*)d_in[17];
    const float* w_m  = (const float*)d_in[19]; const float* b_m = (const float*)d_in[20];
    float* out = (float*)d_out;

    float *vv, *kk, *qq, *x0, *x1, *sc, *scr;
    __nv_bfloat16 *y0, *y1;
    cudaGetSymbolAddress((void**)&vv,  g_vv);
    cudaGetSymbolAddress((void**)&kk,  g_kk);
    cudaGetSymbolAddress((void**)&qq,  g_qq);
    cudaGetSymbolAddress((void**)&x0,  g_x0);
    cudaGetSymbolAddress((void**)&x1,  g_x1);
    cudaGetSymbolAddress((void**)&y0,  g_y0);
    cudaGetSymbolAddress((void**)&y1,  g_y1);
    cudaGetSymbolAddress((void**)&sc,  g_sc);
    cudaGetSymbolAddress((void**)&scr, g_scr);

    static int smem_set = 0;
    if (!smem_set) {
        cudaFuncSetAttribute(hmma_gemm_kernel,
                             cudaFuncAttributeMaxDynamicSharedMemorySize, HM_SMEM_BYTES);
        cudaFuncSetAttribute(merge_tc_kernel,
                             cudaFuncAttributeMaxDynamicSharedMemorySize, HM_SMEM_BYTES);
        smem_set = 1;
    }

    GemmBatch g1;
    g1.A[0] = v;    g1.W[0] = w_v; g1.bias[0] = b_v; g1.C[0] = vv;
    g1.A[1] = kin;  g1.W[1] = w_k; g1.bias[1] = b_k; g1.C[1] = kk;
    g1.A[2] = qin;  g1.W[2] = w_q; g1.bias[2] = b_q; g1.C[2] = qq;
    hmma_gemm_kernel<<<dim3(10, 8, 3), 256, HM_SMEM_BYTES>>>(g1);

    GemmBatch g2;
    g2.A[0] = kk; g2.W[0] = w0; g2.bias[0] = b0; g2.C[0] = x0;
    g2.A[1] = qq; g2.W[1] = w1; g2.bias[1] = b1; g2.C[1] = x1;
    g2.A[2] = kk; g2.W[2] = w0; g2.bias[2] = b0; g2.C[2] = x0;
    hmma_gemm_kernel<<<dim3(10, 8, 2), 256, HM_SMEM_BYTES>>>(g2);

    MergeBatch mrg;
    mrg.X[0] = x0; mrg.WM[0] = wm0; mrg.BM[0] = bm0; mrg.Y[0] = y0;
    mrg.X[1] = x1; mrg.WM[1] = wm1; mrg.BM[1] = bm1; mrg.Y[1] = y1;
    merge_tc_kernel<<<dim3(10, 8, 16), 256, HM_SMEM_BYTES>>>(mrg);

    scores_tc<<<dim3(5, 5, 32), 128>>>(y1, y0, w_bo, sc);
    softmax_kernel<<<1280, 192>>>(sc);
    attv_kernel<<<dim3(5, 8, 8), 256>>>(sc, vv, scr);

    GemmBatch g3;
    g3.A[0] = scr; g3.W[0] = w_m; g3.bias[0] = b_m; g3.C[0] = out;
    g3.A[1] = scr; g3.W[1] = w_m; g3.bias[1] = b_m; g3.C[1] = out;
    g3.A[2] = scr; g3.W[2] = w_m; g3.bias[2] = b_m; g3.C[2] = out;
    hmma_gemm_kernel<<<dim3(10, 8, 1), 256, HM_SMEM_BYTES>>>(g3);
}

// round 7
// speedup vs baseline: 2.1039x; 1.1058x over previous
#include <cuda_runtime.h>
#include <cuda_bf16.h>
#include <cstdint>

// Problem constants (fixed shapes from the reference)
#define NB_B 8
#define NB_L 160
#define NB_H 512
#define NB_C 8
#define NB_S 64
#define NB_R 8
#define NB_BL (NB_B*NB_L)   // 1280
#define SC_PLANE (NB_B*NB_L*NB_L)   // 204800

// ---------------- scratch (device globals: no runtime allocation) -------------
__device__ float g_vv [NB_BL*NB_H];
__device__ float g_w0k[NB_H*NB_H];     // composed weight w0 @ w_k
__device__ float g_w1q[NB_H*NB_H];     // composed weight w1 @ w_q
__device__ float g_bc [2*NB_H];        // composed biases
__device__ float g_x0 [NB_BL*NB_H];
__device__ float g_x1 [NB_BL*NB_H];
// Y layout: [b][c][s(64)][r(16: 8 hi | 8 lo)][l(160)] bf16
__device__ __nv_bfloat16 g_y0 [NB_B*NB_C*NB_S*16*NB_L];
__device__ __nv_bfloat16 g_y1 [NB_B*NB_C*NB_S*16*NB_L];
__device__ float g_sc [4*SC_PLANE];    // 4 chunk-group partial planes
__device__ float g_scr[NB_BL*NB_H];

// ======================= mma.sync helpers (sm_80+ path) =======================
__device__ __forceinline__ uint32_t smem_u32(const void* p) {
    uint32_t a;
    asm("{ .reg .u64 t; cvta.to.shared.u64 t, %1; cvt.u32.u64 %0, t; }"
        : "=r"(a) : "l"(p));
    return a;
}
__device__ __forceinline__ void mma16816(float* d, const uint32_t* a, const uint32_t* b) {
    asm volatile(
        "mma.sync.aligned.m16n8k16.row.col.f32.bf16.bf16.f32 "
        "{%0,%1,%2,%3}, {%4,%5,%6,%7}, {%8,%9}, {%0,%1,%2,%3};"
        : "+f"(d[0]), "+f"(d[1]), "+f"(d[2]), "+f"(d[3])
        : "r"(a[0]), "r"(a[1]), "r"(a[2]), "r"(a[3]), "r"(b[0]), "r"(b[1]));
}
__device__ __forceinline__ void ldsm_x4(uint32_t* r, uint32_t addr) {
    asm volatile("ldmatrix.sync.aligned.m8n8.x4.shared.b16 {%0,%1,%2,%3}, [%4];"
        : "=r"(r[0]), "=r"(r[1]), "=r"(r[2]), "=r"(r[3]) : "r"(addr));
}
__device__ __forceinline__ void ldsm_x4t(uint32_t* r, uint32_t addr) {
    asm volatile("ldmatrix.sync.aligned.m8n8.x4.trans.shared.b16 {%0,%1,%2,%3}, [%4];"
        : "=r"(r[0]), "=r"(r[1]), "=r"(r[2]), "=r"(r[3]) : "r"(addr));
}
__device__ __forceinline__ void mma1688_z(float* d, uint32_t a0, uint32_t a1, uint32_t b) {
    asm volatile(
        "mma.sync.aligned.m16n8k8.row.col.f32.bf16.bf16.f32 "
        "{%0,%1,%2,%3}, {%4,%5}, {%6}, {%7,%8,%9,%10};"
        : "=f"(d[0]), "=f"(d[1]), "=f"(d[2]), "=f"(d[3])
        : "r"(a0), "r"(a1), "r"(b), "f"(0.f), "f"(0.f), "f"(0.f), "f"(0.f));
}
__device__ __forceinline__ void mma1688_acc(float* d, uint32_t a0, uint32_t a1, uint32_t b) {
    asm volatile(
        "mma.sync.aligned.m16n8k8.row.col.f32.bf16.bf16.f32 "
        "{%0,%1,%2,%3}, {%4,%5}, {%6}, {%0,%1,%2,%3};"
        : "+f"(d[0]), "+f"(d[1]), "+f"(d[2]), "+f"(d[3])
        : "r"(a0), "r"(a1), "r"(b));
}
__device__ __forceinline__ void split_store(__nv_bfloat16* smh, __nv_bfloat16* sml,
                                            int off, float4 v) {
    __nv_bfloat162 h01 = __floats2bfloat162_rn(v.x, v.y);
    __nv_bfloat162 h23 = __floats2bfloat162_rn(v.z, v.w);
    float2 f01 = __bfloat1622float2(h01);
    float2 f23 = __bfloat1622float2(h23);
    __nv_bfloat162 l01 = __floats2bfloat162_rn(v.x - f01.x, v.y - f01.y);
    __nv_bfloat162 l23 = __floats2bfloat162_rn(v.z - f23.x, v.w - f23.y);
    *(uint2*)&smh[off] = make_uint2(*(uint32_t*)&h01, *(uint32_t*)&h23);
    *(uint2*)&sml[off] = make_uint2(*(uint32_t*)&l01, *(uint32_t*)&l23);
}

// ================= bf16-split tensor-core GEMM: C = A @ W^T + bias ===========
struct GemmBatch {
    const float* A[3]; const float* W[3]; const float* bias[3]; float* C[3];
};

#define LDA_S 72
#define OFF_AH 0
#define OFF_AL (128*LDA_S)
#define OFF_WH (256*LDA_S)
#define OFF_WL (320*LDA_S)
#define HM_SMEM_BYTES (384*LDA_S*2)   // 55296

__global__ void __launch_bounds__(256) hmma_gemm_kernel(GemmBatch gb)
{
    extern __shared__ __nv_bfloat16 sm[];
    const int tid  = threadIdx.x;
    const int wid  = tid >> 5, lane = tid & 31;
    const int z = blockIdx.z;
    const float* A    = gb.A[z];
    const float* W    = gb.W[z];
    const float* bias = gb.bias[z];
    float*       C    = gb.C[z];
    const int m0 = blockIdx.x * 128;
    const int n0 = blockIdx.y * 64;
    const int wm = wid & 3, wn = wid >> 2;
    const uint32_t sb = smem_u32(sm);

    float acc[2][4][4] = {};

    const int a_row = wm * 32 + (lane & 15);
    const uint32_t a_addr0 = sb + (uint32_t)((OFF_AH + a_row * LDA_S + (lane >> 4) * 8) * 2);
    const int b_row = wn * 32 + ((lane >> 4) & 1) * 8 + (lane & 7);
    const uint32_t b_addr0 = sb + (uint32_t)((OFF_WH + b_row * LDA_S + ((lane >> 3) & 1) * 8) * 2);
    const uint32_t ALO_B = (uint32_t)((OFF_AL - OFF_AH) * 2);
    const uint32_t WLO_B = (uint32_t)((OFF_WL - OFF_WH) * 2);

    for (int kc = 0; kc < 8; kc++) {
        const int kbase = kc * 64;
        __syncthreads();
        #pragma unroll
        for (int it = 0; it < 8; it++) {
            int u = tid + it * 256;
            int row = u >> 4, kg = (u & 15) << 2;
            float4 v = *(const float4*)(A + (m0 + row) * 512 + kbase + kg);
            split_store(sm + OFF_AH, sm + OFF_AL, row * LDA_S + kg, v);
        }
        #pragma unroll
        for (int it = 0; it < 4; it++) {
            int u = tid + it * 256;
            int row = u >> 4, kg = (u & 15) << 2;
            float4 v = *(const float4*)(W + (n0 + row) * 512 + kbase + kg);
            split_store(sm + OFF_WH, sm + OFF_WL, row * LDA_S + kg, v);
        }
        __syncthreads();

        #pragma unroll
        for (int k16 = 0; k16 < 4; k16++) {
            const uint32_t kb = (uint32_t)(k16 * 32);
            uint32_t ah[2][4], al[2][4];
            ldsm_x4(ah[0], a_addr0 + kb);
            ldsm_x4(ah[1], a_addr0 + (uint32_t)(16 * LDA_S * 2) + kb);
            ldsm_x4(al[0], a_addr0 + ALO_B + kb);
            ldsm_x4(al[1], a_addr0 + ALO_B + (uint32_t)(16 * LDA_S * 2) + kb);
            uint32_t bh[2][4], bl[2][4];
            ldsm_x4(bh[0], b_addr0 + kb);
            ldsm_x4(bh[1], b_addr0 + (uint32_t)(16 * LDA_S * 2) + kb);
            ldsm_x4(bl[0], b_addr0 + WLO_B + kb);
            ldsm_x4(bl[1], b_addr0 + WLO_B + (uint32_t)(16 * LDA_S * 2) + kb);
            #pragma unroll
            for (int mi = 0; mi < 2; mi++) {
                #pragma unroll
                for (int nj = 0; nj < 4; nj++) {
                    const uint32_t* bph = &bh[nj >> 1][(nj & 1) * 2];
                    const uint32_t* bpl = &bl[nj >> 1][(nj & 1) * 2];
                    mma16816(acc[mi][nj], ah[mi], bph);
                    mma16816(acc[mi][nj], ah[mi], bpl);
                    mma16816(acc[mi][nj], al[mi], bph);
                }
            }
        }
    }

    const int mrow = m0 + wm * 32 + (lane >> 2);
    const int ncol = n0 + wn * 32 + (lane & 3) * 2;
    #pragma unroll
    for (int mi = 0; mi < 2; mi++) {
        #pragma unroll
        for (int nj = 0; nj < 4; nj++) {
            int n = ncol + nj * 8;
            float b0 = bias[n], b1 = bias[n + 1];
            int m_a = mrow + mi * 16;
            *(float2*)&C[m_a * 512 + n]       = make_float2(acc[mi][nj][0] + b0, acc[mi][nj][1] + b1);
            *(float2*)&C[(m_a + 8) * 512 + n] = make_float2(acc[mi][nj][2] + b0, acc[mi][nj][3] + b1);
        }
    }
}

// ------------------------------------------------------------------------------
// Weight composition (NN GEMM): C[i,j] = sum_h A[i,h] * B[h,j].
// M=N=K=512, two instances (w0k = w0@w_k, w1q = w1@w_q). B loaded via trans.
__global__ void __launch_bounds__(256) prep_hmma_kernel(
    const float* __restrict__ A0, const float* __restrict__ B0, float* __restrict__ C0,
    const float* __restrict__ A1, const float* __restrict__ B1, float* __restrict__ C1)
{
    extern __shared__ __nv_bfloat16 sm[];
    const int tid  = threadIdx.x;
    const int wid  = tid >> 5, lane = tid & 31;
    const float* A = blockIdx.z ? A1 : A0;
    const float* B = blockIdx.z ? B1 : B0;
    float*       C = blockIdx.z ? C1 : C0;
    const int m0 = blockIdx.x * 128;
    const int n0 = blockIdx.y * 64;
    const int wm = wid & 3, wn = wid >> 2;
    const uint32_t sb = smem_u32(sm);

    float acc[2][4][4] = {};

    const int a_row = wm * 32 + (lane & 15);
    const uint32_t a_addr0 = sb + (uint32_t)((OFF_AH + a_row * LDA_S + (lane >> 4) * 8) * 2);
    // trans B: storage [k][n]; per x4: rows = k16 group, cols = 16-wide n group
    const int tb_row = ((lane >> 3) & 1) * 8 + (lane & 7);
    const int tb_col = wn * 32 + (lane >> 4) * 8;
    const uint32_t ALO_B = (uint32_t)((OFF_AL - OFF_AH) * 2);
    const uint32_t WLO_B = (uint32_t)((OFF_WL - OFF_WH) * 2);

    for (int kc = 0; kc < 8; kc++) {
        const int kbase = kc * 64;
        __syncthreads();
        #pragma unroll
        for (int it = 0; it < 8; it++) {
            int u = tid + it * 256;
            int row = u >> 4, kg = (u & 15) << 2;
            float4 v = *(const float4*)(A + (m0 + row) * 512 + kbase + kg);
            split_store(sm + OFF_AH, sm + OFF_AL, row * LDA_S + kg, v);
        }
        // B chunk: 64 k-rows x 64 n-cols, stored [k][n] stride 72
        #pragma unroll
        for (int it = 0; it < 4; it++) {
            int u = tid + it * 256;
            int row = u >> 4, ng = (u & 15) << 2;
            float4 v = *(const float4*)(B + (kbase + row) * 512 + n0 + ng);
            split_store(sm + OFF_WH, sm + OFF_WL, row * LDA_S + ng, v);
        }
        __syncthreads();

        #pragma unroll
        for (int k16 = 0; k16 < 4; k16++) {
            const uint32_t kb = (uint32_t)(k16 * 32);
            uint32_t ah[2][4], al[2][4];
            ldsm_x4(ah[0], a_addr0 + kb);
            ldsm_x4(ah[1], a_addr0 + (uint32_t)(16 * LDA_S * 2) + kb);
            ldsm_x4(al[0], a_addr0 + ALO_B + kb);
            ldsm_x4(al[1], a_addr0 + ALO_B + (uint32_t)(16 * LDA_S * 2) + kb);
            uint32_t bh[2][4], bl[2][4];
            const uint32_t bo = sb + (uint32_t)((OFF_WH + (k16 * 16 + tb_row) * LDA_S + tb_col) * 2);
            ldsm_x4t(bh[0], bo);
            ldsm_x4t(bh[1], bo + 32);          // +16 n-cols
            ldsm_x4t(bl[0], bo + WLO_B);
            ldsm_x4t(bl[1], bo + WLO_B + 32);
            #pragma unroll
            for (int mi = 0; mi < 2; mi++) {
                #pragma unroll
                for (int nj = 0; nj < 4; nj++) {
                    const uint32_t* bph = &bh[nj >> 1][(nj & 1) * 2];
                    const uint32_t* bpl = &bl[nj >> 1][(nj & 1) * 2];
                    mma16816(acc[mi][nj], ah[mi], bph);
                    mma16816(acc[mi][nj], ah[mi], bpl);
                    mma16816(acc[mi][nj], al[mi], bph);
                }
            }
        }
    }

    const int mrow = m0 + wm * 32 + (lane >> 2);
    const int ncol = n0 + wn * 32 + (lane & 3) * 2;
    #pragma unroll
    for (int mi = 0; mi < 2; mi++) {
        #pragma unroll
        for (int nj = 0; nj < 4; nj++) {
            int n = ncol + nj * 8;
            int m_a = mrow + mi * 16;
            *(float2*)&C[m_a * 512 + n]       = make_float2(acc[mi][nj][0], acc[mi][nj][1]);
            *(float2*)&C[(m_a + 8) * 512 + n] = make_float2(acc[mi][nj][2], acc[mi][nj][3]);
        }
    }
}

// ------------------------------------------------------------------------------
// Composed biases: bc[z][n] = dot(wz[n,:], b_in_z) + b_out_z[n].  Warp per n.
__global__ void __launch_bounds__(256) bias_comp_kernel(
    const float* __restrict__ w0, const float* __restrict__ bk, const float* __restrict__ b0,
    const float* __restrict__ w1, const float* __restrict__ bq, const float* __restrict__ b1,
    float* __restrict__ bc)
{
    const int z = blockIdx.y;
    const float* W  = z ? w1 : w0;
    const float* bi = z ? bq : bk;
    const float* bo = z ? b1 : b0;
    const int warp = threadIdx.x >> 5, lane = threadIdx.x & 31;
    const int n = blockIdx.x * 8 + warp;
    const float* row = W + n * 512;
    float s = 0.f;
    #pragma unroll 4
    for (int h = lane; h < 512; h += 32) s = fmaf(row[h], bi[h], s);
    #pragma unroll
    for (int o = 16; o; o >>= 1) s += __shfl_xor_sync(0xffffffffu, s, o);
    if (lane == 0) bc[z * 512 + n] = s + bo[n];
}

// ------------------------------------------------------------------------------
// Tensor-core merge projection + transpose (unchanged from R5/R6).
struct MergeBatch {
    const float* X[2]; const float* WM[2]; const float* BM[2]; __nv_bfloat16* Y[2];
};

__global__ void __launch_bounds__(256) merge_tc_kernel(MergeBatch mb)
{
    extern __shared__ __nv_bfloat16 sm[];
    const int tid  = threadIdx.x;
    const int wid  = tid >> 5, lane = tid & 31;
    const int zz = blockIdx.z;
    const int tensor = zz >> 3, c = zz & 7;
    const float* X  = mb.X[tensor];
    const float* WM = mb.WM[tensor];
    const float* BM = mb.BM[tensor];
    __nv_bfloat16* Y = mb.Y[tensor];
    const int m0 = blockIdx.x * 128;
    const int r  = blockIdx.y;
    const int n0 = r * 64;
    const int wm = wid & 3, wn = wid >> 2;
    const uint32_t sb = smem_u32(sm);

    #pragma unroll
    for (int it = 0; it < 8; it++) {
        int u = tid + it * 256;
        int row = u >> 4, kg = (u & 15) << 2;
        float4 v = *(const float4*)(X + (m0 + row) * 512 + c * 64 + kg);
        split_store(sm + OFF_AH, sm + OFF_AL, row * LDA_S + kg, v);
    }
    #pragma unroll
    for (int it = 0; it < 4; it++) {
        int u = tid + it * 256;
        int row = u >> 4, kg = (u & 15) << 2;
        float4 v = *(const float4*)(WM + (size_t)(c * 512 + n0 + row) * 64 + kg);
        split_store(sm + OFF_WH, sm + OFF_WL, row * LDA_S + kg, v);
    }
    __syncthreads();

    const int a_row = wm * 32 + (lane & 15);
    const uint32_t a_addr0 = sb + (uint32_t)((OFF_AH + a_row * LDA_S + (lane >> 4) * 8) * 2);
    const int b_row = wn * 32 + ((lane >> 4) & 1) * 8 + (lane & 7);
    const uint32_t b_addr0 = sb + (uint32_t)((OFF_WH + b_row * LDA_S + ((lane >> 3) & 1) * 8) * 2);
    const uint32_t ALO_B = (uint32_t)((OFF_AL - OFF_AH) * 2);
    const uint32_t WLO_B = (uint32_t)((OFF_WL - OFF_WH) * 2);

    float acc[2][4][4] = {};
    #pragma unroll
    for (int k16 = 0; k16 < 4; k16++) {
        const uint32_t kb = (uint32_t)(k16 * 32);
        uint32_t ah[2][4], al[2][4];
        ldsm_x4(ah[0], a_addr0 + kb);
        ldsm_x4(ah[1], a_addr0 + (uint32_t)(16 * LDA_S * 2) + kb);
        ldsm_x4(al[0], a_addr0 + ALO_B + kb);
        ldsm_x4(al[1], a_addr0 + ALO_B + (uint32_t)(16 * LDA_S * 2) + kb);
        uint32_t bh[2][4], bl[2][4];
        ldsm_x4(bh[0], b_addr0 + kb);
        ldsm_x4(bh[1], b_addr0 + (uint32_t)(16 * LDA_S * 2) + kb);
        ldsm_x4(bl[0], b_addr0 + WLO_B + kb);
        ldsm_x4(bl[1], b_addr0 + WLO_B + (uint32_t)(16 * LDA_S * 2) + kb);
        #pragma unroll
        for (int mi = 0; mi < 2; mi++) {
            #pragma unroll
            for (int nj = 0; nj < 4; nj++) {
                const uint32_t* bph = &bh[nj >> 1][(nj & 1) * 2];
                const uint32_t* bpl = &bl[nj >> 1][(nj & 1) * 2];
                mma16816(acc[mi][nj], ah[mi], bph);
                mma16816(acc[mi][nj], ah[mi], bpl);
                mma16816(acc[mi][nj], al[mi], bph);
            }
        }
    }

    __syncthreads();
    uint32_t* ps = (uint32_t*)sm;
    const int mbase = wm * 32 + (lane >> 2);
    const int tbase = wn * 32 + (lane & 3) * 2;
    #pragma unroll
    for (int mi = 0; mi < 2; mi++) {
        #pragma unroll
        for (int nj = 0; nj < 4; nj++) {
            int tt = tbase + nj * 8;
            float bb0 = BM[c * 512 + n0 + tt];
            float bb1 = BM[c * 512 + n0 + tt + 1];
            #pragma unroll
            for (int e = 0; e < 4; e++) {
                int mm = mbase + mi * 16 + ((e >> 1) ? 8 : 0);
                int tc2 = tt + (e & 1);
                float v = acc[mi][nj][e] + ((e & 1) ? bb1 : bb0);
                __nv_bfloat16 hi = __float2bfloat16(v);
                __nv_bfloat16 lo = __float2bfloat16(v - __bfloat162float(hi));
                ps[tc2 * 132 + mm] = (uint32_t)*(uint16_t*)&hi
                                   | ((uint32_t)*(uint16_t*)&lo << 16);
            }
        }
    }
    __syncthreads();

    #pragma unroll
    for (int it = 0; it < 8; it++) {
        int u = tid + it * 256;
        int st = u >> 5, g = u & 31;
        int ml = g * 4;
        uint32_t p0 = ps[st * 132 + ml + 0];
        uint32_t p1 = ps[st * 132 + ml + 1];
        uint32_t p2 = ps[st * 132 + ml + 2];
        uint32_t p3 = ps[st * 132 + ml + 3];
        uint32_t hi01 = (p0 & 0xffffu) | (p1 << 16);
        uint32_t hi23 = (p2 & 0xffffu) | (p3 << 16);
        uint32_t lo01 = (p0 >> 16) | (p1 & 0xffff0000u);
        uint32_t lo23 = (p2 >> 16) | (p3 & 0xffff0000u);
        int m = m0 + ml;
        int b = m / 160, l = m % 160;
        size_t base = ((size_t)((b * 8 + c) * 64 + st) * 16 + r) * 160 + l;
        *(uint2*)&Y[base]            = make_uint2(hi01, hi23);
        *(uint2*)&Y[base + 8 * 160]  = make_uint2(lo01, lo23);
    }
}

// ------------------------------------------------------------------------------
// Tensor-core scores, chunk-split over grid (unchanged from R6).
__global__ void __launch_bounds__(128) scores_tc(
    const __nv_bfloat16* __restrict__ Y1, const __nv_bfloat16* __restrict__ Y0,
    const float* __restrict__ wbo, float* __restrict__ SC)
{
    __shared__ __nv_bfloat16 S1[128*72];
    __shared__ __nv_bfloat16 S0[128*72];
    __shared__ float swb[128];
    const int tid = threadIdx.x;
    const int warp = tid >> 5, lane = tid & 31;
    const int qt = blockIdx.x, kt = blockIdx.y;
    const int b = blockIdx.z >> 2, cg = blockIdx.z & 3;
    const int c0 = cg * 2;
    const int qoff = (warp >> 1) * 16, koff = (warp & 1) * 16;
    swb[tid] = wbo[c0 * 64 + tid];

    const uint32_t s1b = smem_u32(S1), s0b = smem_u32(S0);
    const int t4 = lane >> 3, rr = lane & 7;
    const int lrow = ((t4 & 2) ? 8 : 0) + rr;
    const uint32_t aoff = (uint32_t)((lrow * 72 + qoff + (t4 & 1) * 8) * 2);
    const uint32_t boff = (uint32_t)((lrow * 72 + koff + (t4 & 1) * 8) * 2);

    float acc[2][4] = {};
    for (int ci = 0; ci < 2; ci++) {
        const int c = c0 + ci;
        float num[2][4] = {}, den[2][4] = {};
        for (int oct = 0; oct < 8; oct++) {
            __syncthreads();
            const int sbase = ((b*8 + c)*64 + oct*8) * 16;
            #pragma unroll
            for (int it = 0; it < 8; it++) {
                int u = tid + it*128;
                int half = u >> 9, v = u & 511;
                int row = v >> 2, ch = v & 3;
                const __nv_bfloat16* src = (half ? Y0 : Y1)
                    + (size_t)(sbase + row) * 160 + (half ? kt : qt) * 32 + ch * 8;
                __nv_bfloat16* dst = (half ? S0 : S1) + row * 72 + ch * 8;
                *(uint4*)dst = *(const uint4*)src;
            }
            __syncthreads();
            #pragma unroll
            for (int st = 0; st < 8; st++) {
                const uint32_t tb = (uint32_t)(st * 2304);
                uint32_t a[4], bv[4];
                ldsm_x4t(a,  s1b + tb + aoff);
                ldsm_x4t(bv, s0b + tb + boff);
                float z0[4], z1[4];
                mma1688_z  (z0, a[0], a[1], bv[0]);
                mma1688_acc(z0, a[0], a[1], bv[2]);
                mma1688_acc(z0, a[2], a[3], bv[0]);
                mma1688_z  (z1, a[0], a[1], bv[1]);
                mma1688_acc(z1, a[0], a[1], bv[3]);
                mma1688_acc(z1, a[2], a[3], bv[1]);
                const float wb = swb[ci*64 + oct*8 + st];
                #pragma unroll
                for (int e = 0; e < 4; e++) {
                    {
                        float az = fabsf(z0[e]);
                        den[0][e] += az;
                        float s;
                        asm("sqrt.approx.f32 %0, %1;" : "=f"(s) : "f"(az));
                        uint32_t sb2 = (__float_as_uint(s) & 0x7fffffffu)
                                     | (__float_as_uint(z0[e]) & 0x80000000u);
                        num[0][e] = fmaf(wb, __uint_as_float(sb2), num[0][e]);
                    }
                    {
                        float az = fabsf(z1[e]);
                        den[1][e] += az;
                        float s;
                        asm("sqrt.approx.f32 %0, %1;" : "=f"(s) : "f"(az));
                        uint32_t sb2 = (__float_as_uint(s) & 0x7fffffffu)
                                     | (__float_as_uint(z1[e]) & 0x80000000u);
                        num[1][e] = fmaf(wb, __uint_as_float(sb2), num[1][e]);
                    }
                }
            }
        }
        #pragma unroll
        for (int kf = 0; kf < 2; kf++)
            #pragma unroll
            for (int e = 0; e < 4; e++)
                acc[kf][e] += num[kf][e] * rsqrtf(fmaxf(den[kf][e], 1e-24f));
    }
    const int q = qt*32 + qoff + (lane >> 2);
    const int k = kt*32 + koff + (lane & 3)*2;
    float* p0 = SC + (size_t)cg * SC_PLANE + (size_t)(b*160 + q)*160 + k;
    *(float2*)(p0)             = make_float2(acc[0][0], acc[0][1]);
    *(float2*)(p0 + 8)         = make_float2(acc[1][0], acc[1][1]);
    *(float2*)(p0 + 8*160)     = make_float2(acc[0][2], acc[0][3]);
    *(float2*)(p0 + 8*160 + 8) = make_float2(acc[1][2], acc[1][3]);
}

// ------------------------------------------------------------------------------
// Row softmax summing the 4 partial planes; result written to plane 0.
__global__ void __launch_bounds__(192) softmax_kernel(float* __restrict__ sc)
{
    const int row = blockIdx.x;
    float* p = sc + (size_t)row*160;
    const int t = threadIdx.x;
    __shared__ float red[6], red2[6];
    float x = -3.0e38f;
    if (t < 160) {
        x = p[t] + p[SC_PLANE + t] + p[2*SC_PLANE + t] + p[3*SC_PLANE + t];
    }
    float v = x;
    #pragma unroll
    for (int o = 16; o; o >>= 1) v = fmaxf(v, __shfl_xor_sync(0xffffffffu, v, o));
    if ((t & 31) == 0) red[t >> 5] = v;
    __syncthreads();
    float m = red[0];
    #pragma unroll
    for (int i = 1; i < 6; i++) m = fmaxf(m, red[i]);
    float e = (t < 160) ? expf(x - m) : 0.f;
    float sv = e;
    #pragma unroll
    for (int o = 16; o; o >>= 1) sv += __shfl_xor_sync(0xffffffffu, sv, o);
    if ((t & 31) == 0) red2[t >> 5] = sv;
    __syncthreads();
    float ssum = 0.f;
    #pragma unroll
    for (int i = 0; i < 6; i++) ssum += red2[i];
    if (t < 160) p[t] = e / ssum;
}

// ------------------------------------------------------------------------------
// Tensor-core attv (NN GEMM) fused with transpose-scramble:
//   scr[b][h*160 + q] = sum_k att[b][q][k] * vv[b][k][h]
// CTA tile 32q x 64h, K=160 in 5 chunks of 32. 128 threads (2x2 warps, 16x32).
__global__ void __launch_bounds__(128) attv_tc_kernel(
    const float* __restrict__ att, const float* __restrict__ vv,
    float* __restrict__ scr)
{
    __shared__ __nv_bfloat16 Ah[32*40], Al[32*40], Bh[32*72], Bl[32*72];
    __shared__ float ts[64*33];
    const int tid = threadIdx.x;
    const int warp = tid >> 5, lane = tid & 31;
    const int q0 = blockIdx.x * 32, h0 = blockIdx.y * 64, b = blockIdx.z;
    const int wm = warp & 1, wn = warp >> 1;
    const float* A = att + (size_t)b * 25600;
    const float* V = vv + (size_t)b * 81920;
    const uint32_t ahb = smem_u32(Ah), alb = smem_u32(Al);
    const uint32_t bhb = smem_u32(Bh), blb = smem_u32(Bl);
    const uint32_t a_off = (uint32_t)(((wm * 16 + (lane & 15)) * 40 + (lane >> 4) * 8) * 2);
    const int tb_row = ((lane >> 3) & 1) * 8 + (lane & 7);
    const int tb_col = wn * 32 + (lane >> 4) * 8;

    float acc[4][4] = {};
    for (int kc = 0; kc < 5; kc++) {
        const int k0 = kc * 32;
        __syncthreads();
        #pragma unroll
        for (int it = 0; it < 2; it++) {
            int u = tid + it * 128;
            int row = u >> 3, c4 = (u & 7) * 4;
            float4 v4 = *(const float4*)(A + (q0 + row) * 160 + k0 + c4);
            split_store(Ah, Al, row * 40 + c4, v4);
        }
        #pragma unroll
        for (int it = 0; it < 4; it++) {
            int u = tid + it * 128;
            int row = u >> 4, c4 = (u & 15) * 4;
            float4 v4 = *(const float4*)(V + (k0 + row) * 512 + h0 + c4);
            split_store(Bh, Bl, row * 72 + c4, v4);
        }
        __syncthreads();
        #pragma unroll
        for (int k16 = 0; k16 < 2; k16++) {
            uint32_t ah[4], al[4];
            ldsm_x4(ah, ahb + a_off + k16 * 32);
            ldsm_x4(al, alb + a_off + k16 * 32);
            uint32_t bh[2][4], bl[2][4];
            const uint32_t bo = (uint32_t)(((k16 * 16 + tb_row) * 72 + tb_col) * 2);
            ldsm_x4t(bh[0], bhb + bo);
            ldsm_x4t(bh[1], bhb + bo + 32);
            ldsm_x4t(bl[0], blb + bo);
            ldsm_x4t(bl[1], blb + bo + 32);
            #pragma unroll
            for (int nj = 0; nj < 4; nj++) {
                const uint32_t* ph = &bh[nj >> 1][(nj & 1) * 2];
                const uint32_t* pl = &bl[nj >> 1][(nj & 1) * 2];
                mma16816(acc[nj], ah, ph);
                mma16816(acc[nj], ah, pl);
                mma16816(acc[nj], al, ph);
            }
        }
    }
    __syncthreads();
    const int mr = wm * 16 + (lane >> 2);
    const int nc = wn * 32 + (lane & 3) * 2;
    #pragma unroll
    for (int nj = 0; nj < 4; nj++) {
        int h = nc + nj * 8;
        ts[h * 33 + mr]           = acc[nj][0];
        ts[(h + 1) * 33 + mr]     = acc[nj][1];
        ts[h * 33 + mr + 8]       = acc[nj][2];
        ts[(h + 1) * 33 + mr + 8] = acc[nj][3];
    }
    __syncthreads();
    const int h = tid >> 1, qh = (tid & 1) * 16;
    float* dst = scr + (size_t)b * 81920 + (h0 + h) * 160 + q0 + qh;
    #pragma unroll
    for (int i = 0; i < 16; i += 4) {
        float4 o = { ts[h * 33 + qh + i], ts[h * 33 + qh + i + 1],
                     ts[h * 33 + qh + i + 2], ts[h * 33 + qh + i + 3] };
        *(float4*)(dst + i) = o;
    }
}

// ------------------------------------------------------------------------------
extern "C" void kernel_launch(void* const* d_in, const int* in_sizes, int n_in,
                              void* d_out, int out_size)
{
    (void)in_sizes; (void)n_in; (void)out_size;
    const float* v    = (const float*)d_in[0];
    const float* kin  = (const float*)d_in[1];
    const float* qin  = (const float*)d_in[2];
    const float* w_v  = (const float*)d_in[3];  const float* b_v = (const float*)d_in[4];
    const float* w_k  = (const float*)d_in[5];  const float* b_k = (const float*)d_in[6];
    const float* w_q  = (const float*)d_in[7];  const float* b_q = (const float*)d_in[8];
    const float* w0   = (const float*)d_in[9];  const float* b0  = (const float*)d_in[10];
    const float* w1   = (const float*)d_in[11]; const float* b1  = (const float*)d_in[12];
    const float* wm0  = (const float*)d_in[13]; const float* bm0 = (const float*)d_in[14];
    const float* wm1  = (const float*)d_in[15]; const float* bm1 = (const float*)d_in[16];
    const float* w_bo = (const float*)d_in[17];
    const float* w_m  = (const float*)d_in[19]; const float* b_m = (const float*)d_in[20];
    float* out = (float*)d_out;

    float *vv, *w0k, *w1q, *bc, *x0, *x1, *sc, *scr;
    __nv_bfloat16 *y0, *y1;
    cudaGetSymbolAddress((void**)&vv,  g_vv);
    cudaGetSymbolAddress((void**)&w0k, g_w0k);
    cudaGetSymbolAddress((void**)&w1q, g_w1q);
    cudaGetSymbolAddress((void**)&bc,  g_bc);
    cudaGetSymbolAddress((void**)&x0,  g_x0);
    cudaGetSymbolAddress((void**)&x1,  g_x1);
    cudaGetSymbolAddress((void**)&y0,  g_y0);
    cudaGetSymbolAddress((void**)&y1,  g_y1);
    cudaGetSymbolAddress((void**)&sc,  g_sc);
    cudaGetSymbolAddress((void**)&scr, g_scr);

    static int smem_set = 0;
    if (!smem_set) {
        cudaFuncSetAttribute(hmma_gemm_kernel,
                             cudaFuncAttributeMaxDynamicSharedMemorySize, HM_SMEM_BYTES);
        cudaFuncSetAttribute(merge_tc_kernel,
                             cudaFuncAttributeMaxDynamicSharedMemorySize, HM_SMEM_BYTES);
        cudaFuncSetAttribute(prep_hmma_kernel,
                             cudaFuncAttributeMaxDynamicSharedMemorySize, HM_SMEM_BYTES);
        smem_set = 1;
    }

    // Weight composition: w0k = w0 @ w_k, w1q = w1 @ w_q + composed biases
    prep_hmma_kernel<<<dim3(4, 8, 2), 256, HM_SMEM_BYTES>>>(w0, w_k, w0k, w1, w_q, w1q);
    bias_comp_kernel<<<dim3(64, 2), 256>>>(w0, b_k, b0, w1, b_q, b1, bc);

    // Stage 1 (single launch): vv, x0, x1
    GemmBatch g1;
    g1.A[0] = v;    g1.W[0] = w_v; g1.bias[0] = b_v;      g1.C[0] = vv;
    g1.A[1] = kin;  g1.W[1] = w0k; g1.bias[1] = bc;       g1.C[1] = x0;
    g1.A[2] = qin;  g1.W[2] = w1q; g1.bias[2] = bc + 512; g1.C[2] = x1;
    hmma_gemm_kernel<<<dim3(10, 8, 3), 256, HM_SMEM_BYTES>>>(g1);

    MergeBatch mrg;
    mrg.X[0] = x0; mrg.WM[0] = wm0; mrg.BM[0] = bm0; mrg.Y[0] = y0;
    mrg.X[1] = x1; mrg.WM[1] = wm1; mrg.BM[1] = bm1; mrg.Y[1] = y1;
    merge_tc_kernel<<<dim3(10, 8, 16), 256, HM_SMEM_BYTES>>>(mrg);

    scores_tc<<<dim3(5, 5, 32), 128>>>(y1, y0, w_bo, sc);
    softmax_kernel<<<1280, 192>>>(sc);
    attv_tc_kernel<<<dim3(5, 8, 8), 128>>>(sc, vv, scr);

    GemmBatch g3;
    g3.A[0] = scr; g3.W[0] = w_m; g3.bias[0] = b_m; g3.C[0] = out;
    g3.A[1] = scr; g3.W[1] = w_m; g3.bias[1] = b_m; g3.C[1] = out;
    g3.A[2] = scr; g3.W[2] = w_m; g3.bias[2] = b_m; g3.C[2] = out;
    hmma_gemm_kernel<<<dim3(10, 8, 1), 256, HM_SMEM_BYTES>>>(g3);
}

// round 9
// speedup vs baseline: 2.2642x; 1.0762x over previous
#include <cuda_runtime.h>
#include <cuda_bf16.h>
#include <cstdint>

// Problem constants (fixed shapes from the reference)
#define NB_B 8
#define NB_L 160
#define NB_H 512
#define NB_C 8
#define NB_S 64
#define NB_R 8
#define NB_BL (NB_B*NB_L)   // 1280
#define SC_PLANE (NB_B*NB_L*NB_L)   // 204800

// ---------------- scratch (device globals: no runtime allocation) -------------
__device__ float g_vv [NB_BL*NB_H];
__device__ float g_w0k[NB_H*NB_H];     // composed weight w0 @ w_k
__device__ float g_w1q[NB_H*NB_H];     // composed weight w1 @ w_q
__device__ float g_bc [2*NB_H];        // composed biases
__device__ uint32_t g_x0 [NB_BL*NB_H]; // packed bf16 (hi | lo<<16)
__device__ uint32_t g_x1 [NB_BL*NB_H];
// Y layout: [b][c][s(64)][r(16: 8 hi | 8 lo)][l(160)] bf16
__device__ __nv_bfloat16 g_y0 [NB_B*NB_C*NB_S*16*NB_L];
__device__ __nv_bfloat16 g_y1 [NB_B*NB_C*NB_S*16*NB_L];
__device__ float g_sc [8*SC_PLANE];    // 8 per-chunk partial planes
__device__ float g_scr[NB_BL*NB_H];

// ======================= mma.sync helpers (sm_80+ path) =======================
__device__ __forceinline__ uint32_t smem_u32(const void* p) {
    uint32_t a;
    asm("{ .reg .u64 t; cvta.to.shared.u64 t, %1; cvt.u32.u64 %0, t; }"
        : "=r"(a) : "l"(p));
    return a;
}
__device__ __forceinline__ void mma16816(float* d, const uint32_t* a, const uint32_t* b) {
    asm volatile(
        "mma.sync.aligned.m16n8k16.row.col.f32.bf16.bf16.f32 "
        "{%0,%1,%2,%3}, {%4,%5,%6,%7}, {%8,%9}, {%0,%1,%2,%3};"
        : "+f"(d[0]), "+f"(d[1]), "+f"(d[2]), "+f"(d[3])
        : "r"(a[0]), "r"(a[1]), "r"(a[2]), "r"(a[3]), "r"(b[0]), "r"(b[1]));
}
__device__ __forceinline__ void ldsm_x4(uint32_t* r, uint32_t addr) {
    asm volatile("ldmatrix.sync.aligned.m8n8.x4.shared.b16 {%0,%1,%2,%3}, [%4];"
        : "=r"(r[0]), "=r"(r[1]), "=r"(r[2]), "=r"(r[3]) : "r"(addr));
}
__device__ __forceinline__ void ldsm_x4t(uint32_t* r, uint32_t addr) {
    asm volatile("ldmatrix.sync.aligned.m8n8.x4.trans.shared.b16 {%0,%1,%2,%3}, [%4];"
        : "=r"(r[0]), "=r"(r[1]), "=r"(r[2]), "=r"(r[3]) : "r"(addr));
}
__device__ __forceinline__ void mma1688_z(float* d, uint32_t a0, uint32_t a1, uint32_t b) {
    asm volatile(
        "mma.sync.aligned.m16n8k8.row.col.f32.bf16.bf16.f32 "
        "{%0,%1,%2,%3}, {%4,%5}, {%6}, {%7,%8,%9,%10};"
        : "=f"(d[0]), "=f"(d[1]), "=f"(d[2]), "=f"(d[3])
        : "r"(a0), "r"(a1), "r"(b), "f"(0.f), "f"(0.f), "f"(0.f), "f"(0.f));
}
__device__ __forceinline__ void mma1688_acc(float* d, uint32_t a0, uint32_t a1, uint32_t b) {
    asm volatile(
        "mma.sync.aligned.m16n8k8.row.col.f32.bf16.bf16.f32 "
        "{%0,%1,%2,%3}, {%4,%5}, {%6}, {%0,%1,%2,%3};"
        : "+f"(d[0]), "+f"(d[1]), "+f"(d[2]), "+f"(d[3])
        : "r"(a0), "r"(a1), "r"(b));
}
__device__ __forceinline__ void split_store(__nv_bfloat16* smh, __nv_bfloat16* sml,
                                            int off, float4 v) {
    __nv_bfloat162 h01 = __floats2bfloat162_rn(v.x, v.y);
    __nv_bfloat162 h23 = __floats2bfloat162_rn(v.z, v.w);
    float2 f01 = __bfloat1622float2(h01);
    float2 f23 = __bfloat1622float2(h23);
    __nv_bfloat162 l01 = __floats2bfloat162_rn(v.x - f01.x, v.y - f01.y);
    __nv_bfloat162 l23 = __floats2bfloat162_rn(v.z - f23.x, v.w - f23.y);
    *(uint2*)&smh[off] = make_uint2(*(uint32_t*)&h01, *(uint32_t*)&h23);
    *(uint2*)&sml[off] = make_uint2(*(uint32_t*)&l01, *(uint32_t*)&l23);
}
__device__ __forceinline__ uint32_t pack_hilo(float v) {
    __nv_bfloat16 hi = __float2bfloat16(v);
    __nv_bfloat16 lo = __float2bfloat16(v - __bfloat162float(hi));
    return (uint32_t)*(uint16_t*)&hi | ((uint32_t)*(uint16_t*)&lo << 16);
}

// ================= bf16-split tensor-core GEMM: C = A @ W^T + bias ===========
// pack[z] != 0 -> store packed bf16 hi/lo uint32 instead of fp32.
struct GemmBatch {
    const float* A[3]; const float* W[3]; const float* bias[3]; float* C[3];
    int pack[3];
};

#define LDA_S 72
#define OFF_AH 0
#define OFF_AL (128*LDA_S)
#define OFF_WH (256*LDA_S)
#define OFF_WL (320*LDA_S)
#define HM_SMEM_BYTES (384*LDA_S*2)   // 55296

__global__ void __launch_bounds__(256) hmma_gemm_kernel(GemmBatch gb)
{
    extern __shared__ __nv_bfloat16 sm[];
    const int tid  = threadIdx.x;
    const int wid  = tid >> 5, lane = tid & 31;
    const int z = blockIdx.z;
    const float* A    = gb.A[z];
    const float* W    = gb.W[z];
    const float* bias = gb.bias[z];
    float*       C    = gb.C[z];
    const int m0 = blockIdx.x * 128;
    const int n0 = blockIdx.y * 64;
    const int wm = wid & 3, wn = wid >> 2;
    const uint32_t sb = smem_u32(sm);

    float acc[2][4][4] = {};

    const int a_row = wm * 32 + (lane & 15);
    const uint32_t a_addr0 = sb + (uint32_t)((OFF_AH + a_row * LDA_S + (lane >> 4) * 8) * 2);
    const int b_row = wn * 32 + ((lane >> 4) & 1) * 8 + (lane & 7);
    const uint32_t b_addr0 = sb + (uint32_t)((OFF_WH + b_row * LDA_S + ((lane >> 3) & 1) * 8) * 2);
    const uint32_t ALO_B = (uint32_t)((OFF_AL - OFF_AH) * 2);
    const uint32_t WLO_B = (uint32_t)((OFF_WL - OFF_WH) * 2);

    for (int kc = 0; kc < 8; kc++) {
        const int kbase = kc * 64;
        __syncthreads();
        #pragma unroll
        for (int it = 0; it < 8; it++) {
            int u = tid + it * 256;
            int row = u >> 4, kg = (u & 15) << 2;
            float4 v = *(const float4*)(A + (m0 + row) * 512 + kbase + kg);
            split_store(sm + OFF_AH, sm + OFF_AL, row * LDA_S + kg, v);
        }
        #pragma unroll
        for (int it = 0; it < 4; it++) {
            int u = tid + it * 256;
            int row = u >> 4, kg = (u & 15) << 2;
            float4 v = *(const float4*)(W + (n0 + row) * 512 + kbase + kg);
            split_store(sm + OFF_WH, sm + OFF_WL, row * LDA_S + kg, v);
        }
        __syncthreads();

        #pragma unroll
        for (int k16 = 0; k16 < 4; k16++) {
            const uint32_t kb = (uint32_t)(k16 * 32);
            uint32_t ah[2][4], al[2][4];
            ldsm_x4(ah[0], a_addr0 + kb);
            ldsm_x4(ah[1], a_addr0 + (uint32_t)(16 * LDA_S * 2) + kb);
            ldsm_x4(al[0], a_addr0 + ALO_B + kb);
            ldsm_x4(al[1], a_addr0 + ALO_B + (uint32_t)(16 * LDA_S * 2) + kb);
            uint32_t bh[2][4], bl[2][4];
            ldsm_x4(bh[0], b_addr0 + kb);
            ldsm_x4(bh[1], b_addr0 + (uint32_t)(16 * LDA_S * 2) + kb);
            ldsm_x4(bl[0], b_addr0 + WLO_B + kb);
            ldsm_x4(bl[1], b_addr0 + WLO_B + (uint32_t)(16 * LDA_S * 2) + kb);
            #pragma unroll
            for (int mi = 0; mi < 2; mi++) {
                #pragma unroll
                for (int nj = 0; nj < 4; nj++) {
                    const uint32_t* bph = &bh[nj >> 1][(nj & 1) * 2];
                    const uint32_t* bpl = &bl[nj >> 1][(nj & 1) * 2];
                    mma16816(acc[mi][nj], ah[mi], bph);
                    mma16816(acc[mi][nj], ah[mi], bpl);
                    mma16816(acc[mi][nj], al[mi], bph);
                }
            }
        }
    }

    const int mrow = m0 + wm * 32 + (lane >> 2);
    const int ncol = n0 + wn * 32 + (lane & 3) * 2;
    if (gb.pack[z]) {
        uint32_t* Cp = (uint32_t*)C;
        #pragma unroll
        for (int mi = 0; mi < 2; mi++) {
            #pragma unroll
            for (int nj = 0; nj < 4; nj++) {
                int n = ncol + nj * 8;
                float b0 = bias[n], b1 = bias[n + 1];
                int m_a = mrow + mi * 16;
                *(uint2*)&Cp[m_a * 512 + n] =
                    make_uint2(pack_hilo(acc[mi][nj][0] + b0), pack_hilo(acc[mi][nj][1] + b1));
                *(uint2*)&Cp[(m_a + 8) * 512 + n] =
                    make_uint2(pack_hilo(acc[mi][nj][2] + b0), pack_hilo(acc[mi][nj][3] + b1));
            }
        }
    } else {
        #pragma unroll
        for (int mi = 0; mi < 2; mi++) {
            #pragma unroll
            for (int nj = 0; nj < 4; nj++) {
                int n = ncol + nj * 8;
                float b0 = bias[n], b1 = bias[n + 1];
                int m_a = mrow + mi * 16;
                *(float2*)&C[m_a * 512 + n]       = make_float2(acc[mi][nj][0] + b0, acc[mi][nj][1] + b1);
                *(float2*)&C[(m_a + 8) * 512 + n] = make_float2(acc[mi][nj][2] + b0, acc[mi][nj][3] + b1);
            }
        }
    }
}

// ------------------------------------------------------------------------------
// Weight composition (NN GEMM): C[i,j] = sum_h A[i,h] * B[h,j]. (unchanged)
__global__ void __launch_bounds__(256) prep_hmma_kernel(
    const float* __restrict__ A0, const float* __restrict__ B0, float* __restrict__ C0,
    const float* __restrict__ A1, const float* __restrict__ B1, float* __restrict__ C1)
{
    extern __shared__ __nv_bfloat16 sm[];
    const int tid  = threadIdx.x;
    const int wid  = tid >> 5, lane = tid & 31;
    const float* A = blockIdx.z ? A1 : A0;
    const float* B = blockIdx.z ? B1 : B0;
    float*       C = blockIdx.z ? C1 : C0;
    const int m0 = blockIdx.x * 128;
    const int n0 = blockIdx.y * 64;
    const int wm = wid & 3, wn = wid >> 2;
    const uint32_t sb = smem_u32(sm);

    float acc[2][4][4] = {};

    const int a_row = wm * 32 + (lane & 15);
    const uint32_t a_addr0 = sb + (uint32_t)((OFF_AH + a_row * LDA_S + (lane >> 4) * 8) * 2);
    const int tb_row = ((lane >> 3) & 1) * 8 + (lane & 7);
    const int tb_col = wn * 32 + (lane >> 4) * 8;
    const uint32_t ALO_B = (uint32_t)((OFF_AL - OFF_AH) * 2);
    const uint32_t WLO_B = (uint32_t)((OFF_WL - OFF_WH) * 2);

    for (int kc = 0; kc < 8; kc++) {
        const int kbase = kc * 64;
        __syncthreads();
        #pragma unroll
        for (int it = 0; it < 8; it++) {
            int u = tid + it * 256;
            int row = u >> 4, kg = (u & 15) << 2;
            float4 v = *(const float4*)(A + (m0 + row) * 512 + kbase + kg);
            split_store(sm + OFF_AH, sm + OFF_AL, row * LDA_S + kg, v);
        }
        #pragma unroll
        for (int it = 0; it < 4; it++) {
            int u = tid + it * 256;
            int row = u >> 4, ng = (u & 15) << 2;
            float4 v = *(const float4*)(B + (kbase + row) * 512 + n0 + ng);
            split_store(sm + OFF_WH, sm + OFF_WL, row * LDA_S + ng, v);
        }
        __syncthreads();

        #pragma unroll
        for (int k16 = 0; k16 < 4; k16++) {
            const uint32_t kb = (uint32_t)(k16 * 32);
            uint32_t ah[2][4], al[2][4];
            ldsm_x4(ah[0], a_addr0 + kb);
            ldsm_x4(ah[1], a_addr0 + (uint32_t)(16 * LDA_S * 2) + kb);
            ldsm_x4(al[0], a_addr0 + ALO_B + kb);
            ldsm_x4(al[1], a_addr0 + ALO_B + (uint32_t)(16 * LDA_S * 2) + kb);
            uint32_t bh[2][4], bl[2][4];
            const uint32_t bo = sb + (uint32_t)((OFF_WH + (k16 * 16 + tb_row) * LDA_S + tb_col) * 2);
            ldsm_x4t(bh[0], bo);
            ldsm_x4t(bh[1], bo + 32);
            ldsm_x4t(bl[0], bo + WLO_B);
            ldsm_x4t(bl[1], bo + WLO_B + 32);
            #pragma unroll
            for (int mi = 0; mi < 2; mi++) {
                #pragma unroll
                for (int nj = 0; nj < 4; nj++) {
                    const uint32_t* bph = &bh[nj >> 1][(nj & 1) * 2];
                    const uint32_t* bpl = &bl[nj >> 1][(nj & 1) * 2];
                    mma16816(acc[mi][nj], ah[mi], bph);
                    mma16816(acc[mi][nj], ah[mi], bpl);
                    mma16816(acc[mi][nj], al[mi], bph);
                }
            }
        }
    }

    const int mrow = m0 + wm * 32 + (lane >> 2);
    const int ncol = n0 + wn * 32 + (lane & 3) * 2;
    #pragma unroll
    for (int mi = 0; mi < 2; mi++) {
        #pragma unroll
        for (int nj = 0; nj < 4; nj++) {
            int n = ncol + nj * 8;
            int m_a = mrow + mi * 16;
            *(float2*)&C[m_a * 512 + n]       = make_float2(acc[mi][nj][0], acc[mi][nj][1]);
            *(float2*)&C[(m_a + 8) * 512 + n] = make_float2(acc[mi][nj][2], acc[mi][nj][3]);
        }
    }
}

// ------------------------------------------------------------------------------
__global__ void __launch_bounds__(256) bias_comp_kernel(
    const float* __restrict__ w0, const float* __restrict__ bk, const float* __restrict__ b0,
    const float* __restrict__ w1, const float* __restrict__ bq, const float* __restrict__ b1,
    float* __restrict__ bc)
{
    const int z = blockIdx.y;
    const float* W  = z ? w1 : w0;
    const float* bi = z ? bq : bk;
    const float* bo = z ? b1 : b0;
    const int warp = threadIdx.x >> 5, lane = threadIdx.x & 31;
    const int n = blockIdx.x * 8 + warp;
    const float* row = W + n * 512;
    float s = 0.f;
    #pragma unroll 4
    for (int h = lane; h < 512; h += 32) s = fmaf(row[h], bi[h], s);
    #pragma unroll
    for (int o = 16; o; o >>= 1) s += __shfl_xor_sync(0xffffffffu, s, o);
    if (lane == 0) bc[z * 512 + n] = s + bo[n];
}

// ------------------------------------------------------------------------------
// Tensor-core merge: X pre-split packed uint32 (hi|lo<<16). Stride 72 (K=64!).
struct MergeBatch {
    const uint32_t* X[2]; const float* WM[2]; const float* BM[2]; __nv_bfloat16* Y[2];
};

__global__ void __launch_bounds__(256) merge_tc_kernel(MergeBatch mb)
{
    extern __shared__ __nv_bfloat16 sm[];
    const int tid  = threadIdx.x;
    const int wid  = tid >> 5, lane = tid & 31;
    const int zz = blockIdx.z;
    const int tensor = zz >> 3, c = zz & 7;
    const uint32_t* X = mb.X[tensor];
    const float* WM = mb.WM[tensor];
    const float* BM = mb.BM[tensor];
    __nv_bfloat16* Y = mb.Y[tensor];
    const int m0 = blockIdx.x * 128;
    const int r  = blockIdx.y;
    const int n0 = r * 64;
    const int wm = wid & 3, wn = wid >> 2;
    const uint32_t sb = smem_u32(sm);

    // stage X (packed): 128 rows x 64 k -> unpack hi/lo via LOP
    #pragma unroll
    for (int it = 0; it < 8; it++) {
        int u = tid + it * 256;
        int row = u >> 4, kg = (u & 15) << 2;
        uint4 x4 = *(const uint4*)(X + (m0 + row) * 512 + c * 64 + kg);
        uint32_t hi01 = (x4.x & 0xffffu) | (x4.y << 16);
        uint32_t hi23 = (x4.z & 0xffffu) | (x4.w << 16);
        uint32_t lo01 = (x4.x >> 16) | (x4.y & 0xffff0000u);
        uint32_t lo23 = (x4.z >> 16) | (x4.w & 0xffff0000u);
        int o = row * LDA_S + kg;
        *(uint2*)&sm[OFF_AH + o] = make_uint2(hi01, hi23);
        *(uint2*)&sm[OFF_AL + o] = make_uint2(lo01, lo23);
    }
    // stage WM (fp32): 64 rows x 64 k
    #pragma unroll
    for (int it = 0; it < 4; it++) {
        int u = tid + it * 256;
        int row = u >> 4, kg = (u & 15) << 2;
        float4 v = *(const float4*)(WM + (size_t)(c * 512 + n0 + row) * 64 + kg);
        split_store(sm + OFF_WH, sm + OFF_WL, row * LDA_S + kg, v);
    }
    __syncthreads();

    const int a_row = wm * 32 + (lane & 15);
    const uint32_t a_addr0 = sb + (uint32_t)((OFF_AH + a_row * LDA_S + (lane >> 4) * 8) * 2);
    const int b_row = wn * 32 + ((lane >> 4) & 1) * 8 + (lane & 7);
    const uint32_t b_addr0 = sb + (uint32_t)((OFF_WH + b_row * LDA_S + ((lane >> 3) & 1) * 8) * 2);
    const uint32_t ALO_B = (uint32_t)((OFF_AL - OFF_AH) * 2);
    const uint32_t WLO_B = (uint32_t)((OFF_WL - OFF_WH) * 2);

    float acc[2][4][4] = {};
    #pragma unroll
    for (int k16 = 0; k16 < 4; k16++) {
        const uint32_t kb = (uint32_t)(k16 * 32);
        uint32_t ah[2][4], al[2][4];
        ldsm_x4(ah[0], a_addr0 + kb);
        ldsm_x4(ah[1], a_addr0 + (uint32_t)(16 * LDA_S * 2) + kb);
        ldsm_x4(al[0], a_addr0 + ALO_B + kb);
        ldsm_x4(al[1], a_addr0 + ALO_B + (uint32_t)(16 * LDA_S * 2) + kb);
        uint32_t bh[2][4], bl[2][4];
        ldsm_x4(bh[0], b_addr0 + kb);
        ldsm_x4(bh[1], b_addr0 + (uint32_t)(16 * LDA_S * 2) + kb);
        ldsm_x4(bl[0], b_addr0 + WLO_B + kb);
        ldsm_x4(bl[1], b_addr0 + WLO_B + (uint32_t)(16 * LDA_S * 2) + kb);
        #pragma unroll
        for (int mi = 0; mi < 2; mi++) {
            #pragma unroll
            for (int nj = 0; nj < 4; nj++) {
                const uint32_t* bph = &bh[nj >> 1][(nj & 1) * 2];
                const uint32_t* bpl = &bl[nj >> 1][(nj & 1) * 2];
                mma16816(acc[mi][nj], ah[mi], bph);
                mma16816(acc[mi][nj], ah[mi], bpl);
                mma16816(acc[mi][nj], al[mi], bph);
            }
        }
    }

    __syncthreads();
    uint32_t* ps = (uint32_t*)sm;
    const int mbase = wm * 32 + (lane >> 2);
    const int tbase = wn * 32 + (lane & 3) * 2;
    #pragma unroll
    for (int mi = 0; mi < 2; mi++) {
        #pragma unroll
        for (int nj = 0; nj < 4; nj++) {
            int tt = tbase + nj * 8;
            float bb0 = BM[c * 512 + n0 + tt];
            float bb1 = BM[c * 512 + n0 + tt + 1];
            #pragma unroll
            for (int e = 0; e < 4; e++) {
                int mm = mbase + mi * 16 + ((e >> 1) ? 8 : 0);
                int tc2 = tt + (e & 1);
                ps[tc2 * 132 + mm] = pack_hilo(acc[mi][nj][e] + ((e & 1) ? bb1 : bb0));
            }
        }
    }
    __syncthreads();

    #pragma unroll
    for (int it = 0; it < 8; it++) {
        int u = tid + it * 256;
        int st = u >> 5, g = u & 31;
        int ml = g * 4;
        uint32_t p0 = ps[st * 132 + ml + 0];
        uint32_t p1 = ps[st * 132 + ml + 1];
        uint32_t p2 = ps[st * 132 + ml + 2];
        uint32_t p3 = ps[st * 132 + ml + 3];
        uint32_t hi01 = (p0 & 0xffffu) | (p1 << 16);
        uint32_t hi23 = (p2 & 0xffffu) | (p3 << 16);
        uint32_t lo01 = (p0 >> 16) | (p1 & 0xffff0000u);
        uint32_t lo23 = (p2 >> 16) | (p3 & 0xffff0000u);
        int m = m0 + ml;
        int b = m / 160, l = m % 160;
        size_t base = ((size_t)((b * 8 + c) * 64 + st) * 16 + r) * 160 + l;
        *(uint2*)&Y[base]            = make_uint2(hi01, hi23);
        *(uint2*)&Y[base + 8 * 160]  = make_uint2(lo01, lo23);
    }
}

// ------------------------------------------------------------------------------
// Tensor-core scores: ONE chunk per CTA. grid (5,5,64): z = b*8 + c.
// S-tiles 32 cols wide -> stride 40 is safe here.
__global__ void __launch_bounds__(128) scores_tc(
    const __nv_bfloat16* __restrict__ Y1, const __nv_bfloat16* __restrict__ Y0,
    const float* __restrict__ wbo, float* __restrict__ SC)
{
    __shared__ __nv_bfloat16 S1[128*40];
    __shared__ __nv_bfloat16 S0[128*40];
    __shared__ float swb[64];
    const int tid = threadIdx.x;
    const int warp = tid >> 5, lane = tid & 31;
    const int qt = blockIdx.x, kt = blockIdx.y;
    const int b = blockIdx.z >> 3, c = blockIdx.z & 7;
    const int qoff = (warp >> 1) * 16, koff = (warp & 1) * 16;
    if (tid < 64) swb[tid] = wbo[c * 64 + tid];

    const uint32_t s1b = smem_u32(S1), s0b = smem_u32(S0);
    const int t4 = lane >> 3, rr = lane & 7;
    const int lrow = ((t4 & 2) ? 8 : 0) + rr;
    const uint32_t aoff = (uint32_t)((lrow * 40 + qoff + (t4 & 1) * 8) * 2);
    const uint32_t boff = (uint32_t)((lrow * 40 + koff + (t4 & 1) * 8) * 2);

    float num[2][4] = {}, den[2][4] = {};
    for (int oct = 0; oct < 8; oct++) {
        __syncthreads();
        const int sbase = ((b*8 + c)*64 + oct*8) * 16;
        #pragma unroll
        for (int it = 0; it < 8; it++) {
            int u = tid + it*128;
            int half = u >> 9, v = u & 511;
            int row = v >> 2, ch = v & 3;
            const __nv_bfloat16* src = (half ? Y0 : Y1)
                + (size_t)(sbase + row) * 160 + (half ? kt : qt) * 32 + ch * 8;
            __nv_bfloat16* dst = (half ? S0 : S1) + row * 40 + ch * 8;
            *(uint4*)dst = *(const uint4*)src;
        }
        __syncthreads();
        #pragma unroll
        for (int st = 0; st < 8; st++) {
            const uint32_t tb = (uint32_t)(st * 1280);   // 16 rows * 40 * 2B
            uint32_t a[4], bv[4];
            ldsm_x4t(a,  s1b + tb + aoff);
            ldsm_x4t(bv, s0b + tb + boff);
            float z0[4], z1[4];
            mma1688_z  (z0, a[0], a[1], bv[0]);
            mma1688_acc(z0, a[0], a[1], bv[2]);
            mma1688_acc(z0, a[2], a[3], bv[0]);
            mma1688_z  (z1, a[0], a[1], bv[1]);
            mma1688_acc(z1, a[0], a[1], bv[3]);
            mma1688_acc(z1, a[2], a[3], bv[1]);
            const float wb = swb[oct*8 + st];
            #pragma unroll
            for (int e = 0; e < 4; e++) {
                {
                    float az = fabsf(z0[e]);
                    den[0][e] += az;
                    float s;
                    asm("sqrt.approx.f32 %0, %1;" : "=f"(s) : "f"(az));
                    uint32_t sb2 = (__float_as_uint(s) & 0x7fffffffu)
                                 | (__float_as_uint(z0[e]) & 0x80000000u);
                    num[0][e] = fmaf(wb, __uint_as_float(sb2), num[0][e]);
                }
                {
                    float az = fabsf(z1[e]);
                    den[1][e] += az;
                    float s;
                    asm("sqrt.approx.f32 %0, %1;" : "=f"(s) : "f"(az));
                    uint32_t sb2 = (__float_as_uint(s) & 0x7fffffffu)
                                 | (__float_as_uint(z1[e]) & 0x80000000u);
                    num[1][e] = fmaf(wb, __uint_as_float(sb2), num[1][e]);
                }
            }
        }
    }
    const int q = qt*32 + qoff + (lane >> 2);
    const int k = kt*32 + koff + (lane & 3)*2;
    float* p0 = SC + (size_t)c * SC_PLANE + (size_t)(b*160 + q)*160 + k;
    float o00 = num[0][0] * rsqrtf(fmaxf(den[0][0], 1e-24f));
    float o01 = num[0][1] * rsqrtf(fmaxf(den[0][1], 1e-24f));
    float o10 = num[1][0] * rsqrtf(fmaxf(den[1][0], 1e-24f));
    float o11 = num[1][1] * rsqrtf(fmaxf(den[1][1], 1e-24f));
    float o02 = num[0][2] * rsqrtf(fmaxf(den[0][2], 1e-24f));
    float o03 = num[0][3] * rsqrtf(fmaxf(den[0][3], 1e-24f));
    float o12 = num[1][2] * rsqrtf(fmaxf(den[1][2], 1e-24f));
    float o13 = num[1][3] * rsqrtf(fmaxf(den[1][3], 1e-24f));
    *(float2*)(p0)             = make_float2(o00, o01);
    *(float2*)(p0 + 8)         = make_float2(o10, o11);
    *(float2*)(p0 + 8*160)     = make_float2(o02, o03);
    *(float2*)(p0 + 8*160 + 8) = make_float2(o12, o13);
}

// ------------------------------------------------------------------------------
// Row softmax summing the 8 partial planes; result written to plane 0.
__global__ void __launch_bounds__(192) softmax_kernel(float* __restrict__ sc)
{
    const int row = blockIdx.x;
    float* p = sc + (size_t)row*160;
    const int t = threadIdx.x;
    __shared__ float red[6], red2[6];
    float x = -3.0e38f;
    if (t < 160) {
        x = 0.f;
        #pragma unroll
        for (int i = 0; i < 8; i++) x += p[(size_t)i*SC_PLANE + t];
    }
    float v = x;
    #pragma unroll
    for (int o = 16; o; o >>= 1) v = fmaxf(v, __shfl_xor_sync(0xffffffffu, v, o));
    if ((t & 31) == 0) red[t >> 5] = v;
    __syncthreads();
    float m = red[0];
    #pragma unroll
    for (int i = 1; i < 6; i++) m = fmaxf(m, red[i]);
    float e = (t < 160) ? expf(x - m) : 0.f;
    float sv = e;
    #pragma unroll
    for (int o = 16; o; o >>= 1) sv += __shfl_xor_sync(0xffffffffu, sv, o);
    if ((t & 31) == 0) red2[t >> 5] = sv;
    __syncthreads();
    float ssum = 0.f;
    #pragma unroll
    for (int i = 0; i < 6; i++) ssum += red2[i];
    if (t < 160) p[t] = e / ssum;
}

// ------------------------------------------------------------------------------
// Tensor-core attv (NN GEMM) fused with transpose-scramble (unchanged).
__global__ void __launch_bounds__(128) attv_tc_kernel(
    const float* __restrict__ att, const float* __restrict__ vv,
    float* __restrict__ scr)
{
    __shared__ __nv_bfloat16 Ah[32*40], Al[32*40], Bh[32*72], Bl[32*72];
    __shared__ float ts[64*33];
    const int tid = threadIdx.x;
    const int warp = tid >> 5, lane = tid & 31;
    const int q0 = blockIdx.x * 32, h0 = blockIdx.y * 64, b = blockIdx.z;
    const int wm = warp & 1, wn = warp >> 1;
    const float* A = att + (size_t)b * 25600;
    const float* V = vv + (size_t)b * 81920;
    const uint32_t ahb = smem_u32(Ah), alb = smem_u32(Al);
    const uint32_t bhb = smem_u32(Bh), blb = smem_u32(Bl);
    const uint32_t a_off = (uint32_t)(((wm * 16 + (lane & 15)) * 40 + (lane >> 4) * 8) * 2);
    const int tb_row = ((lane >> 3) & 1) * 8 + (lane & 7);
    const int tb_col = wn * 32 + (lane >> 4) * 8;

    float acc[4][4] = {};
    for (int kc = 0; kc < 5; kc++) {
        const int k0 = kc * 32;
        __syncthreads();
        #pragma unroll
        for (int it = 0; it < 2; it++) {
            int u = tid + it * 128;
            int row = u >> 3, c4 = (u & 7) * 4;
            float4 v4 = *(const float4*)(A + (q0 + row) * 160 + k0 + c4);
            split_store(Ah, Al, row * 40 + c4, v4);
        }
        #pragma unroll
        for (int it = 0; it < 4; it++) {
            int u = tid + it * 128;
            int row = u >> 4, c4 = (u & 15) * 4;
            float4 v4 = *(const float4*)(V + (k0 + row) * 512 + h0 + c4);
            split_store(Bh, Bl, row * 72 + c4, v4);
        }
        __syncthreads();
        #pragma unroll
        for (int k16 = 0; k16 < 2; k16++) {
            uint32_t ah[4], al[4];
            ldsm_x4(ah, ahb + a_off + k16 * 32);
            ldsm_x4(al, alb + a_off + k16 * 32);
            uint32_t bh[2][4], bl[2][4];
            const uint32_t bo = (uint32_t)(((k16 * 16 + tb_row) * 72 + tb_col) * 2);
            ldsm_x4t(bh[0], bhb + bo);
            ldsm_x4t(bh[1], bhb + bo + 32);
            ldsm_x4t(bl[0], blb + bo);
            ldsm_x4t(bl[1], blb + bo + 32);
            #pragma unroll
            for (int nj = 0; nj < 4; nj++) {
                const uint32_t* ph = &bh[nj >> 1][(nj & 1) * 2];
                const uint32_t* pl = &bl[nj >> 1][(nj & 1) * 2];
                mma16816(acc[nj], ah, ph);
                mma16816(acc[nj], ah, pl);
                mma16816(acc[nj], al, ph);
            }
        }
    }
    __syncthreads();
    const int mr = wm * 16 + (lane >> 2);
    const int nc = wn * 32 + (lane & 3) * 2;
    #pragma unroll
    for (int nj = 0; nj < 4; nj++) {
        int h = nc + nj * 8;
        ts[h * 33 + mr]           = acc[nj][0];
        ts[(h + 1) * 33 + mr]     = acc[nj][1];
        ts[h * 33 + mr + 8]       = acc[nj][2];
        ts[(h + 1) * 33 + mr + 8] = acc[nj][3];
    }
    __syncthreads();
    const int h = tid >> 1, qh = (tid & 1) * 16;
    float* dst = scr + (size_t)b * 81920 + (h0 + h) * 160 + q0 + qh;
    #pragma unroll
    for (int i = 0; i < 16; i += 4) {
        float4 o = { ts[h * 33 + qh + i], ts[h * 33 + qh + i + 1],
                     ts[h * 33 + qh + i + 2], ts[h * 33 + qh + i + 3] };
        *(float4*)(dst + i) = o;
    }
}

// ------------------------------------------------------------------------------
extern "C" void kernel_launch(void* const* d_in, const int* in_sizes, int n_in,
                              void* d_out, int out_size)
{
    (void)in_sizes; (void)n_in; (void)out_size;
    const float* v    = (const float*)d_in[0];
    const float* kin  = (const float*)d_in[1];
    const float* qin  = (const float*)d_in[2];
    const float* w_v  = (const float*)d_in[3];  const float* b_v = (const float*)d_in[4];
    const float* w_k  = (const float*)d_in[5];  const float* b_k = (const float*)d_in[6];
    const float* w_q  = (const float*)d_in[7];  const float* b_q = (const float*)d_in[8];
    const float* w0   = (const float*)d_in[9];  const float* b0  = (const float*)d_in[10];
    const float* w1   = (const float*)d_in[11]; const float* b1  = (const float*)d_in[12];
    const float* wm0  = (const float*)d_in[13]; const float* bm0 = (const float*)d_in[14];
    const float* wm1  = (const float*)d_in[15]; const float* bm1 = (const float*)d_in[16];
    const float* w_bo = (const float*)d_in[17];
    const float* w_m  = (const float*)d_in[19]; const float* b_m = (const float*)d_in[20];
    float* out = (float*)d_out;

    float *vv, *w0k, *w1q, *bc, *sc, *scr;
    uint32_t *x0, *x1;
    __nv_bfloat16 *y0, *y1;
    cudaGetSymbolAddress((void**)&vv,  g_vv);
    cudaGetSymbolAddress((void**)&w0k, g_w0k);
    cudaGetSymbolAddress((void**)&w1q, g_w1q);
    cudaGetSymbolAddress((void**)&bc,  g_bc);
    cudaGetSymbolAddress((void**)&x0,  g_x0);
    cudaGetSymbolAddress((void**)&x1,  g_x1);
    cudaGetSymbolAddress((void**)&y0,  g_y0);
    cudaGetSymbolAddress((void**)&y1,  g_y1);
    cudaGetSymbolAddress((void**)&sc,  g_sc);
    cudaGetSymbolAddress((void**)&scr, g_scr);

    static int smem_set = 0;
    if (!smem_set) {
        cudaFuncSetAttribute(hmma_gemm_kernel,
                             cudaFuncAttributeMaxDynamicSharedMemorySize, HM_SMEM_BYTES);
        cudaFuncSetAttribute(merge_tc_kernel,
                             cudaFuncAttributeMaxDynamicSharedMemorySize, HM_SMEM_BYTES);
        cudaFuncSetAttribute(prep_hmma_kernel,
                             cudaFuncAttributeMaxDynamicSharedMemorySize, HM_SMEM_BYTES);
        smem_set = 1;
    }

    // Weight composition + composed biases
    prep_hmma_kernel<<<dim3(4, 8, 2), 256, HM_SMEM_BYTES>>>(w0, w_k, w0k, w1, w_q, w1q);
    bias_comp_kernel<<<dim3(64, 2), 256>>>(w0, b_k, b0, w1, b_q, b1, bc);

    // Stage 1 (single launch): vv (fp32), x0/x1 (packed bf16 hi/lo)
    GemmBatch g1;
    g1.A[0] = v;    g1.W[0] = w_v; g1.bias[0] = b_v;      g1.C[0] = vv;          g1.pack[0] = 0;
    g1.A[1] = kin;  g1.W[1] = w0k; g1.bias[1] = bc;       g1.C[1] = (float*)x0;  g1.pack[1] = 1;
    g1.A[2] = qin;  g1.W[2] = w1q; g1.bias[2] = bc + 512; g1.C[2] = (float*)x1;  g1.pack[2] = 1;
    hmma_gemm_kernel<<<dim3(10, 8, 3), 256, HM_SMEM_BYTES>>>(g1);

    MergeBatch mrg;
    mrg.X[0] = x0; mrg.WM[0] = wm0; mrg.BM[0] = bm0; mrg.Y[0] = y0;
    mrg.X[1] = x1; mrg.WM[1] = wm1; mrg.BM[1] = bm1; mrg.Y[1] = y1;
    merge_tc_kernel<<<dim3(10, 8, 16), 256, HM_SMEM_BYTES>>>(mrg);

    scores_tc<<<dim3(5, 5, 64), 128>>>(y1, y0, w_bo, sc);
    softmax_kernel<<<1280, 192>>>(sc);
    attv_tc_kernel<<<dim3(5, 8, 8), 128>>>(sc, vv, scr);

    GemmBatch g3;
    g3.A[0] = scr; g3.W[0] = w_m; g3.bias[0] = b_m; g3.C[0] = out; g3.pack[0] = 0;
    g3.A[1] = scr; g3.W[1] = w_m; g3.bias[1] = b_m; g3.C[1] = out; g3.pack[1] = 0;
    g3.A[2] = scr; g3.W[2] = w_m; g3.bias[2] = b_m; g3.C[2] = out; g3.pack[2] = 0;
    hmma_gemm_kernel<<<dim3(10, 8, 1), 256, HM_SMEM_BYTES>>>(g3);
}

// round 10
// speedup vs baseline: 3.3181x; 1.4655x over previous
#include <cuda_runtime.h>
#include <cuda_bf16.h>
#include <cstdint>

// Problem constants (fixed shapes from the reference)
#define NB_B 8
#define NB_L 160
#define NB_H 512
#define NB_C 8
#define NB_S 64
#define NB_R 8
#define NB_BL (NB_B*NB_L)   // 1280
#define SC_PLANE (NB_B*NB_L*NB_L)   // 204800

// ---------------- scratch (device globals: no runtime allocation) -------------
__device__ float g_vv [NB_BL*NB_H];
__device__ float g_w0k[NB_H*NB_H];
__device__ float g_w1q[NB_H*NB_H];
__device__ float g_bc [2*NB_H];
__device__ uint32_t g_x0 [NB_BL*NB_H]; // packed bf16 (hi | lo<<16)
__device__ uint32_t g_x1 [NB_BL*NB_H];
// Y layout: [b][c][s(64)][r(16: 8 hi | 8 lo)][l(160)] bf16
__device__ __nv_bfloat16 g_y0 [NB_B*NB_C*NB_S*16*NB_L];
__device__ __nv_bfloat16 g_y1 [NB_B*NB_C*NB_S*16*NB_L];
__device__ float g_sc [8*SC_PLANE];
__device__ float g_scr[NB_BL*NB_H];

// ======================= mma.sync helpers (sm_80+ path) =======================
__device__ __forceinline__ uint32_t smem_u32(const void* p) {
    uint32_t a;
    asm("{ .reg .u64 t; cvta.to.shared.u64 t, %1; cvt.u32.u64 %0, t; }"
        : "=r"(a) : "l"(p));
    return a;
}
__device__ __forceinline__ void mma16816(float* d, const uint32_t* a, const uint32_t* b) {
    asm volatile(
        "mma.sync.aligned.m16n8k16.row.col.f32.bf16.bf16.f32 "
        "{%0,%1,%2,%3}, {%4,%5,%6,%7}, {%8,%9}, {%0,%1,%2,%3};"
        : "+f"(d[0]), "+f"(d[1]), "+f"(d[2]), "+f"(d[3])
        : "r"(a[0]), "r"(a[1]), "r"(a[2]), "r"(a[3]), "r"(b[0]), "r"(b[1]));
}
__device__ __forceinline__ void ldsm_x4(uint32_t* r, uint32_t addr) {
    asm volatile("ldmatrix.sync.aligned.m8n8.x4.shared.b16 {%0,%1,%2,%3}, [%4];"
        : "=r"(r[0]), "=r"(r[1]), "=r"(r[2]), "=r"(r[3]) : "r"(addr));
}
__device__ __forceinline__ void ldsm_x4t(uint32_t* r, uint32_t addr) {
    asm volatile("ldmatrix.sync.aligned.m8n8.x4.trans.shared.b16 {%0,%1,%2,%3}, [%4];"
        : "=r"(r[0]), "=r"(r[1]), "=r"(r[2]), "=r"(r[3]) : "r"(addr));
}
__device__ __forceinline__ void mma1688_z(float* d, uint32_t a0, uint32_t a1, uint32_t b) {
    asm volatile(
        "mma.sync.aligned.m16n8k8.row.col.f32.bf16.bf16.f32 "
        "{%0,%1,%2,%3}, {%4,%5}, {%6}, {%7,%8,%9,%10};"
        : "=f"(d[0]), "=f"(d[1]), "=f"(d[2]), "=f"(d[3])
        : "r"(a0), "r"(a1), "r"(b), "f"(0.f), "f"(0.f), "f"(0.f), "f"(0.f));
}
__device__ __forceinline__ void mma1688_acc(float* d, uint32_t a0, uint32_t a1, uint32_t b) {
    asm volatile(
        "mma.sync.aligned.m16n8k8.row.col.f32.bf16.bf16.f32 "
        "{%0,%1,%2,%3}, {%4,%5}, {%6}, {%0,%1,%2,%3};"
        : "+f"(d[0]), "+f"(d[1]), "+f"(d[2]), "+f"(d[3])
        : "r"(a0), "r"(a1), "r"(b));
}
__device__ __forceinline__ void cp16(uint32_t dst, const void* src) {
    asm volatile("cp.async.cg.shared.global [%0], [%1], 16;" :: "r"(dst), "l"(src));
}
__device__ __forceinline__ void split_store(__nv_bfloat16* smh, __nv_bfloat16* sml,
                                            int off, float4 v) {
    __nv_bfloat162 h01 = __floats2bfloat162_rn(v.x, v.y);
    __nv_bfloat162 h23 = __floats2bfloat162_rn(v.z, v.w);
    float2 f01 = __bfloat1622float2(h01);
    float2 f23 = __bfloat1622float2(h23);
    __nv_bfloat162 l01 = __floats2bfloat162_rn(v.x - f01.x, v.y - f01.y);
    __nv_bfloat162 l23 = __floats2bfloat162_rn(v.z - f23.x, v.w - f23.y);
    *(uint2*)&smh[off] = make_uint2(*(uint32_t*)&h01, *(uint32_t*)&h23);
    *(uint2*)&sml[off] = make_uint2(*(uint32_t*)&l01, *(uint32_t*)&l23);
}
__device__ __forceinline__ uint32_t pack_hilo(float v) {
    __nv_bfloat16 hi = __float2bfloat16(v);
    __nv_bfloat16 lo = __float2bfloat16(v - __bfloat162float(hi));
    return (uint32_t)*(uint16_t*)&hi | ((uint32_t)*(uint16_t*)&lo << 16);
}

// ================= bf16-split tensor-core GEMM: C = A @ W^T + bias ===========
struct GemmBatch {
    const float* A[3]; const float* W[3]; const float* bias[3]; float* C[3];
    int pack[3];
};

#define LDA_S 72
#define OFF_AH 0
#define OFF_AL (128*LDA_S)
#define OFF_WH (256*LDA_S)
#define OFF_WL (320*LDA_S)
#define HM_SMEM_BYTES (384*LDA_S*2)   // 55296

__global__ void __launch_bounds__(256) hmma_gemm_kernel(GemmBatch gb)
{
    extern __shared__ __nv_bfloat16 sm[];
    const int tid  = threadIdx.x;
    const int wid  = tid >> 5, lane = tid & 31;
    const int z = blockIdx.z;
    const float* A    = gb.A[z];
    const float* W    = gb.W[z];
    const float* bias = gb.bias[z];
    float*       C    = gb.C[z];
    const int m0 = blockIdx.x * 128;
    const int n0 = blockIdx.y * 64;
    const int wm = wid & 3, wn = wid >> 2;
    const uint32_t sb = smem_u32(sm);

    float acc[2][4][4] = {};

    const int a_row = wm * 32 + (lane & 15);
    const uint32_t a_addr0 = sb + (uint32_t)((OFF_AH + a_row * LDA_S + (lane >> 4) * 8) * 2);
    const int b_row = wn * 32 + ((lane >> 4) & 1) * 8 + (lane & 7);
    const uint32_t b_addr0 = sb + (uint32_t)((OFF_WH + b_row * LDA_S + ((lane >> 3) & 1) * 8) * 2);
    const uint32_t ALO_B = (uint32_t)((OFF_AL - OFF_AH) * 2);
    const uint32_t WLO_B = (uint32_t)((OFF_WL - OFF_WH) * 2);

    // per-thread staging coords
    const int arow = tid >> 4, akg = (tid & 15) << 2;   // A: 16 rows per 256 thr pass
    float4 pa[8], pw[4];
    #pragma unroll
    for (int it = 0; it < 8; it++)
        pa[it] = *(const float4*)(A + (m0 + arow + it * 16) * 512 + akg);
    #pragma unroll
    for (int it = 0; it < 4; it++)
        pw[it] = *(const float4*)(W + (n0 + arow + it * 16) * 512 + akg);

    for (int kc = 0; kc < 8; kc++) {
        __syncthreads();
        #pragma unroll
        for (int it = 0; it < 8; it++)
            split_store(sm + OFF_AH, sm + OFF_AL, (arow + it * 16) * LDA_S + akg, pa[it]);
        #pragma unroll
        for (int it = 0; it < 4; it++)
            split_store(sm + OFF_WH, sm + OFF_WL, (arow + it * 16) * LDA_S + akg, pw[it]);
        __syncthreads();

        if (kc < 7) {
            const int kb2 = (kc + 1) * 64;
            #pragma unroll
            for (int it = 0; it < 8; it++)
                pa[it] = *(const float4*)(A + (m0 + arow + it * 16) * 512 + kb2 + akg);
            #pragma unroll
            for (int it = 0; it < 4; it++)
                pw[it] = *(const float4*)(W + (n0 + arow + it * 16) * 512 + kb2 + akg);
        }

        #pragma unroll
        for (int k16 = 0; k16 < 4; k16++) {
            const uint32_t kb = (uint32_t)(k16 * 32);
            uint32_t ah[2][4], al[2][4];
            ldsm_x4(ah[0], a_addr0 + kb);
            ldsm_x4(ah[1], a_addr0 + (uint32_t)(16 * LDA_S * 2) + kb);
            ldsm_x4(al[0], a_addr0 + ALO_B + kb);
            ldsm_x4(al[1], a_addr0 + ALO_B + (uint32_t)(16 * LDA_S * 2) + kb);
            uint32_t bh[2][4], bl[2][4];
            ldsm_x4(bh[0], b_addr0 + kb);
            ldsm_x4(bh[1], b_addr0 + (uint32_t)(16 * LDA_S * 2) + kb);
            ldsm_x4(bl[0], b_addr0 + WLO_B + kb);
            ldsm_x4(bl[1], b_addr0 + WLO_B + (uint32_t)(16 * LDA_S * 2) + kb);
            #pragma unroll
            for (int mi = 0; mi < 2; mi++) {
                #pragma unroll
                for (int nj = 0; nj < 4; nj++) {
                    const uint32_t* bph = &bh[nj >> 1][(nj & 1) * 2];
                    const uint32_t* bpl = &bl[nj >> 1][(nj & 1) * 2];
                    mma16816(acc[mi][nj], ah[mi], bph);
                    mma16816(acc[mi][nj], ah[mi], bpl);
                    mma16816(acc[mi][nj], al[mi], bph);
                }
            }
        }
    }

    const int mrow = m0 + wm * 32 + (lane >> 2);
    const int ncol = n0 + wn * 32 + (lane & 3) * 2;
    if (gb.pack[z]) {
        uint32_t* Cp = (uint32_t*)C;
        #pragma unroll
        for (int mi = 0; mi < 2; mi++) {
            #pragma unroll
            for (int nj = 0; nj < 4; nj++) {
                int n = ncol + nj * 8;
                float b0 = bias[n], b1 = bias[n + 1];
                int m_a = mrow + mi * 16;
                *(uint2*)&Cp[m_a * 512 + n] =
                    make_uint2(pack_hilo(acc[mi][nj][0] + b0), pack_hilo(acc[mi][nj][1] + b1));
                *(uint2*)&Cp[(m_a + 8) * 512 + n] =
                    make_uint2(pack_hilo(acc[mi][nj][2] + b0), pack_hilo(acc[mi][nj][3] + b1));
            }
        }
    } else {
        #pragma unroll
        for (int mi = 0; mi < 2; mi++) {
            #pragma unroll
            for (int nj = 0; nj < 4; nj++) {
                int n = ncol + nj * 8;
                float b0 = bias[n], b1 = bias[n + 1];
                int m_a = mrow + mi * 16;
                *(float2*)&C[m_a * 512 + n]       = make_float2(acc[mi][nj][0] + b0, acc[mi][nj][1] + b1);
                *(float2*)&C[(m_a + 8) * 512 + n] = make_float2(acc[mi][nj][2] + b0, acc[mi][nj][3] + b1);
            }
        }
    }
}

// ------------------------------------------------------------------------------
// Weight composition (NN GEMM) with the same register prefetch.
__global__ void __launch_bounds__(256) prep_hmma_kernel(
    const float* __restrict__ A0, const float* __restrict__ B0, float* __restrict__ C0,
    const float* __restrict__ A1, const float* __restrict__ B1, float* __restrict__ C1)
{
    extern __shared__ __nv_bfloat16 sm[];
    const int tid  = threadIdx.x;
    const int wid  = tid >> 5, lane = tid & 31;
    const float* A = blockIdx.z ? A1 : A0;
    const float* B = blockIdx.z ? B1 : B0;
    float*       C = blockIdx.z ? C1 : C0;
    const int m0 = blockIdx.x * 128;
    const int n0 = blockIdx.y * 64;
    const int wm = wid & 3, wn = wid >> 2;
    const uint32_t sb = smem_u32(sm);

    float acc[2][4][4] = {};

    const int a_row = wm * 32 + (lane & 15);
    const uint32_t a_addr0 = sb + (uint32_t)((OFF_AH + a_row * LDA_S + (lane >> 4) * 8) * 2);
    const int tb_row = ((lane >> 3) & 1) * 8 + (lane & 7);
    const int tb_col = wn * 32 + (lane >> 4) * 8;
    const uint32_t ALO_B = (uint32_t)((OFF_AL - OFF_AH) * 2);
    const uint32_t WLO_B = (uint32_t)((OFF_WL - OFF_WH) * 2);

    const int arow = tid >> 4, akg = (tid & 15) << 2;
    float4 pa[8], pw[4];
    #pragma unroll
    for (int it = 0; it < 8; it++)
        pa[it] = *(const float4*)(A + (m0 + arow + it * 16) * 512 + akg);
    #pragma unroll
    for (int it = 0; it < 4; it++)
        pw[it] = *(const float4*)(B + (arow + it * 16) * 512 + n0 + akg);

    for (int kc = 0; kc < 8; kc++) {
        __syncthreads();
        #pragma unroll
        for (int it = 0; it < 8; it++)
            split_store(sm + OFF_AH, sm + OFF_AL, (arow + it * 16) * LDA_S + akg, pa[it]);
        #pragma unroll
        for (int it = 0; it < 4; it++)
            split_store(sm + OFF_WH, sm + OFF_WL, (arow + it * 16) * LDA_S + akg, pw[it]);
        __syncthreads();

        if (kc < 7) {
            const int kb2 = (kc + 1) * 64;
            #pragma unroll
            for (int it = 0; it < 8; it++)
                pa[it] = *(const float4*)(A + (m0 + arow + it * 16) * 512 + kb2 + akg);
            #pragma unroll
            for (int it = 0; it < 4; it++)
                pw[it] = *(const float4*)(B + (kb2 + arow + it * 16) * 512 + n0 + akg);
        }

        #pragma unroll
        for (int k16 = 0; k16 < 4; k16++) {
            const uint32_t kb = (uint32_t)(k16 * 32);
            uint32_t ah[2][4], al[2][4];
            ldsm_x4(ah[0], a_addr0 + kb);
            ldsm_x4(ah[1], a_addr0 + (uint32_t)(16 * LDA_S * 2) + kb);
            ldsm_x4(al[0], a_addr0 + ALO_B + kb);
            ldsm_x4(al[1], a_addr0 + ALO_B + (uint32_t)(16 * LDA_S * 2) + kb);
            uint32_t bh[2][4], bl[2][4];
            const uint32_t bo = sb + (uint32_t)((OFF_WH + (k16 * 16 + tb_row) * LDA_S + tb_col) * 2);
            ldsm_x4t(bh[0], bo);
            ldsm_x4t(bh[1], bo + 32);
            ldsm_x4t(bl[0], bo + WLO_B);
            ldsm_x4t(bl[1], bo + WLO_B + 32);
            #pragma unroll
            for (int mi = 0; mi < 2; mi++) {
                #pragma unroll
                for (int nj = 0; nj < 4; nj++) {
                    const uint32_t* bph = &bh[nj >> 1][(nj & 1) * 2];
                    const uint32_t* bpl = &bl[nj >> 1][(nj & 1) * 2];
                    mma16816(acc[mi][nj], ah[mi], bph);
                    mma16816(acc[mi][nj], ah[mi], bpl);
                    mma16816(acc[mi][nj], al[mi], bph);
                }
            }
        }
    }

    const int mrow = m0 + wm * 32 + (lane >> 2);
    const int ncol = n0 + wn * 32 + (lane & 3) * 2;
    #pragma unroll
    for (int mi = 0; mi < 2; mi++) {
        #pragma unroll
        for (int nj = 0; nj < 4; nj++) {
            int n = ncol + nj * 8;
            int m_a = mrow + mi * 16;
            *(float2*)&C[m_a * 512 + n]       = make_float2(acc[mi][nj][0], acc[mi][nj][1]);
            *(float2*)&C[(m_a + 8) * 512 + n] = make_float2(acc[mi][nj][2], acc[mi][nj][3]);
        }
    }
}

// ------------------------------------------------------------------------------
__global__ void __launch_bounds__(256) bias_comp_kernel(
    const float* __restrict__ w0, const float* __restrict__ bk, const float* __restrict__ b0,
    const float* __restrict__ w1, const float* __restrict__ bq, const float* __restrict__ b1,
    float* __restrict__ bc)
{
    const int z = blockIdx.y;
    const float* W  = z ? w1 : w0;
    const float* bi = z ? bq : bk;
    const float* bo = z ? b1 : b0;
    const int warp = threadIdx.x >> 5, lane = threadIdx.x & 31;
    const int n = blockIdx.x * 8 + warp;
    const float* row = W + n * 512;
    float s = 0.f;
    #pragma unroll 4
    for (int h = lane; h < 512; h += 32) s = fmaf(row[h], bi[h], s);
    #pragma unroll
    for (int o = 16; o; o >>= 1) s += __shfl_xor_sync(0xffffffffu, s, o);
    if (lane == 0) bc[z * 512 + n] = s + bo[n];
}

// ------------------------------------------------------------------------------
// Tensor-core merge (unchanged from R9: packed X, stride 72).
struct MergeBatch {
    const uint32_t* X[2]; const float* WM[2]; const float* BM[2]; __nv_bfloat16* Y[2];
};

__global__ void __launch_bounds__(256) merge_tc_kernel(MergeBatch mb)
{
    extern __shared__ __nv_bfloat16 sm[];
    const int tid  = threadIdx.x;
    const int wid  = tid >> 5, lane = tid & 31;
    const int zz = blockIdx.z;
    const int tensor = zz >> 3, c = zz & 7;
    const uint32_t* X = mb.X[tensor];
    const float* WM = mb.WM[tensor];
    const float* BM = mb.BM[tensor];
    __nv_bfloat16* Y = mb.Y[tensor];
    const int m0 = blockIdx.x * 128;
    const int r  = blockIdx.y;
    const int n0 = r * 64;
    const int wm = wid & 3, wn = wid >> 2;
    const uint32_t sb = smem_u32(sm);

    #pragma unroll
    for (int it = 0; it < 8; it++) {
        int u = tid + it * 256;
        int row = u >> 4, kg = (u & 15) << 2;
        uint4 x4 = *(const uint4*)(X + (m0 + row) * 512 + c * 64 + kg);
        uint32_t hi01 = (x4.x & 0xffffu) | (x4.y << 16);
        uint32_t hi23 = (x4.z & 0xffffu) | (x4.w << 16);
        uint32_t lo01 = (x4.x >> 16) | (x4.y & 0xffff0000u);
        uint32_t lo23 = (x4.z >> 16) | (x4.w & 0xffff0000u);
        int o = row * LDA_S + kg;
        *(uint2*)&sm[OFF_AH + o] = make_uint2(hi01, hi23);
        *(uint2*)&sm[OFF_AL + o] = make_uint2(lo01, lo23);
    }
    #pragma unroll
    for (int it = 0; it < 4; it++) {
        int u = tid + it * 256;
        int row = u >> 4, kg = (u & 15) << 2;
        float4 v = *(const float4*)(WM + (size_t)(c * 512 + n0 + row) * 64 + kg);
        split_store(sm + OFF_WH, sm + OFF_WL, row * LDA_S + kg, v);
    }
    __syncthreads();

    const int a_row = wm * 32 + (lane & 15);
    const uint32_t a_addr0 = sb + (uint32_t)((OFF_AH + a_row * LDA_S + (lane >> 4) * 8) * 2);
    const int b_row = wn * 32 + ((lane >> 4) & 1) * 8 + (lane & 7);
    const uint32_t b_addr0 = sb + (uint32_t)((OFF_WH + b_row * LDA_S + ((lane >> 3) & 1) * 8) * 2);
    const uint32_t ALO_B = (uint32_t)((OFF_AL - OFF_AH) * 2);
    const uint32_t WLO_B = (uint32_t)((OFF_WL - OFF_WH) * 2);

    float acc[2][4][4] = {};
    #pragma unroll
    for (int k16 = 0; k16 < 4; k16++) {
        const uint32_t kb = (uint32_t)(k16 * 32);
        uint32_t ah[2][4], al[2][4];
        ldsm_x4(ah[0], a_addr0 + kb);
        ldsm_x4(ah[1], a_addr0 + (uint32_t)(16 * LDA_S * 2) + kb);
        ldsm_x4(al[0], a_addr0 + ALO_B + kb);
        ldsm_x4(al[1], a_addr0 + ALO_B + (uint32_t)(16 * LDA_S * 2) + kb);
        uint32_t bh[2][4], bl[2][4];
        ldsm_x4(bh[0], b_addr0 + kb);
        ldsm_x4(bh[1], b_addr0 + (uint32_t)(16 * LDA_S * 2) + kb);
        ldsm_x4(bl[0], b_addr0 + WLO_B + kb);
        ldsm_x4(bl[1], b_addr0 + WLO_B + (uint32_t)(16 * LDA_S * 2) + kb);
        #pragma unroll
        for (int mi = 0; mi < 2; mi++) {
            #pragma unroll
            for (int nj = 0; nj < 4; nj++) {
                const uint32_t* bph = &bh[nj >> 1][(nj & 1) * 2];
                const uint32_t* bpl = &bl[nj >> 1][(nj & 1) * 2];
                mma16816(acc[mi][nj], ah[mi], bph);
                mma16816(acc[mi][nj], ah[mi], bpl);
                mma16816(acc[mi][nj], al[mi], bph);
            }
        }
    }

    __syncthreads();
    uint32_t* ps = (uint32_t*)sm;
    const int mbase = wm * 32 + (lane >> 2);
    const int tbase = wn * 32 + (lane & 3) * 2;
    #pragma unroll
    for (int mi = 0; mi < 2; mi++) {
        #pragma unroll
        for (int nj = 0; nj < 4; nj++) {
            int tt = tbase + nj * 8;
            float bb0 = BM[c * 512 + n0 + tt];
            float bb1 = BM[c * 512 + n0 + tt + 1];
            #pragma unroll
            for (int e = 0; e < 4; e++) {
                int mm = mbase + mi * 16 + ((e >> 1) ? 8 : 0);
                int tc2 = tt + (e & 1);
                ps[tc2 * 132 + mm] = pack_hilo(acc[mi][nj][e] + ((e & 1) ? bb1 : bb0));
            }
        }
    }
    __syncthreads();

    #pragma unroll
    for (int it = 0; it < 8; it++) {
        int u = tid + it * 256;
        int st = u >> 5, g = u & 31;
        int ml = g * 4;
        uint32_t p0 = ps[st * 132 + ml + 0];
        uint32_t p1 = ps[st * 132 + ml + 1];
        uint32_t p2 = ps[st * 132 + ml + 2];
        uint32_t p3 = ps[st * 132 + ml + 3];
        uint32_t hi01 = (p0 & 0xffffu) | (p1 << 16);
        uint32_t hi23 = (p2 & 0xffffu) | (p3 << 16);
        uint32_t lo01 = (p0 >> 16) | (p1 & 0xffff0000u);
        uint32_t lo23 = (p2 >> 16) | (p3 & 0xffff0000u);
        int m = m0 + ml;
        int b = m / 160, l = m % 160;
        size_t base = ((size_t)((b * 8 + c) * 64 + st) * 16 + r) * 160 + l;
        *(uint2*)&Y[base]            = make_uint2(hi01, hi23);
        *(uint2*)&Y[base + 8 * 160]  = make_uint2(lo01, lo23);
    }
}

// ------------------------------------------------------------------------------
// Tensor-core scores: one chunk per CTA, cp.async double-buffered staging.
__global__ void __launch_bounds__(128) scores_tc(
    const __nv_bfloat16* __restrict__ Y1, const __nv_bfloat16* __restrict__ Y0,
    const float* __restrict__ wbo, float* __restrict__ SC)
{
    __shared__ __nv_bfloat16 SB[2][2][128*40];  // [buf][Y1/Y0][row*40]
    __shared__ float swb[64];
    const int tid = threadIdx.x;
    const int warp = tid >> 5, lane = tid & 31;
    const int qt = blockIdx.x, kt = blockIdx.y;
    const int b = blockIdx.z >> 3, c = blockIdx.z & 7;
    const int qoff = (warp >> 1) * 16, koff = (warp & 1) * 16;
    if (tid < 64) swb[tid] = wbo[c * 64 + tid];

    const uint32_t sbb = smem_u32(SB);
    const int t4 = lane >> 3, rr = lane & 7;
    const int lrow = ((t4 & 2) ? 8 : 0) + rr;
    const uint32_t aoff = (uint32_t)((lrow * 40 + qoff + (t4 & 1) * 8) * 2);
    const uint32_t boff = (uint32_t)((lrow * 40 + koff + (t4 & 1) * 8) * 2);

    // per-thread staging coords (fixed across octs)
    const int su   = tid;             // + it*128
    const int cbase = (b * 8 + c) * 1024;  // 64*16 rows

    // issue one oct's 16KB via cp.async into buf
    auto issue = [&](int oct, int buf) {
        const int sbase = cbase + oct * 128;   // oct*8*16 rows
        #pragma unroll
        for (int it = 0; it < 8; it++) {
            int u = su + it * 128;
            int half = u >> 9, v = u & 511;
            int row = v >> 2, ch = v & 3;
            const __nv_bfloat16* src = (half ? Y0 : Y1)
                + (size_t)(sbase + row) * 160 + (half ? kt : qt) * 32 + ch * 8;
            uint32_t dst = sbb + (uint32_t)(((buf * 2 + half) * 5120 + row * 40 + ch * 8) * 2);
            cp16(dst, src);
        }
        asm volatile("cp.async.commit_group;" ::: "memory");
    };

    issue(0, 0);

    float num[2][4] = {}, den[2][4] = {};
    for (int oct = 0; oct < 8; oct++) {
        const int buf = oct & 1;
        if (oct < 7) {
            issue(oct + 1, buf ^ 1);
            asm volatile("cp.async.wait_group 1;" ::: "memory");
        } else {
            asm volatile("cp.async.wait_group 0;" ::: "memory");
        }
        __syncthreads();
        const uint32_t s1b = sbb + (uint32_t)(buf * 2 * 10240);
        const uint32_t s0b = s1b + 10240;
        #pragma unroll
        for (int st = 0; st < 8; st++) {
            const uint32_t tb = (uint32_t)(st * 1280);
            uint32_t a[4], bv[4];
            ldsm_x4t(a,  s1b + tb + aoff);
            ldsm_x4t(bv, s0b + tb + boff);
            float z0[4], z1[4];
            mma1688_z  (z0, a[0], a[1], bv[0]);
            mma1688_acc(z0, a[0], a[1], bv[2]);
            mma1688_acc(z0, a[2], a[3], bv[0]);
            mma1688_z  (z1, a[0], a[1], bv[1]);
            mma1688_acc(z1, a[0], a[1], bv[3]);
            mma1688_acc(z1, a[2], a[3], bv[1]);
            const float wb = swb[oct * 8 + st];
            #pragma unroll
            for (int e = 0; e < 4; e++) {
                {
                    float az = fabsf(z0[e]);
                    den[0][e] += az;
                    float s;
                    asm("sqrt.approx.f32 %0, %1;" : "=f"(s) : "f"(az));
                    uint32_t sb2 = (__float_as_uint(s) & 0x7fffffffu)
                                 | (__float_as_uint(z0[e]) & 0x80000000u);
                    num[0][e] = fmaf(wb, __uint_as_float(sb2), num[0][e]);
                }
                {
                    float az = fabsf(z1[e]);
                    den[1][e] += az;
                    float s;
                    asm("sqrt.approx.f32 %0, %1;" : "=f"(s) : "f"(az));
                    uint32_t sb2 = (__float_as_uint(s) & 0x7fffffffu)
                                 | (__float_as_uint(z1[e]) & 0x80000000u);
                    num[1][e] = fmaf(wb, __uint_as_float(sb2), num[1][e]);
                }
            }
        }
        __syncthreads();   // protect buf before its cp.async refill at oct+2
    }

    const int q = qt*32 + qoff + (lane >> 2);
    const int k = kt*32 + koff + (lane & 3)*2;
    float* p0 = SC + (size_t)c * SC_PLANE + (size_t)(b*160 + q)*160 + k;
    *(float2*)(p0)             = make_float2(num[0][0] * rsqrtf(fmaxf(den[0][0], 1e-24f)),
                                             num[0][1] * rsqrtf(fmaxf(den[0][1], 1e-24f)));
    *(float2*)(p0 + 8)         = make_float2(num[1][0] * rsqrtf(fmaxf(den[1][0], 1e-24f)),
                                             num[1][1] * rsqrtf(fmaxf(den[1][1], 1e-24f)));
    *(float2*)(p0 + 8*160)     = make_float2(num[0][2] * rsqrtf(fmaxf(den[0][2], 1e-24f)),
                                             num[0][3] * rsqrtf(fmaxf(den[0][3], 1e-24f)));
    *(float2*)(p0 + 8*160 + 8) = make_float2(num[1][2] * rsqrtf(fmaxf(den[1][2], 1e-24f)),
                                             num[1][3] * rsqrtf(fmaxf(den[1][3], 1e-24f)));
}

// ------------------------------------------------------------------------------
__global__ void __launch_bounds__(192) softmax_kernel(float* __restrict__ sc)
{
    const int row = blockIdx.x;
    float* p = sc + (size_t)row*160;
    const int t = threadIdx.x;
    __shared__ float red[6], red2[6];
    float x = -3.0e38f;
    if (t < 160) {
        x = 0.f;
        #pragma unroll
        for (int i = 0; i < 8; i++) x += p[(size_t)i*SC_PLANE + t];
    }
    float v = x;
    #pragma unroll
    for (int o = 16; o; o >>= 1) v = fmaxf(v, __shfl_xor_sync(0xffffffffu, v, o));
    if ((t & 31) == 0) red[t >> 5] = v;
    __syncthreads();
    float m = red[0];
    #pragma unroll
    for (int i = 1; i < 6; i++) m = fmaxf(m, red[i]);
    float e = (t < 160) ? expf(x - m) : 0.f;
    float sv = e;
    #pragma unroll
    for (int o = 16; o; o >>= 1) sv += __shfl_xor_sync(0xffffffffu, sv, o);
    if ((t & 31) == 0) red2[t >> 5] = sv;
    __syncthreads();
    float ssum = 0.f;
    #pragma unroll
    for (int i = 0; i < 6; i++) ssum += red2[i];
    if (t < 160) p[t] = e / ssum;
}

// ------------------------------------------------------------------------------
// Tensor-core attv (NN GEMM) fused with transpose-scramble (unchanged).
__global__ void __launch_bounds__(128) attv_tc_kernel(
    const float* __restrict__ att, const float* __restrict__ vv,
    float* __restrict__ scr)
{
    __shared__ __nv_bfloat16 Ah[32*40], Al[32*40], Bh[32*72], Bl[32*72];
    __shared__ float ts[64*33];
    const int tid = threadIdx.x;
    const int warp = tid >> 5, lane = tid & 31;
    const int q0 = blockIdx.x * 32, h0 = blockIdx.y * 64, b = blockIdx.z;
    const int wm = warp & 1, wn = warp >> 1;
    const float* A = att + (size_t)b * 25600;
    const float* V = vv + (size_t)b * 81920;
    const uint32_t ahb = smem_u32(Ah), alb = smem_u32(Al);
    const uint32_t bhb = smem_u32(Bh), blb = smem_u32(Bl);
    const uint32_t a_off = (uint32_t)(((wm * 16 + (lane & 15)) * 40 + (lane >> 4) * 8) * 2);
    const int tb_row = ((lane >> 3) & 1) * 8 + (lane & 7);
    const int tb_col = wn * 32 + (lane >> 4) * 8;

    float acc[4][4] = {};
    for (int kc = 0; kc < 5; kc++) {
        const int k0 = kc * 32;
        __syncthreads();
        #pragma unroll
        for (int it = 0; it < 2; it++) {
            int u = tid + it * 128;
            int row = u >> 3, c4 = (u & 7) * 4;
            float4 v4 = *(const float4*)(A + (q0 + row) * 160 + k0 + c4);
            split_store(Ah, Al, row * 40 + c4, v4);
        }
        #pragma unroll
        for (int it = 0; it < 4; it++) {
            int u = tid + it * 128;
            int row = u >> 4, c4 = (u & 15) * 4;
            float4 v4 = *(const float4*)(V + (k0 + row) * 512 + h0 + c4);
            split_store(Bh, Bl, row * 72 + c4, v4);
        }
        __syncthreads();
        #pragma unroll
        for (int k16 = 0; k16 < 2; k16++) {
            uint32_t ah[4], al[4];
            ldsm_x4(ah, ahb + a_off + k16 * 32);
            ldsm_x4(al, alb + a_off + k16 * 32);
            uint32_t bh[2][4], bl[2][4];
            const uint32_t bo = (uint32_t)(((k16 * 16 + tb_row) * 72 + tb_col) * 2);
            ldsm_x4t(bh[0], bhb + bo);
            ldsm_x4t(bh[1], bhb + bo + 32);
            ldsm_x4t(bl[0], blb + bo);
            ldsm_x4t(bl[1], blb + bo + 32);
            #pragma unroll
            for (int nj = 0; nj < 4; nj++) {
                const uint32_t* ph = &bh[nj >> 1][(nj & 1) * 2];
                const uint32_t* pl = &bl[nj >> 1][(nj & 1) * 2];
                mma16816(acc[nj], ah, ph);
                mma16816(acc[nj], ah, pl);
                mma16816(acc[nj], al, ph);
            }
        }
    }
    __syncthreads();
    const int mr = wm * 16 + (lane >> 2);
    const int nc = wn * 32 + (lane & 3) * 2;
    #pragma unroll
    for (int nj = 0; nj < 4; nj++) {
        int h = nc + nj * 8;
        ts[h * 33 + mr]           = acc[nj][0];
        ts[(h + 1) * 33 + mr]     = acc[nj][1];
        ts[h * 33 + mr + 8]       = acc[nj][2];
        ts[(h + 1) * 33 + mr + 8] = acc[nj][3];
    }
    __syncthreads();
    const int h = tid >> 1, qh = (tid & 1) * 16;
    float* dst = scr + (size_t)b * 81920 + (h0 + h) * 160 + q0 + qh;
    #pragma unroll
    for (int i = 0; i < 16; i += 4) {
        float4 o = { ts[h * 33 + qh + i], ts[h * 33 + qh + i + 1],
                     ts[h * 33 + qh + i + 2], ts[h * 33 + qh + i + 3] };
        *(float4*)(dst + i) = o;
    }
}

// ------------------------------------------------------------------------------
extern "C" void kernel_launch(void* const* d_in, const int* in_sizes, int n_in,
                              void* d_out, int out_size)
{
    (void)in_sizes; (void)n_in; (void)out_size;
    const float* v    = (const float*)d_in[0];
    const float* kin  = (const float*)d_in[1];
    const float* qin  = (const float*)d_in[2];
    const float* w_v  = (const float*)d_in[3];  const float* b_v = (const float*)d_in[4];
    const float* w_k  = (const float*)d_in[5];  const float* b_k = (const float*)d_in[6];
    const float* w_q  = (const float*)d_in[7];  const float* b_q = (const float*)d_in[8];
    const float* w0   = (const float*)d_in[9];  const float* b0  = (const float*)d_in[10];
    const float* w1   = (const float*)d_in[11]; const float* b1  = (const float*)d_in[12];
    const float* wm0  = (const float*)d_in[13]; const float* bm0 = (const float*)d_in[14];
    const float* wm1  = (const float*)d_in[15]; const float* bm1 = (const float*)d_in[16];
    const float* w_bo = (const float*)d_in[17];
    const float* w_m  = (const float*)d_in[19]; const float* b_m = (const float*)d_in[20];
    float* out = (float*)d_out;

    float *vv, *w0k, *w1q, *bc, *sc, *scr;
    uint32_t *x0, *x1;
    __nv_bfloat16 *y0, *y1;
    cudaGetSymbolAddress((void**)&vv,  g_vv);
    cudaGetSymbolAddress((void**)&w0k, g_w0k);
    cudaGetSymbolAddress((void**)&w1q, g_w1q);
    cudaGetSymbolAddress((void**)&bc,  g_bc);
    cudaGetSymbolAddress((void**)&x0,  g_x0);
    cudaGetSymbolAddress((void**)&x1,  g_x1);
    cudaGetSymbolAddress((void**)&y0,  g_y0);
    cudaGetSymbolAddress((void**)&y1,  g_y1);
    cudaGetSymbolAddress((void**)&sc,  g_sc);
    cudaGetSymbolAddress((void**)&scr, g_scr);

    static int smem_set = 0;
    if (!smem_set) {
        cudaFuncSetAttribute(hmma_gemm_kernel,
                             cudaFuncAttributeMaxDynamicSharedMemorySize, HM_SMEM_BYTES);
        cudaFuncSetAttribute(merge_tc_kernel,
                             cudaFuncAttributeMaxDynamicSharedMemorySize, HM_SMEM_BYTES);
        cudaFuncSetAttribute(prep_hmma_kernel,
                             cudaFuncAttributeMaxDynamicSharedMemorySize, HM_SMEM_BYTES);
        smem_set = 1;
    }

    prep_hmma_kernel<<<dim3(4, 8, 2), 256, HM_SMEM_BYTES>>>(w0, w_k, w0k, w1, w_q, w1q);
    bias_comp_kernel<<<dim3(64, 2), 256>>>(w0, b_k, b0, w1, b_q, b1, bc);

    GemmBatch g1;
    g1.A[0] = v;    g1.W[0] = w_v; g1.bias[0] = b_v;      g1.C[0] = vv;          g1.pack[0] = 0;
    g1.A[1] = kin;  g1.W[1] = w0k; g1.bias[1] = bc;       g1.C[1] = (float*)x0;  g1.pack[1] = 1;
    g1.A[2] = qin;  g1.W[2] = w1q; g1.bias[2] = bc + 512; g1.C[2] = (float*)x1;  g1.pack[2] = 1;
    hmma_gemm_kernel<<<dim3(10, 8, 3), 256, HM_SMEM_BYTES>>>(g1);

    MergeBatch mrg;
    mrg.X[0] = x0; mrg.WM[0] = wm0; mrg.BM[0] = bm0; mrg.Y[0] = y0;
    mrg.X[1] = x1; mrg.WM[1] = wm1; mrg.BM[1] = bm1; mrg.Y[1] = y1;
    merge_tc_kernel<<<dim3(10, 8, 16), 256, HM_SMEM_BYTES>>>(mrg);

    scores_tc<<<dim3(5, 5, 64), 128>>>(y1, y0, w_bo, sc);
    softmax_kernel<<<1280, 192>>>(sc);
    attv_tc_kernel<<<dim3(5, 8, 8), 128>>>(sc, vv, scr);

    GemmBatch g3;
    g3.A[0] = scr; g3.W[0] = w_m; g3.bias[0] = b_m; g3.C[0] = out; g3.pack[0] = 0;
    g3.A[1] = scr; g3.W[1] = w_m; g3.bias[1] = b_m; g3.C[1] = out; g3.pack[1] = 0;
    g3.A[2] = scr; g3.W[2] = w_m; g3.bias[2] = b_m; g3.C[2] = out; g3.pack[2] = 0;
    hmma_gemm_kernel<<<dim3(10, 8, 1), 256, HM_SMEM_BYTES>>>(g3);
}

// round 11
// speedup vs baseline: 3.3645x; 1.0140x over previous
#include <cuda_runtime.h>
#include <cuda_bf16.h>
#include <cstdint>

// Problem constants (fixed shapes from the reference)
#define NB_B 8
#define NB_L 160
#define NB_H 512
#define NB_C 8
#define NB_S 64
#define NB_R 8
#define NB_BL (NB_B*NB_L)   // 1280
#define SC_PLANE (NB_B*NB_L*NB_L)   // 204800
#define XPLANE (NB_BL*NB_H)         // 655360
#define WMPLANE (NB_C*NB_H*NB_S)    // 262144

// ---------------- scratch (device globals: no runtime allocation) -------------
__device__ float g_vv [NB_BL*NB_H];
__device__ float g_w0k[NB_H*NB_H];
__device__ float g_w1q[NB_H*NB_H];
__device__ float g_bc [2*NB_H];
__device__ __nv_bfloat16 g_x0 [2*XPLANE];   // hi plane | lo plane
__device__ __nv_bfloat16 g_x1 [2*XPLANE];
__device__ __nv_bfloat16 g_wms[2][2*WMPLANE]; // [tensor][hi|lo]
// Y layout: [b][c][s(64)][r(16: 8 hi | 8 lo)][l(160)] bf16
__device__ __nv_bfloat16 g_y0 [NB_B*NB_C*NB_S*16*NB_L];
__device__ __nv_bfloat16 g_y1 [NB_B*NB_C*NB_S*16*NB_L];
__device__ float g_sc [8*SC_PLANE];
__device__ float g_scr[NB_BL*NB_H];

// ======================= mma.sync helpers (sm_80+ path) =======================
__device__ __forceinline__ uint32_t smem_u32(const void* p) {
    uint32_t a;
    asm("{ .reg .u64 t; cvta.to.shared.u64 t, %1; cvt.u32.u64 %0, t; }"
        : "=r"(a) : "l"(p));
    return a;
}
__device__ __forceinline__ void mma16816(float* d, const uint32_t* a, const uint32_t* b) {
    asm volatile(
        "mma.sync.aligned.m16n8k16.row.col.f32.bf16.bf16.f32 "
        "{%0,%1,%2,%3}, {%4,%5,%6,%7}, {%8,%9}, {%0,%1,%2,%3};"
        : "+f"(d[0]), "+f"(d[1]), "+f"(d[2]), "+f"(d[3])
        : "r"(a[0]), "r"(a[1]), "r"(a[2]), "r"(a[3]), "r"(b[0]), "r"(b[1]));
}
__device__ __forceinline__ void ldsm_x4(uint32_t* r, uint32_t addr) {
    asm volatile("ldmatrix.sync.aligned.m8n8.x4.shared.b16 {%0,%1,%2,%3}, [%4];"
        : "=r"(r[0]), "=r"(r[1]), "=r"(r[2]), "=r"(r[3]) : "r"(addr));
}
__device__ __forceinline__ void ldsm_x4t(uint32_t* r, uint32_t addr) {
    asm volatile("ldmatrix.sync.aligned.m8n8.x4.trans.shared.b16 {%0,%1,%2,%3}, [%4];"
        : "=r"(r[0]), "=r"(r[1]), "=r"(r[2]), "=r"(r[3]) : "r"(addr));
}
__device__ __forceinline__ void mma1688_z(float* d, uint32_t a0, uint32_t a1, uint32_t b) {
    asm volatile(
        "mma.sync.aligned.m16n8k8.row.col.f32.bf16.bf16.f32 "
        "{%0,%1,%2,%3}, {%4,%5}, {%6}, {%7,%8,%9,%10};"
        : "=f"(d[0]), "=f"(d[1]), "=f"(d[2]), "=f"(d[3])
        : "r"(a0), "r"(a1), "r"(b), "f"(0.f), "f"(0.f), "f"(0.f), "f"(0.f));
}
__device__ __forceinline__ void mma1688_acc(float* d, uint32_t a0, uint32_t a1, uint32_t b) {
    asm volatile(
        "mma.sync.aligned.m16n8k8.row.col.f32.bf16.bf16.f32 "
        "{%0,%1,%2,%3}, {%4,%5}, {%6}, {%0,%1,%2,%3};"
        : "+f"(d[0]), "+f"(d[1]), "+f"(d[2]), "+f"(d[3])
        : "r"(a0), "r"(a1), "r"(b));
}
__device__ __forceinline__ void cp16(uint32_t dst, const void* src) {
    asm volatile("cp.async.cg.shared.global [%0], [%1], 16;" :: "r"(dst), "l"(src));
}
__device__ __forceinline__ void cp8(uint32_t dst, const void* src) {
    asm volatile("cp.async.ca.shared.global [%0], [%1], 8;" :: "r"(dst), "l"(src));
}
__device__ __forceinline__ void split_store(__nv_bfloat16* smh, __nv_bfloat16* sml,
                                            int off, float4 v) {
    __nv_bfloat162 h01 = __floats2bfloat162_rn(v.x, v.y);
    __nv_bfloat162 h23 = __floats2bfloat162_rn(v.z, v.w);
    float2 f01 = __bfloat1622float2(h01);
    float2 f23 = __bfloat1622float2(h23);
    __nv_bfloat162 l01 = __floats2bfloat162_rn(v.x - f01.x, v.y - f01.y);
    __nv_bfloat162 l23 = __floats2bfloat162_rn(v.z - f23.x, v.w - f23.y);
    *(uint2*)&smh[off] = make_uint2(*(uint32_t*)&h01, *(uint32_t*)&h23);
    *(uint2*)&sml[off] = make_uint2(*(uint32_t*)&l01, *(uint32_t*)&l23);
}
__device__ __forceinline__ uint32_t pack_hilo(float v) {
    __nv_bfloat16 hi = __float2bfloat16(v);
    __nv_bfloat16 lo = __float2bfloat16(v - __bfloat162float(hi));
    return (uint32_t)*(uint16_t*)&hi | ((uint32_t)*(uint16_t*)&lo << 16);
}
// split two floats into (hi0|hi1<<16) and (lo0|lo1<<16)
__device__ __forceinline__ void split_pair(float a, float b, uint32_t& h, uint32_t& l) {
    __nv_bfloat162 hp = __floats2bfloat162_rn(a, b);
    float2 f = __bfloat1622float2(hp);
    __nv_bfloat162 lp = __floats2bfloat162_rn(a - f.x, b - f.y);
    h = *(uint32_t*)&hp;
    l = *(uint32_t*)&lp;
}

// ================= bf16-split tensor-core GEMM: C = A @ W^T + bias ===========
// pack[z] != 0 -> store bf16 hi plane at C, lo plane at C + XPLANE.
struct GemmBatch {
    const float* A[3]; const float* W[3]; const float* bias[3]; float* C[3];
    int pack[3];
};

#define LDA_S 72
#define OFF_AH 0
#define OFF_AL (128*LDA_S)
#define OFF_WH (256*LDA_S)
#define OFF_WL (320*LDA_S)
#define HM_SMEM_BYTES (384*LDA_S*2)   // 55296

__global__ void __launch_bounds__(256) hmma_gemm_kernel(GemmBatch gb)
{
    extern __shared__ __nv_bfloat16 sm[];
    const int tid  = threadIdx.x;
    const int wid  = tid >> 5, lane = tid & 31;
    const int z = blockIdx.z;
    const float* A    = gb.A[z];
    const float* W    = gb.W[z];
    const float* bias = gb.bias[z];
    float*       C    = gb.C[z];
    const int m0 = blockIdx.x * 128;
    const int n0 = blockIdx.y * 64;
    const int wm = wid & 3, wn = wid >> 2;
    const uint32_t sb = smem_u32(sm);

    float acc[2][4][4] = {};

    const int a_row = wm * 32 + (lane & 15);
    const uint32_t a_addr0 = sb + (uint32_t)((OFF_AH + a_row * LDA_S + (lane >> 4) * 8) * 2);
    const int b_row = wn * 32 + ((lane >> 4) & 1) * 8 + (lane & 7);
    const uint32_t b_addr0 = sb + (uint32_t)((OFF_WH + b_row * LDA_S + ((lane >> 3) & 1) * 8) * 2);
    const uint32_t ALO_B = (uint32_t)((OFF_AL - OFF_AH) * 2);
    const uint32_t WLO_B = (uint32_t)((OFF_WL - OFF_WH) * 2);

    const int arow = tid >> 4, akg = (tid & 15) << 2;
    float4 pa[8], pw[4];
    #pragma unroll
    for (int it = 0; it < 8; it++)
        pa[it] = *(const float4*)(A + (m0 + arow + it * 16) * 512 + akg);
    #pragma unroll
    for (int it = 0; it < 4; it++)
        pw[it] = *(const float4*)(W + (n0 + arow + it * 16) * 512 + akg);

    for (int kc = 0; kc < 8; kc++) {
        __syncthreads();
        #pragma unroll
        for (int it = 0; it < 8; it++)
            split_store(sm + OFF_AH, sm + OFF_AL, (arow + it * 16) * LDA_S + akg, pa[it]);
        #pragma unroll
        for (int it = 0; it < 4; it++)
            split_store(sm + OFF_WH, sm + OFF_WL, (arow + it * 16) * LDA_S + akg, pw[it]);
        __syncthreads();

        if (kc < 7) {
            const int kb2 = (kc + 1) * 64;
            #pragma unroll
            for (int it = 0; it < 8; it++)
                pa[it] = *(const float4*)(A + (m0 + arow + it * 16) * 512 + kb2 + akg);
            #pragma unroll
            for (int it = 0; it < 4; it++)
                pw[it] = *(const float4*)(W + (n0 + arow + it * 16) * 512 + kb2 + akg);
        }

        #pragma unroll
        for (int k16 = 0; k16 < 4; k16++) {
            const uint32_t kb = (uint32_t)(k16 * 32);
            uint32_t ah[2][4], al[2][4];
            ldsm_x4(ah[0], a_addr0 + kb);
            ldsm_x4(ah[1], a_addr0 + (uint32_t)(16 * LDA_S * 2) + kb);
            ldsm_x4(al[0], a_addr0 + ALO_B + kb);
            ldsm_x4(al[1], a_addr0 + ALO_B + (uint32_t)(16 * LDA_S * 2) + kb);
            uint32_t bh[2][4], bl[2][4];
            ldsm_x4(bh[0], b_addr0 + kb);
            ldsm_x4(bh[1], b_addr0 + (uint32_t)(16 * LDA_S * 2) + kb);
            ldsm_x4(bl[0], b_addr0 + WLO_B + kb);
            ldsm_x4(bl[1], b_addr0 + WLO_B + (uint32_t)(16 * LDA_S * 2) + kb);
            #pragma unroll
            for (int mi = 0; mi < 2; mi++) {
                #pragma unroll
                for (int nj = 0; nj < 4; nj++) {
                    const uint32_t* bph = &bh[nj >> 1][(nj & 1) * 2];
                    const uint32_t* bpl = &bl[nj >> 1][(nj & 1) * 2];
                    mma16816(acc[mi][nj], ah[mi], bph);
                    mma16816(acc[mi][nj], ah[mi], bpl);
                    mma16816(acc[mi][nj], al[mi], bph);
                }
            }
        }
    }

    const int mrow = m0 + wm * 32 + (lane >> 2);
    const int ncol = n0 + wn * 32 + (lane & 3) * 2;
    if (gb.pack[z]) {
        __nv_bfloat16* Ch = (__nv_bfloat16*)C;
        __nv_bfloat16* Cl = Ch + XPLANE;
        #pragma unroll
        for (int mi = 0; mi < 2; mi++) {
            #pragma unroll
            for (int nj = 0; nj < 4; nj++) {
                int n = ncol + nj * 8;
                float b0 = bias[n], b1 = bias[n + 1];
                int m_a = mrow + mi * 16;
                uint32_t h, l;
                split_pair(acc[mi][nj][0] + b0, acc[mi][nj][1] + b1, h, l);
                *(uint32_t*)&Ch[m_a * 512 + n] = h;
                *(uint32_t*)&Cl[m_a * 512 + n] = l;
                split_pair(acc[mi][nj][2] + b0, acc[mi][nj][3] + b1, h, l);
                *(uint32_t*)&Ch[(m_a + 8) * 512 + n] = h;
                *(uint32_t*)&Cl[(m_a + 8) * 512 + n] = l;
            }
        }
    } else {
        #pragma unroll
        for (int mi = 0; mi < 2; mi++) {
            #pragma unroll
            for (int nj = 0; nj < 4; nj++) {
                int n = ncol + nj * 8;
                float b0 = bias[n], b1 = bias[n + 1];
                int m_a = mrow + mi * 16;
                *(float2*)&C[m_a * 512 + n]       = make_float2(acc[mi][nj][0] + b0, acc[mi][nj][1] + b1);
                *(float2*)&C[(m_a + 8) * 512 + n] = make_float2(acc[mi][nj][2] + b0, acc[mi][nj][3] + b1);
            }
        }
    }
}

// ------------------------------------------------------------------------------
// Weight composition (NN GEMM) with register prefetch (unchanged from R10).
__global__ void __launch_bounds__(256) prep_hmma_kernel(
    const float* __restrict__ A0, const float* __restrict__ B0, float* __restrict__ C0,
    const float* __restrict__ A1, const float* __restrict__ B1, float* __restrict__ C1)
{
    extern __shared__ __nv_bfloat16 sm[];
    const int tid  = threadIdx.x;
    const int wid  = tid >> 5, lane = tid & 31;
    const float* A = blockIdx.z ? A1 : A0;
    const float* B = blockIdx.z ? B1 : B0;
    float*       C = blockIdx.z ? C1 : C0;
    const int m0 = blockIdx.x * 128;
    const int n0 = blockIdx.y * 64;
    const int wm = wid & 3, wn = wid >> 2;
    const uint32_t sb = smem_u32(sm);

    float acc[2][4][4] = {};

    const int a_row = wm * 32 + (lane & 15);
    const uint32_t a_addr0 = sb + (uint32_t)((OFF_AH + a_row * LDA_S + (lane >> 4) * 8) * 2);
    const int tb_row = ((lane >> 3) & 1) * 8 + (lane & 7);
    const int tb_col = wn * 32 + (lane >> 4) * 8;
    const uint32_t ALO_B = (uint32_t)((OFF_AL - OFF_AH) * 2);
    const uint32_t WLO_B = (uint32_t)((OFF_WL - OFF_WH) * 2);

    const int arow = tid >> 4, akg = (tid & 15) << 2;
    float4 pa[8], pw[4];
    #pragma unroll
    for (int it = 0; it < 8; it++)
        pa[it] = *(const float4*)(A + (m0 + arow + it * 16) * 512 + akg);
    #pragma unroll
    for (int it = 0; it < 4; it++)
        pw[it] = *(const float4*)(B + (arow + it * 16) * 512 + n0 + akg);

    for (int kc = 0; kc < 8; kc++) {
        __syncthreads();
        #pragma unroll
        for (int it = 0; it < 8; it++)
            split_store(sm + OFF_AH, sm + OFF_AL, (arow + it * 16) * LDA_S + akg, pa[it]);
        #pragma unroll
        for (int it = 0; it < 4; it++)
            split_store(sm + OFF_WH, sm + OFF_WL, (arow + it * 16) * LDA_S + akg, pw[it]);
        __syncthreads();

        if (kc < 7) {
            const int kb2 = (kc + 1) * 64;
            #pragma unroll
            for (int it = 0; it < 8; it++)
                pa[it] = *(const float4*)(A + (m0 + arow + it * 16) * 512 + kb2 + akg);
            #pragma unroll
            for (int it = 0; it < 4; it++)
                pw[it] = *(const float4*)(B + (kb2 + arow + it * 16) * 512 + n0 + akg);
        }

        #pragma unroll
        for (int k16 = 0; k16 < 4; k16++) {
            const uint32_t kb = (uint32_t)(k16 * 32);
            uint32_t ah[2][4], al[2][4];
            ldsm_x4(ah[0], a_addr0 + kb);
            ldsm_x4(ah[1], a_addr0 + (uint32_t)(16 * LDA_S * 2) + kb);
            ldsm_x4(al[0], a_addr0 + ALO_B + kb);
            ldsm_x4(al[1], a_addr0 + ALO_B + (uint32_t)(16 * LDA_S * 2) + kb);
            uint32_t bh[2][4], bl[2][4];
            const uint32_t bo = sb + (uint32_t)((OFF_WH + (k16 * 16 + tb_row) * LDA_S + tb_col) * 2);
            ldsm_x4t(bh[0], bo);
            ldsm_x4t(bh[1], bo + 32);
            ldsm_x4t(bl[0], bo + WLO_B);
            ldsm_x4t(bl[1], bo + WLO_B + 32);
            #pragma unroll
            for (int mi = 0; mi < 2; mi++) {
                #pragma unroll
                for (int nj = 0; nj < 4; nj++) {
                    const uint32_t* bph = &bh[nj >> 1][(nj & 1) * 2];
                    const uint32_t* bpl = &bl[nj >> 1][(nj & 1) * 2];
                    mma16816(acc[mi][nj], ah[mi], bph);
                    mma16816(acc[mi][nj], ah[mi], bpl);
                    mma16816(acc[mi][nj], al[mi], bph);
                }
            }
        }
    }

    const int mrow = m0 + wm * 32 + (lane >> 2);
    const int ncol = n0 + wn * 32 + (lane & 3) * 2;
    #pragma unroll
    for (int mi = 0; mi < 2; mi++) {
        #pragma unroll
        for (int nj = 0; nj < 4; nj++) {
            int n = ncol + nj * 8;
            int m_a = mrow + mi * 16;
            *(float2*)&C[m_a * 512 + n]       = make_float2(acc[mi][nj][0], acc[mi][nj][1]);
            *(float2*)&C[(m_a + 8) * 512 + n] = make_float2(acc[mi][nj][2], acc[mi][nj][3]);
        }
    }
}

// ------------------------------------------------------------------------------
__global__ void __launch_bounds__(256) bias_comp_kernel(
    const float* __restrict__ w0, const float* __restrict__ bk, const float* __restrict__ b0,
    const float* __restrict__ w1, const float* __restrict__ bq, const float* __restrict__ b1,
    float* __restrict__ bc)
{
    const int z = blockIdx.y;
    const float* W  = z ? w1 : w0;
    const float* bi = z ? bq : bk;
    const float* bo = z ? b1 : b0;
    const int warp = threadIdx.x >> 5, lane = threadIdx.x & 31;
    const int n = blockIdx.x * 8 + warp;
    const float* row = W + n * 512;
    float s = 0.f;
    #pragma unroll 4
    for (int h = lane; h < 512; h += 32) s = fmaf(row[h], bi[h], s);
    #pragma unroll
    for (int o = 16; o; o >>= 1) s += __shfl_xor_sync(0xffffffffu, s, o);
    if (lane == 0) bc[z * 512 + n] = s + bo[n];
}

// ------------------------------------------------------------------------------
// wm split: fp32 merge weights -> bf16 hi/lo planes. grid (128, 2), 256 thr.
__global__ void __launch_bounds__(256) wm_split_kernel(
    const float* __restrict__ wm0, const float* __restrict__ wm1,
    __nv_bfloat16* __restrict__ wms)
{
    const int t = blockIdx.y;
    const float* src = t ? wm1 : wm0;
    __nv_bfloat16* dh = wms + (size_t)t * 2 * WMPLANE;
    __nv_bfloat16* dl = dh + WMPLANE;
    const int base4 = blockIdx.x * 512 + threadIdx.x * 2;   // float4 index
    #pragma unroll
    for (int j = 0; j < 2; j++) {
        int i4 = base4 + j;
        float4 v = *(const float4*)(src + i4 * 4);
        uint32_t h01, l01, h23, l23;
        split_pair(v.x, v.y, h01, l01);
        split_pair(v.z, v.w, h23, l23);
        *(uint2*)&dh[i4 * 4] = make_uint2(h01, h23);
        *(uint2*)&dl[i4 * 4] = make_uint2(l01, l23);
    }
}

// ------------------------------------------------------------------------------
// Tensor-core merge: ALL operands pre-split bf16 planes, staged via cp.async.
struct MergeBatch {
    const __nv_bfloat16* X[2];   // hi plane; lo plane at +XPLANE
    const __nv_bfloat16* WMS[2]; // hi plane; lo plane at +WMPLANE
    const float* BM[2];
    __nv_bfloat16* Y[2];
};

__global__ void __launch_bounds__(256) merge_tc_kernel(MergeBatch mb)
{
    extern __shared__ __nv_bfloat16 sm[];
    const int tid  = threadIdx.x;
    const int wid  = tid >> 5, lane = tid & 31;
    const int zz = blockIdx.z;
    const int tensor = zz >> 3, c = zz & 7;
    const __nv_bfloat16* X   = mb.X[tensor];
    const __nv_bfloat16* WMS = mb.WMS[tensor];
    const float* BM = mb.BM[tensor];
    __nv_bfloat16* Y = mb.Y[tensor];
    const int m0 = blockIdx.x * 128;
    const int r  = blockIdx.y;
    const int n0 = r * 64;
    const int wm = wid & 3, wn = wid >> 2;
    const uint32_t sb = smem_u32(sm);

    // ---- stage X planes: 2 x 128 rows x 16 8B-units ----
    #pragma unroll
    for (int it = 0; it < 16; it++) {
        int u = tid + it * 256;
        int plane = u >> 11, v = u & 2047;
        int row = v >> 4, g = v & 15;
        const __nv_bfloat16* src = X + plane * XPLANE
            + (size_t)(m0 + row) * 512 + c * 64 + g * 4;
        uint32_t dst = sb + (uint32_t)(((plane ? OFF_AL : OFF_AH) + row * LDA_S + g * 4) * 2);
        cp8(dst, src);
    }
    // ---- stage WM planes: 2 x 64 rows x 16 8B-units ----
    #pragma unroll
    for (int it = 0; it < 8; it++) {
        int u = tid + it * 256;
        int plane = u >> 10, v = u & 1023;
        int row = v >> 4, g = v & 15;
        const __nv_bfloat16* src = WMS + plane * WMPLANE
            + (size_t)(c * 512 + n0 + row) * 64 + g * 4;
        uint32_t dst = sb + (uint32_t)(((plane ? OFF_WL : OFF_WH) + row * LDA_S + g * 4) * 2);
        cp8(dst, src);
    }
    asm volatile("cp.async.commit_group;" ::: "memory");
    asm volatile("cp.async.wait_group 0;" ::: "memory");
    __syncthreads();

    const int a_row = wm * 32 + (lane & 15);
    const uint32_t a_addr0 = sb + (uint32_t)((OFF_AH + a_row * LDA_S + (lane >> 4) * 8) * 2);
    const int b_row = wn * 32 + ((lane >> 4) & 1) * 8 + (lane & 7);
    const uint32_t b_addr0 = sb + (uint32_t)((OFF_WH + b_row * LDA_S + ((lane >> 3) & 1) * 8) * 2);
    const uint32_t ALO_B = (uint32_t)((OFF_AL - OFF_AH) * 2);
    const uint32_t WLO_B = (uint32_t)((OFF_WL - OFF_WH) * 2);

    float acc[2][4][4] = {};
    #pragma unroll
    for (int k16 = 0; k16 < 4; k16++) {
        const uint32_t kb = (uint32_t)(k16 * 32);
        uint32_t ah[2][4], al[2][4];
        ldsm_x4(ah[0], a_addr0 + kb);
        ldsm_x4(ah[1], a_addr0 + (uint32_t)(16 * LDA_S * 2) + kb);
        ldsm_x4(al[0], a_addr0 + ALO_B + kb);
        ldsm_x4(al[1], a_addr0 + ALO_B + (uint32_t)(16 * LDA_S * 2) + kb);
        uint32_t bh[2][4], bl[2][4];
        ldsm_x4(bh[0], b_addr0 + kb);
        ldsm_x4(bh[1], b_addr0 + (uint32_t)(16 * LDA_S * 2) + kb);
        ldsm_x4(bl[0], b_addr0 + WLO_B + kb);
        ldsm_x4(bl[1], b_addr0 + WLO_B + (uint32_t)(16 * LDA_S * 2) + kb);
        #pragma unroll
        for (int mi = 0; mi < 2; mi++) {
            #pragma unroll
            for (int nj = 0; nj < 4; nj++) {
                const uint32_t* bph = &bh[nj >> 1][(nj & 1) * 2];
                const uint32_t* bpl = &bl[nj >> 1][(nj & 1) * 2];
                mma16816(acc[mi][nj], ah[mi], bph);
                mma16816(acc[mi][nj], ah[mi], bpl);
                mma16816(acc[mi][nj], al[mi], bph);
            }
        }
    }

    __syncthreads();
    uint32_t* ps = (uint32_t*)sm;
    const int mbase = wm * 32 + (lane >> 2);
    const int tbase = wn * 32 + (lane & 3) * 2;
    #pragma unroll
    for (int mi = 0; mi < 2; mi++) {
        #pragma unroll
        for (int nj = 0; nj < 4; nj++) {
            int tt = tbase + nj * 8;
            float bb0 = BM[c * 512 + n0 + tt];
            float bb1 = BM[c * 512 + n0 + tt + 1];
            #pragma unroll
            for (int e = 0; e < 4; e++) {
                int mm = mbase + mi * 16 + ((e >> 1) ? 8 : 0);
                int tc2 = tt + (e & 1);
                ps[tc2 * 132 + mm] = pack_hilo(acc[mi][nj][e] + ((e & 1) ? bb1 : bb0));
            }
        }
    }
    __syncthreads();

    #pragma unroll
    for (int it = 0; it < 8; it++) {
        int u = tid + it * 256;
        int st = u >> 5, g = u & 31;
        int ml = g * 4;
        uint32_t p0 = ps[st * 132 + ml + 0];
        uint32_t p1 = ps[st * 132 + ml + 1];
        uint32_t p2 = ps[st * 132 + ml + 2];
        uint32_t p3 = ps[st * 132 + ml + 3];
        uint32_t hi01 = (p0 & 0xffffu) | (p1 << 16);
        uint32_t hi23 = (p2 & 0xffffu) | (p3 << 16);
        uint32_t lo01 = (p0 >> 16) | (p1 & 0xffff0000u);
        uint32_t lo23 = (p2 >> 16) | (p3 & 0xffff0000u);
        int m = m0 + ml;
        int b = m / 160, l = m % 160;
        size_t base = ((size_t)((b * 8 + c) * 64 + st) * 16 + r) * 160 + l;
        *(uint2*)&Y[base]            = make_uint2(hi01, hi23);
        *(uint2*)&Y[base + 8 * 160]  = make_uint2(lo01, lo23);
    }
}

// ------------------------------------------------------------------------------
// Tensor-core scores: one chunk per CTA, cp.async double-buffered (unchanged).
__global__ void __launch_bounds__(128) scores_tc(
    const __nv_bfloat16* __restrict__ Y1, const __nv_bfloat16* __restrict__ Y0,
    const float* __restrict__ wbo, float* __restrict__ SC)
{
    __shared__ __nv_bfloat16 SB[2][2][128*40];
    __shared__ float swb[64];
    const int tid = threadIdx.x;
    const int warp = tid >> 5, lane = tid & 31;
    const int qt = blockIdx.x, kt = blockIdx.y;
    const int b = blockIdx.z >> 3, c = blockIdx.z & 7;
    const int qoff = (warp >> 1) * 16, koff = (warp & 1) * 16;
    if (tid < 64) swb[tid] = wbo[c * 64 + tid];

    const uint32_t sbb = smem_u32(SB);
    const int t4 = lane >> 3, rr = lane & 7;
    const int lrow = ((t4 & 2) ? 8 : 0) + rr;
    const uint32_t aoff = (uint32_t)((lrow * 40 + qoff + (t4 & 1) * 8) * 2);
    const uint32_t boff = (uint32_t)((lrow * 40 + koff + (t4 & 1) * 8) * 2);

    const int su   = tid;
    const int cbase = (b * 8 + c) * 1024;

    auto issue = [&](int oct, int buf) {
        const int sbase = cbase + oct * 128;
        #pragma unroll
        for (int it = 0; it < 8; it++) {
            int u = su + it * 128;
            int half = u >> 9, v = u & 511;
            int row = v >> 2, ch = v & 3;
            const __nv_bfloat16* src = (half ? Y0 : Y1)
                + (size_t)(sbase + row) * 160 + (half ? kt : qt) * 32 + ch * 8;
            uint32_t dst = sbb + (uint32_t)(((buf * 2 + half) * 5120 + row * 40 + ch * 8) * 2);
            cp16(dst, src);
        }
        asm volatile("cp.async.commit_group;" ::: "memory");
    };

    issue(0, 0);

    float num[2][4] = {}, den[2][4] = {};
    for (int oct = 0; oct < 8; oct++) {
        const int buf = oct & 1;
        if (oct < 7) {
            issue(oct + 1, buf ^ 1);
            asm volatile("cp.async.wait_group 1;" ::: "memory");
        } else {
            asm volatile("cp.async.wait_group 0;" ::: "memory");
        }
        __syncthreads();
        const uint32_t s1b = sbb + (uint32_t)(buf * 2 * 10240);
        const uint32_t s0b = s1b + 10240;
        #pragma unroll
        for (int st = 0; st < 8; st++) {
            const uint32_t tb = (uint32_t)(st * 1280);
            uint32_t a[4], bv[4];
            ldsm_x4t(a,  s1b + tb + aoff);
            ldsm_x4t(bv, s0b + tb + boff);
            float z0[4], z1[4];
            mma1688_z  (z0, a[0], a[1], bv[0]);
            mma1688_acc(z0, a[0], a[1], bv[2]);
            mma1688_acc(z0, a[2], a[3], bv[0]);
            mma1688_z  (z1, a[0], a[1], bv[1]);
            mma1688_acc(z1, a[0], a[1], bv[3]);
            mma1688_acc(z1, a[2], a[3], bv[1]);
            const float wb = swb[oct * 8 + st];
            #pragma unroll
            for (int e = 0; e < 4; e++) {
                {
                    float az = fabsf(z0[e]);
                    den[0][e] += az;
                    float s;
                    asm("sqrt.approx.f32 %0, %1;" : "=f"(s) : "f"(az));
                    uint32_t sb2 = (__float_as_uint(s) & 0x7fffffffu)
                                 | (__float_as_uint(z0[e]) & 0x80000000u);
                    num[0][e] = fmaf(wb, __uint_as_float(sb2), num[0][e]);
                }
                {
                    float az = fabsf(z1[e]);
                    den[1][e] += az;
                    float s;
                    asm("sqrt.approx.f32 %0, %1;" : "=f"(s) : "f"(az));
                    uint32_t sb2 = (__float_as_uint(s) & 0x7fffffffu)
                                 | (__float_as_uint(z1[e]) & 0x80000000u);
                    num[1][e] = fmaf(wb, __uint_as_float(sb2), num[1][e]);
                }
            }
        }
        __syncthreads();
    }

    const int q = qt*32 + qoff + (lane >> 2);
    const int k = kt*32 + koff + (lane & 3)*2;
    float* p0 = SC + (size_t)c * SC_PLANE + (size_t)(b*160 + q)*160 + k;
    *(float2*)(p0)             = make_float2(num[0][0] * rsqrtf(fmaxf(den[0][0], 1e-24f)),
                                             num[0][1] * rsqrtf(fmaxf(den[0][1], 1e-24f)));
    *(float2*)(p0 + 8)         = make_float2(num[1][0] * rsqrtf(fmaxf(den[1][0], 1e-24f)),
                                             num[1][1] * rsqrtf(fmaxf(den[1][1], 1e-24f)));
    *(float2*)(p0 + 8*160)     = make_float2(num[0][2] * rsqrtf(fmaxf(den[0][2], 1e-24f)),
                                             num[0][3] * rsqrtf(fmaxf(den[0][3], 1e-24f)));
    *(float2*)(p0 + 8*160 + 8) = make_float2(num[1][2] * rsqrtf(fmaxf(den[1][2], 1e-24f)),
                                             num[1][3] * rsqrtf(fmaxf(den[1][3], 1e-24f)));
}

// ------------------------------------------------------------------------------
__global__ void __launch_bounds__(192) softmax_kernel(float* __restrict__ sc)
{
    const int row = blockIdx.x;
    float* p = sc + (size_t)row*160;
    const int t = threadIdx.x;
    __shared__ float red[6], red2[6];
    float x = -3.0e38f;
    if (t < 160) {
        x = 0.f;
        #pragma unroll
        for (int i = 0; i < 8; i++) x += p[(size_t)i*SC_PLANE + t];
    }
    float v = x;
    #pragma unroll
    for (int o = 16; o; o >>= 1) v = fmaxf(v, __shfl_xor_sync(0xffffffffu, v, o));
    if ((t & 31) == 0) red[t >> 5] = v;
    __syncthreads();
    float m = red[0];
    #pragma unroll
    for (int i = 1; i < 6; i++) m = fmaxf(m, red[i]);
    float e = (t < 160) ? expf(x - m) : 0.f;
    float sv = e;
    #pragma unroll
    for (int o = 16; o; o >>= 1) sv += __shfl_xor_sync(0xffffffffu, sv, o);
    if ((t & 31) == 0) red2[t >> 5] = sv;
    __syncthreads();
    float ssum = 0.f;
    #pragma unroll
    for (int i = 0; i < 6; i++) ssum += red2[i];
    if (t < 160) p[t] = e / ssum;
}

// ------------------------------------------------------------------------------
// Tensor-core attv (NN GEMM) fused with transpose-scramble (unchanged).
__global__ void __launch_bounds__(128) attv_tc_kernel(
    const float* __restrict__ att, const float* __restrict__ vv,
    float* __restrict__ scr)
{
    __shared__ __nv_bfloat16 Ah[32*40], Al[32*40], Bh[32*72], Bl[32*72];
    __shared__ float ts[64*33];
    const int tid = threadIdx.x;
    const int warp = tid >> 5, lane = tid & 31;
    const int q0 = blockIdx.x * 32, h0 = blockIdx.y * 64, b = blockIdx.z;
    const int wm = warp & 1, wn = warp >> 1;
    const float* A = att + (size_t)b * 25600;
    const float* V = vv + (size_t)b * 81920;
    const uint32_t ahb = smem_u32(Ah), alb = smem_u32(Al);
    const uint32_t bhb = smem_u32(Bh), blb = smem_u32(Bl);
    const uint32_t a_off = (uint32_t)(((wm * 16 + (lane & 15)) * 40 + (lane >> 4) * 8) * 2);
    const int tb_row = ((lane >> 3) & 1) * 8 + (lane & 7);
    const int tb_col = wn * 32 + (lane >> 4) * 8;

    float acc[4][4] = {};
    for (int kc = 0; kc < 5; kc++) {
        const int k0 = kc * 32;
        __syncthreads();
        #pragma unroll
        for (int it = 0; it < 2; it++) {
            int u = tid + it * 128;
            int row = u >> 3, c4 = (u & 7) * 4;
            float4 v4 = *(const float4*)(A + (q0 + row) * 160 + k0 + c4);
            split_store(Ah, Al, row * 40 + c4, v4);
        }
        #pragma unroll
        for (int it = 0; it < 4; it++) {
            int u = tid + it * 128;
            int row = u >> 4, c4 = (u & 15) * 4;
            float4 v4 = *(const float4*)(V + (k0 + row) * 512 + h0 + c4);
            split_store(Bh, Bl, row * 72 + c4, v4);
        }
        __syncthreads();
        #pragma unroll
        for (int k16 = 0; k16 < 2; k16++) {
            uint32_t ah[4], al[4];
            ldsm_x4(ah, ahb + a_off + k16 * 32);
            ldsm_x4(al, alb + a_off + k16 * 32);
            uint32_t bh[2][4], bl[2][4];
            const uint32_t bo = (uint32_t)(((k16 * 16 + tb_row) * 72 + tb_col) * 2);
            ldsm_x4t(bh[0], bhb + bo);
            ldsm_x4t(bh[1], bhb + bo + 32);
            ldsm_x4t(bl[0], blb + bo);
            ldsm_x4t(bl[1], blb + bo + 32);
            #pragma unroll
            for (int nj = 0; nj < 4; nj++) {
                const uint32_t* ph = &bh[nj >> 1][(nj & 1) * 2];
                const uint32_t* pl = &bl[nj >> 1][(nj & 1) * 2];
                mma16816(acc[nj], ah, ph);
                mma16816(acc[nj], ah, pl);
                mma16816(acc[nj], al, ph);
            }
        }
    }
    __syncthreads();
    const int mr = wm * 16 + (lane >> 2);
    const int nc = wn * 32 + (lane & 3) * 2;
    #pragma unroll
    for (int nj = 0; nj < 4; nj++) {
        int h = nc + nj * 8;
        ts[h * 33 + mr]           = acc[nj][0];
        ts[(h + 1) * 33 + mr]     = acc[nj][1];
        ts[h * 33 + mr + 8]       = acc[nj][2];
        ts[(h + 1) * 33 + mr + 8] = acc[nj][3];
    }
    __syncthreads();
    const int h = tid >> 1, qh = (tid & 1) * 16;
    float* dst = scr + (size_t)b * 81920 + (h0 + h) * 160 + q0 + qh;
    #pragma unroll
    for (int i = 0; i < 16; i += 4) {
        float4 o = { ts[h * 33 + qh + i], ts[h * 33 + qh + i + 1],
                     ts[h * 33 + qh + i + 2], ts[h * 33 + qh + i + 3] };
        *(float4*)(dst + i) = o;
    }
}

// ------------------------------------------------------------------------------
extern "C" void kernel_launch(void* const* d_in, const int* in_sizes, int n_in,
                              void* d_out, int out_size)
{
    (void)in_sizes; (void)n_in; (void)out_size;
    const float* v    = (const float*)d_in[0];
    const float* kin  = (const float*)d_in[1];
    const float* qin  = (const float*)d_in[2];
    const float* w_v  = (const float*)d_in[3];  const float* b_v = (const float*)d_in[4];
    const float* w_k  = (const float*)d_in[5];  const float* b_k = (const float*)d_in[6];
    const float* w_q  = (const float*)d_in[7];  const float* b_q = (const float*)d_in[8];
    const float* w0   = (const float*)d_in[9];  const float* b0  = (const float*)d_in[10];
    const float* w1   = (const float*)d_in[11]; const float* b1  = (const float*)d_in[12];
    const float* wm0  = (const float*)d_in[13]; const float* bm0 = (const float*)d_in[14];
    const float* wm1  = (const float*)d_in[15]; const float* bm1 = (const float*)d_in[16];
    const float* w_bo = (const float*)d_in[17];
    const float* w_m  = (const float*)d_in[19]; const float* b_m = (const float*)d_in[20];
    float* out = (float*)d_out;

    float *vv, *w0k, *w1q, *bc, *sc, *scr;
    __nv_bfloat16 *x0, *x1, *wms, *y0, *y1;
    cudaGetSymbolAddress((void**)&vv,  g_vv);
    cudaGetSymbolAddress((void**)&w0k, g_w0k);
    cudaGetSymbolAddress((void**)&w1q, g_w1q);
    cudaGetSymbolAddress((void**)&bc,  g_bc);
    cudaGetSymbolAddress((void**)&x0,  g_x0);
    cudaGetSymbolAddress((void**)&x1,  g_x1);
    cudaGetSymbolAddress((void**)&wms, g_wms);
    cudaGetSymbolAddress((void**)&y0,  g_y0);
    cudaGetSymbolAddress((void**)&y1,  g_y1);
    cudaGetSymbolAddress((void**)&sc,  g_sc);
    cudaGetSymbolAddress((void**)&scr, g_scr);

    static int smem_set = 0;
    if (!smem_set) {
        cudaFuncSetAttribute(hmma_gemm_kernel,
                             cudaFuncAttributeMaxDynamicSharedMemorySize, HM_SMEM_BYTES);
        cudaFuncSetAttribute(merge_tc_kernel,
                             cudaFuncAttributeMaxDynamicSharedMemorySize, HM_SMEM_BYTES);
        cudaFuncSetAttribute(prep_hmma_kernel,
                             cudaFuncAttributeMaxDynamicSharedMemorySize, HM_SMEM_BYTES);
        smem_set = 1;
    }

    prep_hmma_kernel<<<dim3(4, 8, 2), 256, HM_SMEM_BYTES>>>(w0, w_k, w0k, w1, w_q, w1q);
    bias_comp_kernel<<<dim3(64, 2), 256>>>(w0, b_k, b0, w1, b_q, b1, bc);
    wm_split_kernel<<<dim3(128, 2), 256>>>(wm0, wm1, wms);

    GemmBatch g1;
    g1.A[0] = v;    g1.W[0] = w_v; g1.bias[0] = b_v;      g1.C[0] = vv;          g1.pack[0] = 0;
    g1.A[1] = kin;  g1.W[1] = w0k; g1.bias[1] = bc;       g1.C[1] = (float*)x0;  g1.pack[1] = 1;
    g1.A[2] = qin;  g1.W[2] = w1q; g1.bias[2] = bc + 512; g1.C[2] = (float*)x1;  g1.pack[2] = 1;
    hmma_gemm_kernel<<<dim3(10, 8, 3), 256, HM_SMEM_BYTES>>>(g1);

    MergeBatch mrg;
    mrg.X[0] = x0; mrg.WMS[0] = wms;              mrg.BM[0] = bm0; mrg.Y[0] = y0;
    mrg.X[1] = x1; mrg.WMS[1] = wms + 2*WMPLANE;  mrg.BM[1] = bm1; mrg.Y[1] = y1;
    merge_tc_kernel<<<dim3(10, 8, 16), 256, HM_SMEM_BYTES>>>(mrg);

    scores_tc<<<dim3(5, 5, 64), 128>>>(y1, y0, w_bo, sc);
    softmax_kernel<<<1280, 192>>>(sc);
    attv_tc_kernel<<<dim3(5, 8, 8), 128>>>(sc, vv, scr);

    GemmBatch g3;
    g3.A[0] = scr; g3.W[0] = w_m; g3.bias[0] = b_m; g3.C[0] = out; g3.pack[0] = 0;
    g3.A[1] = scr; g3.W[1] = w_m; g3.bias[1] = b_m; g3.C[1] = out; g3.pack[1] = 0;
    g3.A[2] = scr; g3.W[2] = w_m; g3.bias[2] = b_m; g3.C[2] = out; g3.pack[2] = 0;
    hmma_gemm_kernel<<<dim3(10, 8, 1), 256, HM_SMEM_BYTES>>>(g3);
}